// round 10
// baseline (speedup 1.0000x reference)
#include <cuda_runtime.h>
#include <cuda_bf16.h>
#include <math.h>
#include <stdint.h>

#define NT    1025
#define EMB   768
#define BATCH 2
#define HEADS 12
#define NREL  3972

// ------------------------- device scratch (no allocs allowed) ---------------
__device__ float g_t[BATCH * NT * EMB];
__device__ float g_qkv[BATCH * NT * 3 * EMB];
__device__ float g_patch[BATCH * 1024 * EMB];
__device__ float g_tok[BATCH * 1024 * EMB];
__device__ float g_feat0[BATCH * NT * EMB];
__device__ float g_feat1[BATCH * NT * EMB];
__device__ float g_feat2[BATCH * NT * EMB];
__device__ float g_feat3[BATCH * NT * EMB];
__device__ float g_y[BATCH * 64 * 64 * EMB];
__device__ float g_tmp[(size_t)BATCH * 4096 * 3072];
__device__ float g_wpack[3072 * 768];
__device__ float g_qkvbias[3 * EMB];
__device__ __nv_bfloat16 g_pa[14000000];   // A operands (ln/attn/fpn packs)
__device__ __nv_bfloat16 g_pb[5000000];    // B operands (max fc1: 3072*1536=4.7M)
__device__ __nv_bfloat16 g_pc[12700000];   // fc2 A operand (2050*6144=12.6M) - DEDICATED

__device__ __forceinline__ float gelu_exact(float x) {
    return 0.5f * x * (1.0f + erff(x * 0.70710678118654752f));
}

__device__ __forceinline__ uint32_t smem_u32(const void* p) {
    uint32_t a;
    asm("{ .reg .u64 t; cvta.to.shared.u64 t, %1; cvt.u32.u64 %0, t; }" : "=r"(a) : "l"(p));
    return a;
}

#define LDSM_X4(r0, r1, r2, r3, addr) \
    asm volatile("ldmatrix.sync.aligned.m8n8.x4.shared.b16 {%0,%1,%2,%3}, [%4];" \
                 : "=r"(r0), "=r"(r1), "=r"(r2), "=r"(r3) : "r"(addr))

#define MMA16816(d, a0, a1, a2, a3, b0, b1) \
    asm volatile("mma.sync.aligned.m16n8k16.row.col.f32.bf16.bf16.f32 " \
                 "{%0,%1,%2,%3}, {%4,%5,%6,%7}, {%8,%9}, {%0,%1,%2,%3};" \
                 : "+f"((d)[0]), "+f"((d)[1]), "+f"((d)[2]), "+f"((d)[3]) \
                 : "r"(a0), "r"(a1), "r"(a2), "r"(a3), "r"(b0), "r"(b1))

#define CP_ASYNC16(dst, src, sz) \
    asm volatile("cp.async.cg.shared.global [%0], [%1], 16, %2;" \
                 :: "r"(dst), "l"(src), "r"(sz))

__device__ __forceinline__ uint32_t pack_bf16(float x, float y) {
    __nv_bfloat162 t = __floats2bfloat162_rn(x, y);
    return *(uint32_t*)&t;
}
__device__ __forceinline__ void split2(float v, __nv_bfloat16& hi, __nv_bfloat16& lo) {
    hi = __float2bfloat16(v);
    lo = __float2bfloat16(v - __bfloat162float(hi));
}

// ========================= split-bf16 pack ([hi|lo]) ========================
__global__ void pack_kernel(const float* __restrict__ in, __nv_bfloat16* __restrict__ out,
                            int M, int K, int Kp, size_t irs, size_t ics,
                            size_t ibs0, size_t ibs1, int nh, size_t obs, float scale) {
    int idx = blockIdx.x * 256 + threadIdx.x;
    int z = blockIdx.y;
    if (idx >= M * Kp) return;
    int k = idx % Kp, m = idx / Kp;
    const float* src = in + (size_t)(z / nh) * ibs0 + (size_t)(z % nh) * ibs1;
    float v = (k < K) ? src[(size_t)m * irs + (size_t)k * ics] * scale : 0.f;
    __nv_bfloat16 hi, lo; split2(v, hi, lo);
    __nv_bfloat16* o = out + (size_t)z * obs + (size_t)m * (2 * (size_t)Kp);
    o[k] = hi; o[Kp + k] = lo;
}

// ---------------- fused LayerNorm + split-bf16 pack -------------------------
__global__ void ln_pack_kernel(const float* __restrict__ x, const float* __restrict__ w,
                               const float* __restrict__ b, __nv_bfloat16* __restrict__ out) {
    int r = blockIdx.x;
    const float* xr = x + (size_t)r * EMB;
    __shared__ float red[256];
    int tid = threadIdx.x;
    float s = 0.f;
    for (int i = tid; i < EMB; i += 256) s += xr[i];
    red[tid] = s; __syncthreads();
    for (int st = 128; st > 0; st >>= 1) { if (tid < st) red[tid] += red[tid + st]; __syncthreads(); }
    float mean = red[0] * (1.0f / EMB);
    __syncthreads();
    float s2 = 0.f;
    for (int i = tid; i < EMB; i += 256) { float d = xr[i] - mean; s2 += d * d; }
    red[tid] = s2; __syncthreads();
    for (int st = 128; st > 0; st >>= 1) { if (tid < st) red[tid] += red[tid + st]; __syncthreads(); }
    float inv = rsqrtf(red[0] * (1.0f / EMB) + 1e-6f);
    __nv_bfloat16* o = out + (size_t)r * (2 * EMB);
    for (int i = tid; i < EMB; i += 256) {
        float v = (xr[i] - mean) * inv * w[i] + b[i];
        __nv_bfloat16 hi, lo; split2(v, hi, lo);
        o[i] = hi; o[EMB + i] = lo;
    }
}

// ========================= HMMA GEMM (split-product reuse) ==================
template <int BN, int NSTAGE, int MINB>
__global__ void __launch_bounds__(256, MINB) hgemm2(
    const __nv_bfloat16* __restrict__ A, const __nv_bfloat16* __restrict__ B,
    float* __restrict__ C, __nv_bfloat16* __restrict__ Cp,
    const float* __restrict__ bias, const float* __restrict__ resid,
    int M, int Nreal, int Kp, size_t Abs, size_t Bbs,
    size_t ldc, size_t cs0, size_t cs1, int nh, int do_gelu) {
    constexpr int WTN = BN / 4;
    constexpr int NT8 = WTN / 8;
    constexpr int NB4 = BN / 64;
    constexpr int AHALF = 128 * 40;
    constexpr int BHALF = BN * 40;
    constexpr int STAGE = 2 * (AHALF + BHALF);
    extern __shared__ __nv_bfloat16 dsm[];

    int tid = threadIdx.x;
    int wid = tid >> 5, lane = tid & 31;
    int warp_m = wid >> 2, warp_n = wid & 3;
    int m0 = blockIdx.y * 128, n0 = blockIdx.x * BN;
    int z = blockIdx.z;

    const size_t lda = 2 * (size_t)Kp, ldb = 2 * (size_t)Kp;
    const __nv_bfloat16* Az = A + (size_t)z * Abs;
    const __nv_bfloat16* Bz = B + (size_t)z * Bbs;

    float acc[4][NT8][4];
#pragma unroll
    for (int i = 0; i < 4; i++)
#pragma unroll
        for (int j = 0; j < NT8; j++)
#pragma unroll
            for (int e = 0; e < 4; e++) acc[i][j][e] = 0.f;

    int nk = Kp >> 5;

    auto load_body = [&](int c, int s) {
        __nv_bfloat16* st = dsm + s * STAGE;
#pragma unroll
        for (int sec = 0; sec < 2; sec++) {
#pragma unroll
            for (int i = 0; i < 2; i++) {
                int idx = tid + i * 256, row = idx >> 2, cg = idx & 3;
                uint32_t dst = smem_u32(st + sec * AHALF + row * 40 + cg * 8);
                const __nv_bfloat16* src = Az + (size_t)(m0 + row) * lda +
                                           (size_t)sec * Kp + c * 32 + cg * 8;
                CP_ASYNC16(dst, src, (m0 + row < M) ? 16 : 0);
            }
        }
#pragma unroll
        for (int sec = 0; sec < 2; sec++) {
#pragma unroll
            for (int i = 0; i < NB4; i++) {
                int idx = tid + i * 256, row = idx >> 2, cg = idx & 3;
                uint32_t dst = smem_u32(st + 2 * AHALF + sec * BHALF + row * 40 + cg * 8);
                const __nv_bfloat16* src = Bz + (size_t)(n0 + row) * ldb +
                                           (size_t)sec * Kp + c * 32 + cg * 8;
                CP_ASYNC16(dst, src, (n0 + row < Nreal) ? 16 : 0);
            }
        }
    };

#pragma unroll
    for (int s = 0; s < NSTAGE - 1; s++) {
        if (s < nk) load_body(s, s);
        asm volatile("cp.async.commit_group;");
    }

    uint32_t aoff = (warp_m * 64 + (lane & 15)) * 40 + (lane >> 4) * 8;
    uint32_t boff = (warp_n * WTN + ((lane >> 4) << 3) + (lane & 7)) * 40 + ((lane >> 3) & 1) * 8;
    uint32_t dsm0 = smem_u32(dsm);

    for (int c = 0; c < nk; c++) {
        asm volatile("cp.async.wait_group %0;" :: "n"(NSTAGE - 2));
        __syncthreads();
        {
            int ncd = c + NSTAGE - 1;
            if (ncd < nk) load_body(ncd, ncd % NSTAGE);
            asm volatile("cp.async.commit_group;");
        }
        uint32_t sbase = dsm0 + (c % NSTAGE) * STAGE * 2;
#pragma unroll
        for (int kk = 0; kk < 2; kk++) {
            uint32_t ahi[4][4], alo[4][4];
#pragma unroll
            for (int mt = 0; mt < 4; mt++) {
                uint32_t ad = sbase + (aoff + mt * 16 * 40 + kk * 16) * 2;
                LDSM_X4(ahi[mt][0], ahi[mt][1], ahi[mt][2], ahi[mt][3], ad);
                LDSM_X4(alo[mt][0], alo[mt][1], alo[mt][2], alo[mt][3], ad + AHALF * 2);
            }
            uint32_t bhi[NT8][2], blo[NT8][2];
#pragma unroll
            for (int p = 0; p < NT8 / 2; p++) {
                uint32_t bd = sbase + 2 * AHALF * 2 + (boff + p * 16 * 40 + kk * 16) * 2;
                LDSM_X4(bhi[2 * p][0], bhi[2 * p][1], bhi[2 * p + 1][0], bhi[2 * p + 1][1], bd);
                LDSM_X4(blo[2 * p][0], blo[2 * p][1], blo[2 * p + 1][0], blo[2 * p + 1][1],
                        bd + BHALF * 2);
            }
#pragma unroll
            for (int mt = 0; mt < 4; mt++)
#pragma unroll
                for (int nt = 0; nt < NT8; nt++)
                    MMA16816(acc[mt][nt], ahi[mt][0], ahi[mt][1], ahi[mt][2], ahi[mt][3],
                             bhi[nt][0], bhi[nt][1]);
#pragma unroll
            for (int mt = 0; mt < 4; mt++)
#pragma unroll
                for (int nt = 0; nt < NT8; nt++)
                    MMA16816(acc[mt][nt], ahi[mt][0], ahi[mt][1], ahi[mt][2], ahi[mt][3],
                             blo[nt][0], blo[nt][1]);
#pragma unroll
            for (int mt = 0; mt < 4; mt++)
#pragma unroll
                for (int nt = 0; nt < NT8; nt++)
                    MMA16816(acc[mt][nt], alo[mt][0], alo[mt][1], alo[mt][2], alo[mt][3],
                             bhi[nt][0], bhi[nt][1]);
        }
    }

    size_t cbase = (size_t)(z / nh) * cs0 + (size_t)(z % nh) * cs1;
    int mrow = lane >> 2, ncol = (lane & 3) * 2;
#pragma unroll
    for (int mt = 0; mt < 4; mt++) {
#pragma unroll
        for (int half = 0; half < 2; half++) {
            int row = m0 + warp_m * 64 + mt * 16 + mrow + half * 8;
            if (row >= M) continue;
#pragma unroll
            for (int nt = 0; nt < NT8; nt++) {
                int col = n0 + warp_n * WTN + nt * 8 + ncol;
                float v0 = acc[mt][nt][half * 2];
                float v1 = acc[mt][nt][half * 2 + 1];
                if (bias) { v0 += bias[col]; v1 += bias[col + 1]; }
                if (resid) {
                    size_t off = cbase + (size_t)row * ldc + col;
                    v0 += resid[off]; v1 += resid[off + 1];
                }
                if (do_gelu) { v0 = gelu_exact(v0); v1 = gelu_exact(v1); }
                if (C) {
                    size_t off = cbase + (size_t)row * ldc + col;
                    if (col < Nreal) C[off] = v0;
                    if (col + 1 < Nreal) C[off + 1] = v1;
                }
                if (Cp) {
                    __nv_bfloat16 h0, l0b, h1, l1b;
                    split2(v0, h0, l0b); split2(v1, h1, l1b);
                    __nv_bfloat16* o = Cp + (size_t)row * (2 * (size_t)Nreal);
                    if (col + 1 < Nreal) {
                        *(uint32_t*)&o[col] = pack_bf16(__bfloat162float(h0), __bfloat162float(h1));
                        *(uint32_t*)&o[Nreal + col] = pack_bf16(__bfloat162float(l0b), __bfloat162float(l1b));
                    } else if (col < Nreal) {
                        o[col] = h0; o[Nreal + col] = l0b;
                    }
                }
            }
        }
    }
}

// ========================= fused flash attention ============================
// Writes output directly as packed split-bf16 [hi(768) | lo(768)] per row.
#define FA_LD 136
__global__ void __launch_bounds__(256, 2) flash_attn_kernel(
    const float* __restrict__ qkv, const float* __restrict__ relt,
    const int* __restrict__ relidx, __nv_bfloat16* __restrict__ opk) {
    extern __shared__ __nv_bfloat16 fsm[];
    __nv_bfloat16* sQ = fsm;
    __nv_bfloat16* sK = fsm + 128 * FA_LD;
    __nv_bfloat16* sV = sK + 64 * FA_LD;

    int tid = threadIdx.x, wid = tid >> 5, lane = tid & 31;
    int i0 = blockIdx.x * 128;
    int z = blockIdx.y;
    int b = z / HEADS, h = z % HEADS;
    const float* qb = qkv + (size_t)b * NT * 2304 + h * 64;
    const float* kb = qb + 768;
    const float* vb = qb + 1536;

    for (int idx = tid; idx < 128 * 64; idx += 256) {
        int r = idx >> 6, c = idx & 63;
        int gi = i0 + r;
        float v = (gi < NT) ? qb[(size_t)gi * 2304 + c] * 0.125f : 0.f;
        __nv_bfloat16 hi, lo; split2(v, hi, lo);
        sQ[r * FA_LD + c] = hi;
        sQ[r * FA_LD + 64 + c] = lo;
    }

    float m0 = -1e30f, m1 = -1e30f, l0 = 0.f, l1 = 0.f;
    float O[8][4];
#pragma unroll
    for (int t = 0; t < 8; t++)
#pragma unroll
        for (int e = 0; e < 4; e++) O[t][e] = 0.f;

    int r0g = i0 + wid * 16 + (lane >> 2);
    int r1g = r0g + 8;

    for (int j0 = 0; j0 < NT; j0 += 64) {
        __syncthreads();
        for (int idx = tid; idx < 64 * 64; idx += 256) {
            int r = idx >> 6, c = idx & 63;
            int gj = j0 + r;
            float kv = (gj < NT) ? kb[(size_t)gj * 2304 + c] : 0.f;
            __nv_bfloat16 khi, klo; split2(kv, khi, klo);
            sK[r * FA_LD + c] = khi;
            sK[r * FA_LD + 64 + c] = klo;
            float vv = (gj < NT) ? vb[(size_t)gj * 2304 + c] : 0.f;
            __nv_bfloat16 vhi, vlo; split2(vv, vhi, vlo);
            sV[c * FA_LD + r] = vhi;
            sV[c * FA_LD + 64 + r] = vlo;
        }
        __syncthreads();

        float S[8][4];
#pragma unroll
        for (int t = 0; t < 8; t++)
#pragma unroll
            for (int e = 0; e < 4; e++) S[t][e] = 0.f;

        const int qsec[3] = {0, 1, 0}, ksec[3] = {0, 0, 1};
#pragma unroll
        for (int sp = 0; sp < 3; sp++) {
#pragma unroll
            for (int kk = 0; kk < 4; kk++) {
                uint32_t a0, a1, a2, a3;
                uint32_t addr = smem_u32(&sQ[(wid * 16 + (lane & 15)) * FA_LD +
                                             qsec[sp] * 64 + kk * 16 + (lane >> 4) * 8]);
                LDSM_X4(a0, a1, a2, a3, addr);
                uint32_t bf[8][2];
#pragma unroll
                for (int p = 0; p < 4; p++) {
                    uint32_t ba = smem_u32(&sK[(p * 16 + ((lane >> 4) << 3) + (lane & 7)) * FA_LD +
                                               ksec[sp] * 64 + kk * 16 + ((lane >> 3) & 1) * 8]);
                    LDSM_X4(bf[2 * p][0], bf[2 * p][1], bf[2 * p + 1][0], bf[2 * p + 1][1], ba);
                }
#pragma unroll
                for (int nt = 0; nt < 8; nt++)
                    MMA16816(S[nt], a0, a1, a2, a3, bf[nt][0], bf[nt][1]);
            }
        }

#pragma unroll
        for (int nt = 0; nt < 8; nt++) {
            int c0 = j0 + nt * 8 + (lane & 3) * 2;
#pragma unroll
            for (int e = 0; e < 2; e++) {
                int jj = c0 + e;
                if (jj < NT) {
                    if (r0g < NT) S[nt][e]     += relt[(size_t)relidx[(size_t)r0g * NT + jj] * HEADS + h];
                    if (r1g < NT) S[nt][2 + e] += relt[(size_t)relidx[(size_t)r1g * NT + jj] * HEADS + h];
                } else {
                    S[nt][e] = -1e30f;
                    S[nt][2 + e] = -1e30f;
                }
            }
        }

        float t0 = -1e30f, t1 = -1e30f;
#pragma unroll
        for (int nt = 0; nt < 8; nt++) {
            t0 = fmaxf(t0, fmaxf(S[nt][0], S[nt][1]));
            t1 = fmaxf(t1, fmaxf(S[nt][2], S[nt][3]));
        }
        t0 = fmaxf(t0, __shfl_xor_sync(0xffffffff, t0, 1));
        t0 = fmaxf(t0, __shfl_xor_sync(0xffffffff, t0, 2));
        t1 = fmaxf(t1, __shfl_xor_sync(0xffffffff, t1, 1));
        t1 = fmaxf(t1, __shfl_xor_sync(0xffffffff, t1, 2));
        float mn0 = fmaxf(m0, t0), mn1 = fmaxf(m1, t1);
        float al0 = __expf(m0 - mn0), al1 = __expf(m1 - mn1);
#pragma unroll
        for (int nt = 0; nt < 8; nt++) {
            O[nt][0] *= al0; O[nt][1] *= al0;
            O[nt][2] *= al1; O[nt][3] *= al1;
        }
        float ls0 = 0.f, ls1 = 0.f;
        uint32_t phi[4][4], plo[4][4];
#pragma unroll
        for (int kk = 0; kk < 4; kk++) {
#pragma unroll
            for (int tt = 0; tt < 2; tt++) {
                int t = 2 * kk + tt;
                float p0 = __expf(S[t][0] - mn0), p1 = __expf(S[t][1] - mn0);
                float p2 = __expf(S[t][2] - mn1), p3 = __expf(S[t][3] - mn1);
                ls0 += p0 + p1; ls1 += p2 + p3;
                float h0 = __bfloat162float(__float2bfloat16(p0));
                float h1 = __bfloat162float(__float2bfloat16(p1));
                float h2 = __bfloat162float(__float2bfloat16(p2));
                float h3 = __bfloat162float(__float2bfloat16(p3));
                phi[kk][tt * 2]     = pack_bf16(h0, h1);
                phi[kk][tt * 2 + 1] = pack_bf16(h2, h3);
                plo[kk][tt * 2]     = pack_bf16(p0 - h0, p1 - h1);
                plo[kk][tt * 2 + 1] = pack_bf16(p2 - h2, p3 - h3);
            }
        }
        ls0 += __shfl_xor_sync(0xffffffff, ls0, 1);
        ls0 += __shfl_xor_sync(0xffffffff, ls0, 2);
        ls1 += __shfl_xor_sync(0xffffffff, ls1, 1);
        ls1 += __shfl_xor_sync(0xffffffff, ls1, 2);
        l0 = l0 * al0 + ls0;
        l1 = l1 * al1 + ls1;
        m0 = mn0; m1 = mn1;

        const int vsec[3] = {0, 0, 1};
#pragma unroll
        for (int sp = 0; sp < 3; sp++) {
#pragma unroll
            for (int kk = 0; kk < 4; kk++) {
                uint32_t* A = (sp == 1) ? plo[kk] : phi[kk];
                uint32_t bf[8][2];
#pragma unroll
                for (int p = 0; p < 4; p++) {
                    uint32_t ba = smem_u32(&sV[(p * 16 + ((lane >> 4) << 3) + (lane & 7)) * FA_LD +
                                               vsec[sp] * 64 + kk * 16 + ((lane >> 3) & 1) * 8]);
                    LDSM_X4(bf[2 * p][0], bf[2 * p][1], bf[2 * p + 1][0], bf[2 * p + 1][1], ba);
                }
#pragma unroll
                for (int nt = 0; nt < 8; nt++)
                    MMA16816(O[nt], A[0], A[1], A[2], A[3], bf[nt][0], bf[nt][1]);
            }
        }
    }

    float il0 = 1.0f / l0, il1 = 1.0f / l1;
#pragma unroll
    for (int nt = 0; nt < 8; nt++) {
        int d = h * 64 + nt * 8 + (lane & 3) * 2;
        if (r0g < NT) {
            float v0 = O[nt][0] * il0, v1 = O[nt][1] * il0;
            __nv_bfloat16 h0, lo0, h1, lo1;
            split2(v0, h0, lo0); split2(v1, h1, lo1);
            __nv_bfloat16* o = opk + ((size_t)b * NT + r0g) * 1536;
            *(uint32_t*)&o[d] = pack_bf16(__bfloat162float(h0), __bfloat162float(h1));
            *(uint32_t*)&o[768 + d] = pack_bf16(__bfloat162float(lo0), __bfloat162float(lo1));
        }
        if (r1g < NT) {
            float v0 = O[nt][2] * il1, v1 = O[nt][3] * il1;
            __nv_bfloat16 h0, lo0, h1, lo1;
            split2(v0, h0, lo0); split2(v1, h1, lo1);
            __nv_bfloat16* o = opk + ((size_t)b * NT + r1g) * 1536;
            *(uint32_t*)&o[d] = pack_bf16(__bfloat162float(h0), __bfloat162float(h1));
            *(uint32_t*)&o[768 + d] = pack_bf16(__bfloat162float(lo0), __bfloat162float(lo1));
        }
    }
}

// ------------------------- elementwise helpers ------------------------------
__global__ void patchify_kernel(const float* __restrict__ x, float* __restrict__ A) {
    int idx = blockIdx.x * 256 + threadIdx.x;
    if (idx >= BATCH * 1024 * EMB) return;
    int col = idx % EMB;
    int m = idx / EMB;
    int b = m / 1024, g = m % 1024;
    int gh = g / 32, gw = g % 32;
    int c = col / 256, rem = col % 256;
    int i = rem / 16, j = rem % 16;
    A[idx] = x[(((size_t)(b * 3 + c) * 512) + gh * 16 + i) * 512 + gw * 16 + j];
}

__global__ void assemble_kernel(const float* __restrict__ tok, const float* __restrict__ cls,
                                const float* __restrict__ pos, float* __restrict__ t) {
    int idx = blockIdx.x * 256 + threadIdx.x;
    if (idx >= BATCH * NT * EMB) return;
    int d = idx % EMB;
    int n = (idx / EMB) % NT;
    int b = idx / (EMB * NT);
    float v = (n == 0) ? cls[d] : tok[((size_t)b * 1024 + (n - 1)) * EMB + d];
    t[idx] = v + pos[n * EMB + d];
}

__global__ void biaspack_kernel(const float* __restrict__ qb, const float* __restrict__ vb,
                                float* __restrict__ out) {
    int i = blockIdx.x * 256 + threadIdx.x;
    if (i >= 3 * EMB) return;
    out[i] = (i < EMB) ? qb[i] : ((i < 2 * EMB) ? 0.f : vb[i - 2 * EMB]);
}

__global__ void copy_kernel(const float* __restrict__ src, float* __restrict__ dst, int n) {
    int i = blockIdx.x * 256 + threadIdx.x;
    if (i < n) dst[i] = src[i];
}

__global__ void repack_w_kernel(const float* __restrict__ w, float* __restrict__ wp) {
    int idx = blockIdx.x * 256 + threadIdx.x;
    if (idx >= 3072 * 768) return;
    int c = idx % 768, n = idx / 768;
    int ij = n / 768, d = n % 768;
    wp[idx] = w[(size_t)c * 3072 + d * 4 + ij];
}

__global__ void scatter_bhwc_kernel(const float* __restrict__ tmp, const float* __restrict__ bias,
                                    float* __restrict__ y, int HW) {
    int total = BATCH * HW * HW * 4 * 768;
    int idx = blockIdx.x * 256 + threadIdx.x;
    if (idx >= total) return;
    int d = idx % 768;
    int ij = (idx / 768) % 4;
    int p = (idx / 3072) % (HW * HW);
    int b = idx / (3072 * HW * HW);
    int h = p / HW, w = p % HW, i = ij / 2, j = ij % 2;
    int W2 = 2 * HW;
    y[(((size_t)b * W2 + 2 * h + i) * W2 + (2 * w + j)) * 768 + d] = tmp[idx] + bias[d];
}

__global__ void scatter_bchw_kernel(const float* __restrict__ tmp, const float* __restrict__ bias,
                                    float* __restrict__ out, int HW) {
    int total = BATCH * HW * HW * 4 * 768;
    int idx = blockIdx.x * 256 + threadIdx.x;
    if (idx >= total) return;
    int d = idx % 768;
    int ij = (idx / 768) % 4;
    int p = (idx / 3072) % (HW * HW);
    int b = idx / (3072 * HW * HW);
    int h = p / HW, w = p % HW, i = ij / 2, j = ij % 2;
    int W2 = 2 * HW;
    out[(((size_t)b * 768 + d) * W2 + 2 * h + i) * W2 + (2 * w + j)] = tmp[idx] + bias[d];
}

__global__ void bn_gelu_kernel(float* __restrict__ y, const float* __restrict__ w,
                               const float* __restrict__ b, const float* __restrict__ mean,
                               const float* __restrict__ var) {
    int idx = blockIdx.x * 256 + threadIdx.x;
    if (idx >= BATCH * 64 * 64 * 768) return;
    int c = idx % 768;
    float v = y[idx];
    v = (v - mean[c]) * rsqrtf(var[c] + 1e-5f) * w[c] + b[c];
    y[idx] = gelu_exact(v);
}

__global__ void to_map_kernel(const float* __restrict__ feat, float* __restrict__ out) {
    int idx = blockIdx.x * 256 + threadIdx.x;
    if (idx >= BATCH * 768 * 32 * 32) return;
    int xw = idx % 32;
    int yh = (idx / 32) % 32;
    int c = (idx / 1024) % 768;
    int b = idx / (1024 * 768);
    out[idx] = feat[((size_t)b * NT + 1 + yh * 32 + xw) * EMB + c];
}

__global__ void maxpool_kernel(const float* __restrict__ feat, float* __restrict__ out) {
    int idx = blockIdx.x * 256 + threadIdx.x;
    if (idx >= BATCH * 768 * 16 * 16) return;
    int xw = idx % 16;
    int yh = (idx / 16) % 16;
    int c = (idx / 256) % 768;
    int b = idx / (256 * 768);
    float m = -1e30f;
#pragma unroll
    for (int i = 0; i < 2; i++)
#pragma unroll
        for (int j = 0; j < 2; j++) {
            int Y = 2 * yh + i, X = 2 * xw + j;
            m = fmaxf(m, feat[((size_t)b * NT + 1 + Y * 32 + X) * EMB + c]);
        }
    out[idx] = m;
}

// ------------------------- host helpers -------------------------------------
static void pack(const float* in, __nv_bfloat16* out, int M, int K, int Kp,
                 size_t irs, size_t ics, size_t ibs0, size_t ibs1, int nh,
                 size_t obs, float scale, int nz) {
    dim3 g((M * Kp + 255) / 256, nz);
    pack_kernel<<<g, 256>>>(in, out, M, K, Kp, irs, ics, ibs0, ibs1, nh, obs, scale);
}
#define SMEM64  (2 * 2 * (128 + 64) * 40 * 2)    // 61440 (2-stage, 3 CTAs/SM)
#define SMEM128 (2 * 2 * (128 + 128) * 40 * 2)   // 81920 (2-stage, 2 CTAs/SM)
static void gemm_tc(const __nv_bfloat16* A, const __nv_bfloat16* B, float* C,
                    __nv_bfloat16* Cp, const float* bias, const float* resid,
                    int M, int N, int Kp, size_t Abs, size_t Bbs, size_t ldc,
                    size_t cs0, size_t cs1, int nh, int gelu, int nz) {
    int gm = (M + 127) / 128;
    int g128 = ((N + 127) / 128) * gm * nz;
    if (N % 64 == 0 && (N % 128 != 0 || g128 < 148)) {
        dim3 g(N / 64, gm, nz);
        hgemm2<64, 2, 3><<<g, 256, SMEM64>>>(A, B, C, Cp, bias, resid, M, N, Kp, Abs, Bbs,
                                             ldc, cs0, cs1, nh, gelu);
    } else {
        dim3 g((N + 127) / 128, gm, nz);
        hgemm2<128, 2, 2><<<g, 256, SMEM128>>>(A, B, C, Cp, bias, resid, M, N, Kp, Abs, Bbs,
                                               ldc, cs0, cs1, nh, gelu);
    }
}

extern "C" void kernel_launch(void* const* d_in, const int* in_sizes, int n_in,
                              void* d_out, int out_size) {
    const float* x         = (const float*)d_in[0];
    const float* patch_w   = (const float*)d_in[1];
    const float* patch_b   = (const float*)d_in[2];
    const float* cls_token = (const float*)d_in[3];
    const float* pos_embed = (const float*)d_in[4];
    const float* ln1_w     = (const float*)d_in[5];
    const float* ln1_b     = (const float*)d_in[6];
    const float* qkv_w     = (const float*)d_in[7];
    const float* q_bias    = (const float*)d_in[8];
    const float* v_bias    = (const float*)d_in[9];
    const float* rel_tab   = (const float*)d_in[10];
    const float* proj_w    = (const float*)d_in[11];
    const float* proj_b    = (const float*)d_in[12];
    const float* ln2_w     = (const float*)d_in[13];
    const float* ln2_b     = (const float*)d_in[14];
    const float* fc1_w     = (const float*)d_in[15];
    const float* fc1_b     = (const float*)d_in[16];
    const float* fc2_w     = (const float*)d_in[17];
    const float* fc2_b     = (const float*)d_in[18];
    const float* d1_w      = (const float*)d_in[19];
    const float* d1_b      = (const float*)d_in[20];
    const float* bn_w      = (const float*)d_in[21];
    const float* bn_b      = (const float*)d_in[22];
    const float* bn_mean   = (const float*)d_in[23];
    const float* bn_var    = (const float*)d_in[24];
    const float* d2_w      = (const float*)d_in[25];
    const float* d2_b      = (const float*)d_in[26];
    const float* f2w       = (const float*)d_in[27];
    const float* f2b       = (const float*)d_in[28];
    const int*   rel_idx   = (const int*)d_in[29];

    float* out = (float*)d_out;
    float* out1 = out;
    float* out2 = out1 + (size_t)BATCH * 768 * 128 * 128;
    float* out3 = out2 + (size_t)BATCH * 768 * 64 * 64;
    float* out4 = out3 + (size_t)BATCH * 768 * 32 * 32;

    static float *pt = nullptr, *pqkv, *ppatch, *ptok;
    static float *pf0, *pf1, *pf2, *pf3, *py, *ptmp, *pwp, *pqb;
    static __nv_bfloat16 *pa, *pb, *pc;
    if (!pt) {
        cudaGetSymbolAddress((void**)&pt, g_t);
        cudaGetSymbolAddress((void**)&pqkv, g_qkv);
        cudaGetSymbolAddress((void**)&ppatch, g_patch);
        cudaGetSymbolAddress((void**)&ptok, g_tok);
        cudaGetSymbolAddress((void**)&pf0, g_feat0);
        cudaGetSymbolAddress((void**)&pf1, g_feat1);
        cudaGetSymbolAddress((void**)&pf2, g_feat2);
        cudaGetSymbolAddress((void**)&pf3, g_feat3);
        cudaGetSymbolAddress((void**)&py, g_y);
        cudaGetSymbolAddress((void**)&ptmp, g_tmp);
        cudaGetSymbolAddress((void**)&pwp, g_wpack);
        cudaGetSymbolAddress((void**)&pqb, g_qkvbias);
        cudaGetSymbolAddress((void**)&pa, g_pa);
        cudaGetSymbolAddress((void**)&pb, g_pb);
        cudaGetSymbolAddress((void**)&pc, g_pc);
        cudaFuncSetAttribute(flash_attn_kernel,
                             cudaFuncAttributeMaxDynamicSharedMemorySize,
                             (128 + 64 + 64) * FA_LD * 2);
        cudaFuncSetAttribute((const void*)hgemm2<64, 2, 3>,
                             cudaFuncAttributeMaxDynamicSharedMemorySize, SMEM64);
        cudaFuncSetAttribute((const void*)hgemm2<128, 2, 2>,
                             cudaFuncAttributeMaxDynamicSharedMemorySize, SMEM128);
    }

    const int TOKELEMS = BATCH * NT * EMB;
    const int M = BATCH * NT;  // 2050
    const int FA_SMEM = (128 + 64 + 64) * FA_LD * 2;

    // ---- patch embed ----
    patchify_kernel<<<(BATCH * 1024 * EMB + 255) / 256, 256>>>(x, ppatch);
    pack(ppatch, pa, 2048, 768, 768, 768, 1, 0, 0, 1, 0, 1.0f, 1);
    pack(patch_w, pb, 768, 768, 768, 768, 1, 0, 0, 1, 0, 1.0f, 1);
    gemm_tc(pa, pb, ptok, nullptr, patch_b, nullptr, 2048, 768, 768, 0, 0,
            768, 0, 0, 1, 0, 1);
    assemble_kernel<<<(TOKELEMS + 255) / 256, 256>>>(ptok, cls_token, pos_embed, pt);

    // ---- transformer layers ----
    for (int l = 0; l < 12; l++) {
        // LN1 fused with split-pack -> pa
        ln_pack_kernel<<<M, 256>>>(pt, ln1_w + l * EMB, ln1_b + l * EMB, pa);
        biaspack_kernel<<<(3 * EMB + 255) / 256, 256>>>(q_bias + l * EMB, v_bias + l * EMB, pqb);
        pack(qkv_w + (size_t)l * 2304 * 768, pb, 2304, 768, 768, 768, 1, 0, 0, 1, 0, 1.0f, 1);
        gemm_tc(pa, pb, pqkv, nullptr, pqb, nullptr, M, 2304, 768, 0, 0,
                2304, 0, 0, 1, 0, 1);
        // fused attention -> packed proj-A directly in pa
        {
            dim3 g((NT + 127) / 128, BATCH * HEADS);
            flash_attn_kernel<<<g, 256, FA_SMEM>>>(pqkv, rel_tab + (size_t)l * NREL * HEADS,
                                                   rel_idx, pa);
        }
        pack(proj_w + (size_t)l * 768 * 768, pb, 768, 768, 768, 768, 1, 0, 0, 1, 0, 1.0f, 1);
        gemm_tc(pa, pb, pt, nullptr, proj_b + l * EMB, pt, M, 768, 768, 0, 0,
                768, 0, 0, 1, 0, 1);
        // LN2 fused pack -> pa ; fc1 emits packed fc2-A into DEDICATED pc buffer
        ln_pack_kernel<<<M, 256>>>(pt, ln2_w + l * EMB, ln2_b + l * EMB, pa);
        pack(fc1_w + (size_t)l * 3072 * 768, pb, 3072, 768, 768, 768, 1, 0, 0, 1, 0, 1.0f, 1);
        gemm_tc(pa, pb, nullptr, pc, fc1_b + l * 4 * EMB, nullptr, M, 3072, 768, 0, 0,
                3072, 0, 0, 1, 1, 1);
        pack(fc2_w + (size_t)l * 768 * 3072, pb, 768, 3072, 3072, 3072, 1, 0, 0, 1, 0, 1.0f, 1);
        gemm_tc(pc, pb, pt, nullptr, fc2_b + l * EMB, pt, M, 768, 3072, 0, 0,
                768, 0, 0, 1, 0, 1);
        float* fdst = nullptr;
        if (l == 3) fdst = pf0;
        else if (l == 5) fdst = pf1;
        else if (l == 7) fdst = pf2;
        else if (l == 11) fdst = pf3;
        if (fdst) copy_kernel<<<(TOKELEMS + 255) / 256, 256>>>(pt, fdst, TOKELEMS);
    }

    // ---- o3 / o4 ----
    to_map_kernel<<<(BATCH * 768 * 1024 + 255) / 256, 256>>>(pf2, out3);
    maxpool_kernel<<<(BATCH * 768 * 256 + 255) / 256, 256>>>(pf3, out4);

    // ---- fpn1 stage 1 ----
    repack_w_kernel<<<(3072 * 768 + 255) / 256, 256>>>(d1_w, pwp);
    pack(pwp, pb, 3072, 768, 768, 768, 1, 0, 0, 1, 0, 1.0f, 1);
    pack(pf0 + 768, pa, 1024, 768, 768, 768, 1, (size_t)NT * 768, 0, 1,
         (size_t)1024 * 1536, 1.0f, BATCH);
    gemm_tc(pa, pb, ptmp, nullptr, nullptr, nullptr, 1024, 3072, 768,
            (size_t)1024 * 1536, 0, 3072, (size_t)1024 * 3072, 0, 1, 0, BATCH);
    scatter_bhwc_kernel<<<(BATCH * 1024 * 3072 + 255) / 256, 256>>>(ptmp, d1_b, py, 32);
    bn_gelu_kernel<<<(BATCH * 64 * 64 * 768 + 255) / 256, 256>>>(py, bn_w, bn_b, bn_mean, bn_var);

    // ---- fpn1 stage 2 ----
    repack_w_kernel<<<(3072 * 768 + 255) / 256, 256>>>(d2_w, pwp);
    pack(pwp, pb, 3072, 768, 768, 768, 1, 0, 0, 1, 0, 1.0f, 1);
    pack(py, pa, 4096, 768, 768, 768, 1, (size_t)4096 * 768, 0, 1,
         (size_t)4096 * 1536, 1.0f, BATCH);
    gemm_tc(pa, pb, ptmp, nullptr, nullptr, nullptr, 4096, 3072, 768,
            (size_t)4096 * 1536, 0, 3072, (size_t)4096 * 3072, 0, 1, 0, BATCH);
    scatter_bchw_kernel<<<(BATCH * 4096 * 3072 + 255) / 256, 256>>>(ptmp, d2_b, out1, 64);

    // ---- o2 ----
    repack_w_kernel<<<(3072 * 768 + 255) / 256, 256>>>(f2w, pwp);
    pack(pwp, pb, 3072, 768, 768, 768, 1, 0, 0, 1, 0, 1.0f, 1);
    pack(pf1 + 768, pa, 1024, 768, 768, 768, 1, (size_t)NT * 768, 0, 1,
         (size_t)1024 * 1536, 1.0f, BATCH);
    gemm_tc(pa, pb, ptmp, nullptr, nullptr, nullptr, 1024, 3072, 768,
            (size_t)1024 * 1536, 0, 3072, (size_t)1024 * 3072, 0, 1, 0, BATCH);
    scatter_bchw_kernel<<<(BATCH * 1024 * 3072 + 255) / 256, 256>>>(ptmp, f2b, out2, 32);

    (void)in_sizes; (void)n_in; (void)out_size;
}

// round 11
// speedup vs baseline: 1.0518x; 1.0518x over previous
#include <cuda_runtime.h>
#include <cuda_bf16.h>
#include <math.h>
#include <stdint.h>

#define NT    1025
#define EMB   768
#define BATCH 2
#define HEADS 12
#define NREL  3972

// ------------------------- device scratch (no allocs allowed) ---------------
__device__ float g_t[BATCH * NT * EMB];
__device__ float g_qkv[BATCH * NT * 3 * EMB];
__device__ float g_patch[BATCH * 1024 * EMB];
__device__ float g_tok[BATCH * 1024 * EMB];
__device__ float g_feat0[BATCH * NT * EMB];
__device__ float g_feat1[BATCH * NT * EMB];
__device__ float g_feat2[BATCH * NT * EMB];
__device__ float g_feat3[BATCH * NT * EMB];
__device__ float g_y[BATCH * 64 * 64 * EMB];
__device__ float g_tmp[(size_t)BATCH * 4096 * 3072];
__device__ float g_wpack[3072 * 768];
__device__ float g_qkvbias[3 * EMB];
__device__ __nv_bfloat16 g_pa[14000000];
__device__ __nv_bfloat16 g_pb[5000000];
__device__ __nv_bfloat16 g_pc[12700000];

__device__ __forceinline__ float gelu_exact(float x) {
    return 0.5f * x * (1.0f + erff(x * 0.70710678118654752f));
}

__device__ __forceinline__ uint32_t smem_u32(const void* p) {
    uint32_t a;
    asm("{ .reg .u64 t; cvta.to.shared.u64 t, %1; cvt.u32.u64 %0, t; }" : "=r"(a) : "l"(p));
    return a;
}

#define LDSM_X4(r0, r1, r2, r3, addr) \
    asm volatile("ldmatrix.sync.aligned.m8n8.x4.shared.b16 {%0,%1,%2,%3}, [%4];" \
                 : "=r"(r0), "=r"(r1), "=r"(r2), "=r"(r3) : "r"(addr))

#define MMA16816(d, a0, a1, a2, a3, b0, b1) \
    asm volatile("mma.sync.aligned.m16n8k16.row.col.f32.bf16.bf16.f32 " \
                 "{%0,%1,%2,%3}, {%4,%5,%6,%7}, {%8,%9}, {%0,%1,%2,%3};" \
                 : "+f"((d)[0]), "+f"((d)[1]), "+f"((d)[2]), "+f"((d)[3]) \
                 : "r"(a0), "r"(a1), "r"(a2), "r"(a3), "r"(b0), "r"(b1))

#define CP_ASYNC16(dst, src, sz) \
    asm volatile("cp.async.cg.shared.global [%0], [%1], 16, %2;" \
                 :: "r"(dst), "l"(src), "r"(sz))

__device__ __forceinline__ uint32_t pack_bf16(float x, float y) {
    __nv_bfloat162 t = __floats2bfloat162_rn(x, y);
    return *(uint32_t*)&t;
}
__device__ __forceinline__ void split2(float v, __nv_bfloat16& hi, __nv_bfloat16& lo) {
    hi = __float2bfloat16(v);
    lo = __float2bfloat16(v - __bfloat162float(hi));
}

// ========================= split-bf16 pack ([hi|lo]) ========================
__global__ void pack_kernel(const float* __restrict__ in, __nv_bfloat16* __restrict__ out,
                            int M, int K, int Kp, size_t irs, size_t ics,
                            size_t ibs0, size_t ibs1, int nh, size_t obs, float scale) {
    int idx = blockIdx.x * 256 + threadIdx.x;
    int z = blockIdx.y;
    if (idx >= M * Kp) return;
    int k = idx % Kp, m = idx / Kp;
    const float* src = in + (size_t)(z / nh) * ibs0 + (size_t)(z % nh) * ibs1;
    float v = (k < K) ? src[(size_t)m * irs + (size_t)k * ics] * scale : 0.f;
    __nv_bfloat16 hi, lo; split2(v, hi, lo);
    __nv_bfloat16* o = out + (size_t)z * obs + (size_t)m * (2 * (size_t)Kp);
    o[k] = hi; o[Kp + k] = lo;
}

// ---------------- fused LayerNorm + split-bf16 pack -------------------------
__global__ void ln_pack_kernel(const float* __restrict__ x, const float* __restrict__ w,
                               const float* __restrict__ b, __nv_bfloat16* __restrict__ out) {
    int r = blockIdx.x;
    const float* xr = x + (size_t)r * EMB;
    __shared__ float red[256];
    int tid = threadIdx.x;
    float s = 0.f;
    for (int i = tid; i < EMB; i += 256) s += xr[i];
    red[tid] = s; __syncthreads();
    for (int st = 128; st > 0; st >>= 1) { if (tid < st) red[tid] += red[tid + st]; __syncthreads(); }
    float mean = red[0] * (1.0f / EMB);
    __syncthreads();
    float s2 = 0.f;
    for (int i = tid; i < EMB; i += 256) { float d = xr[i] - mean; s2 += d * d; }
    red[tid] = s2; __syncthreads();
    for (int st = 128; st > 0; st >>= 1) { if (tid < st) red[tid] += red[tid + st]; __syncthreads(); }
    float inv = rsqrtf(red[0] * (1.0f / EMB) + 1e-6f);
    __nv_bfloat16* o = out + (size_t)r * (2 * EMB);
    for (int i = tid; i < EMB; i += 256) {
        float v = (xr[i] - mean) * inv * w[i] + b[i];
        __nv_bfloat16 hi, lo; split2(v, hi, lo);
        o[i] = hi; o[EMB + i] = lo;
    }
}

// ========================= HMMA GEMM (split-product reuse) ==================
// Operands packed [hi|lo] along K. S += Ahi*Bhi + Ahi*Blo + Alo*Bhi.
// BM x BN block tile (8 warps, warp tile (BM/2) x (BN/4)), NSTAGE cp.async ring.
template <int BM, int BN, int NSTAGE, int MINB>
__global__ void __launch_bounds__(256, MINB) hgemm2(
    const __nv_bfloat16* __restrict__ A, const __nv_bfloat16* __restrict__ B,
    float* __restrict__ C, __nv_bfloat16* __restrict__ Cp,
    const float* __restrict__ bias, const float* __restrict__ resid,
    int M, int Nreal, int Kp, size_t Abs, size_t Bbs,
    size_t ldc, size_t cs0, size_t cs1, int nh, int do_gelu) {
    constexpr int MT = BM / 32;          // m16 tiles per warp (4 or 2)
    constexpr int WTN = BN / 4;
    constexpr int NT8 = WTN / 8;
    constexpr int AIT = BM / 64;         // A uint4 loads per thread per section
    constexpr int NB4 = BN / 64;
    constexpr int AHALF = BM * 40;
    constexpr int BHALF = BN * 40;
    constexpr int STAGE = 2 * (AHALF + BHALF);
    extern __shared__ __nv_bfloat16 dsm[];

    int tid = threadIdx.x;
    int wid = tid >> 5, lane = tid & 31;
    int warp_m = wid >> 2, warp_n = wid & 3;
    int m0 = blockIdx.y * BM, n0 = blockIdx.x * BN;
    int z = blockIdx.z;

    const size_t lda = 2 * (size_t)Kp, ldb = 2 * (size_t)Kp;
    const __nv_bfloat16* Az = A + (size_t)z * Abs;
    const __nv_bfloat16* Bz = B + (size_t)z * Bbs;

    float acc[MT][NT8][4];
#pragma unroll
    for (int i = 0; i < MT; i++)
#pragma unroll
        for (int j = 0; j < NT8; j++)
#pragma unroll
            for (int e = 0; e < 4; e++) acc[i][j][e] = 0.f;

    int nk = Kp >> 5;

    auto load_body = [&](int c, int s) {
        __nv_bfloat16* st = dsm + s * STAGE;
#pragma unroll
        for (int sec = 0; sec < 2; sec++) {
#pragma unroll
            for (int i = 0; i < AIT; i++) {
                int idx = tid + i * 256, row = idx >> 2, cg = idx & 3;
                uint32_t dst = smem_u32(st + sec * AHALF + row * 40 + cg * 8);
                const __nv_bfloat16* src = Az + (size_t)(m0 + row) * lda +
                                           (size_t)sec * Kp + c * 32 + cg * 8;
                CP_ASYNC16(dst, src, (m0 + row < M) ? 16 : 0);
            }
        }
#pragma unroll
        for (int sec = 0; sec < 2; sec++) {
#pragma unroll
            for (int i = 0; i < NB4; i++) {
                int idx = tid + i * 256, row = idx >> 2, cg = idx & 3;
                uint32_t dst = smem_u32(st + 2 * AHALF + sec * BHALF + row * 40 + cg * 8);
                const __nv_bfloat16* src = Bz + (size_t)(n0 + row) * ldb +
                                           (size_t)sec * Kp + c * 32 + cg * 8;
                CP_ASYNC16(dst, src, (n0 + row < Nreal) ? 16 : 0);
            }
        }
    };

#pragma unroll
    for (int s = 0; s < NSTAGE - 1; s++) {
        if (s < nk) load_body(s, s);
        asm volatile("cp.async.commit_group;");
    }

    uint32_t aoff = (warp_m * (BM / 2) + (lane & 15)) * 40 + (lane >> 4) * 8;
    uint32_t boff = (warp_n * WTN + ((lane >> 4) << 3) + (lane & 7)) * 40 + ((lane >> 3) & 1) * 8;
    uint32_t dsm0 = smem_u32(dsm);

    for (int c = 0; c < nk; c++) {
        asm volatile("cp.async.wait_group %0;" :: "n"(NSTAGE - 2));
        __syncthreads();
        {
            int ncd = c + NSTAGE - 1;
            if (ncd < nk) load_body(ncd, ncd % NSTAGE);
            asm volatile("cp.async.commit_group;");
        }
        uint32_t sbase = dsm0 + (c % NSTAGE) * STAGE * 2;
#pragma unroll
        for (int kk = 0; kk < 2; kk++) {
            uint32_t ahi[MT][4], alo[MT][4];
#pragma unroll
            for (int mt = 0; mt < MT; mt++) {
                uint32_t ad = sbase + (aoff + mt * 16 * 40 + kk * 16) * 2;
                LDSM_X4(ahi[mt][0], ahi[mt][1], ahi[mt][2], ahi[mt][3], ad);
                LDSM_X4(alo[mt][0], alo[mt][1], alo[mt][2], alo[mt][3], ad + AHALF * 2);
            }
            uint32_t bhi[NT8][2], blo[NT8][2];
#pragma unroll
            for (int p = 0; p < NT8 / 2; p++) {
                uint32_t bd = sbase + 2 * AHALF * 2 + (boff + p * 16 * 40 + kk * 16) * 2;
                LDSM_X4(bhi[2 * p][0], bhi[2 * p][1], bhi[2 * p + 1][0], bhi[2 * p + 1][1], bd);
                LDSM_X4(blo[2 * p][0], blo[2 * p][1], blo[2 * p + 1][0], blo[2 * p + 1][1],
                        bd + BHALF * 2);
            }
#pragma unroll
            for (int mt = 0; mt < MT; mt++)
#pragma unroll
                for (int nt = 0; nt < NT8; nt++)
                    MMA16816(acc[mt][nt], ahi[mt][0], ahi[mt][1], ahi[mt][2], ahi[mt][3],
                             bhi[nt][0], bhi[nt][1]);
#pragma unroll
            for (int mt = 0; mt < MT; mt++)
#pragma unroll
                for (int nt = 0; nt < NT8; nt++)
                    MMA16816(acc[mt][nt], ahi[mt][0], ahi[mt][1], ahi[mt][2], ahi[mt][3],
                             blo[nt][0], blo[nt][1]);
#pragma unroll
            for (int mt = 0; mt < MT; mt++)
#pragma unroll
                for (int nt = 0; nt < NT8; nt++)
                    MMA16816(acc[mt][nt], alo[mt][0], alo[mt][1], alo[mt][2], alo[mt][3],
                             bhi[nt][0], bhi[nt][1]);
        }
    }

    size_t cbase = (size_t)(z / nh) * cs0 + (size_t)(z % nh) * cs1;
    int mrow = lane >> 2, ncol = (lane & 3) * 2;
#pragma unroll
    for (int mt = 0; mt < MT; mt++) {
#pragma unroll
        for (int half = 0; half < 2; half++) {
            int row = m0 + warp_m * (BM / 2) + mt * 16 + mrow + half * 8;
            if (row >= M) continue;
#pragma unroll
            for (int nt = 0; nt < NT8; nt++) {
                int col = n0 + warp_n * WTN + nt * 8 + ncol;
                float v0 = acc[mt][nt][half * 2];
                float v1 = acc[mt][nt][half * 2 + 1];
                if (bias) { v0 += bias[col]; v1 += bias[col + 1]; }
                if (resid) {
                    size_t off = cbase + (size_t)row * ldc + col;
                    v0 += resid[off]; v1 += resid[off + 1];
                }
                if (do_gelu) { v0 = gelu_exact(v0); v1 = gelu_exact(v1); }
                if (C) {
                    size_t off = cbase + (size_t)row * ldc + col;
                    if (col < Nreal) C[off] = v0;
                    if (col + 1 < Nreal) C[off + 1] = v1;
                }
                if (Cp) {
                    __nv_bfloat16 h0, l0b, h1, l1b;
                    split2(v0, h0, l0b); split2(v1, h1, l1b);
                    __nv_bfloat16* o = Cp + (size_t)row * (2 * (size_t)Nreal);
                    if (col + 1 < Nreal) {
                        *(uint32_t*)&o[col] = pack_bf16(__bfloat162float(h0), __bfloat162float(h1));
                        *(uint32_t*)&o[Nreal + col] = pack_bf16(__bfloat162float(l0b), __bfloat162float(l1b));
                    } else if (col < Nreal) {
                        o[col] = h0; o[Nreal + col] = l0b;
                    }
                }
            }
        }
    }
}

// ========================= fused flash attention ============================
#define FA_LD 136
__global__ void __launch_bounds__(256, 2) flash_attn_kernel(
    const float* __restrict__ qkv, const float* __restrict__ relt,
    const int* __restrict__ relidx, __nv_bfloat16* __restrict__ opk) {
    extern __shared__ __nv_bfloat16 fsm[];
    __nv_bfloat16* sQ = fsm;
    __nv_bfloat16* sK = fsm + 128 * FA_LD;
    __nv_bfloat16* sV = sK + 64 * FA_LD;

    int tid = threadIdx.x, wid = tid >> 5, lane = tid & 31;
    int i0 = blockIdx.x * 128;
    int z = blockIdx.y;
    int b = z / HEADS, h = z % HEADS;
    const float* qb = qkv + (size_t)b * NT * 2304 + h * 64;
    const float* kb = qb + 768;
    const float* vb = qb + 1536;

    for (int idx = tid; idx < 128 * 64; idx += 256) {
        int r = idx >> 6, c = idx & 63;
        int gi = i0 + r;
        float v = (gi < NT) ? qb[(size_t)gi * 2304 + c] * 0.125f : 0.f;
        __nv_bfloat16 hi, lo; split2(v, hi, lo);
        sQ[r * FA_LD + c] = hi;
        sQ[r * FA_LD + 64 + c] = lo;
    }

    float m0 = -1e30f, m1 = -1e30f, l0 = 0.f, l1 = 0.f;
    float O[8][4];
#pragma unroll
    for (int t = 0; t < 8; t++)
#pragma unroll
        for (int e = 0; e < 4; e++) O[t][e] = 0.f;

    int r0g = i0 + wid * 16 + (lane >> 2);
    int r1g = r0g + 8;

    for (int j0 = 0; j0 < NT; j0 += 64) {
        __syncthreads();
        for (int idx = tid; idx < 64 * 64; idx += 256) {
            int r = idx >> 6, c = idx & 63;
            int gj = j0 + r;
            float kv = (gj < NT) ? kb[(size_t)gj * 2304 + c] : 0.f;
            __nv_bfloat16 khi, klo; split2(kv, khi, klo);
            sK[r * FA_LD + c] = khi;
            sK[r * FA_LD + 64 + c] = klo;
            float vv = (gj < NT) ? vb[(size_t)gj * 2304 + c] : 0.f;
            __nv_bfloat16 vhi, vlo; split2(vv, vhi, vlo);
            sV[c * FA_LD + r] = vhi;
            sV[c * FA_LD + 64 + r] = vlo;
        }
        __syncthreads();

        float S[8][4];
#pragma unroll
        for (int t = 0; t < 8; t++)
#pragma unroll
            for (int e = 0; e < 4; e++) S[t][e] = 0.f;

        const int qsec[3] = {0, 1, 0}, ksec[3] = {0, 0, 1};
#pragma unroll
        for (int sp = 0; sp < 3; sp++) {
#pragma unroll
            for (int kk = 0; kk < 4; kk++) {
                uint32_t a0, a1, a2, a3;
                uint32_t addr = smem_u32(&sQ[(wid * 16 + (lane & 15)) * FA_LD +
                                             qsec[sp] * 64 + kk * 16 + (lane >> 4) * 8]);
                LDSM_X4(a0, a1, a2, a3, addr);
                uint32_t bf[8][2];
#pragma unroll
                for (int p = 0; p < 4; p++) {
                    uint32_t ba = smem_u32(&sK[(p * 16 + ((lane >> 4) << 3) + (lane & 7)) * FA_LD +
                                               ksec[sp] * 64 + kk * 16 + ((lane >> 3) & 1) * 8]);
                    LDSM_X4(bf[2 * p][0], bf[2 * p][1], bf[2 * p + 1][0], bf[2 * p + 1][1], ba);
                }
#pragma unroll
                for (int nt = 0; nt < 8; nt++)
                    MMA16816(S[nt], a0, a1, a2, a3, bf[nt][0], bf[nt][1]);
            }
        }

#pragma unroll
        for (int nt = 0; nt < 8; nt++) {
            int c0 = j0 + nt * 8 + (lane & 3) * 2;
#pragma unroll
            for (int e = 0; e < 2; e++) {
                int jj = c0 + e;
                if (jj < NT) {
                    if (r0g < NT) S[nt][e]     += relt[(size_t)relidx[(size_t)r0g * NT + jj] * HEADS + h];
                    if (r1g < NT) S[nt][2 + e] += relt[(size_t)relidx[(size_t)r1g * NT + jj] * HEADS + h];
                } else {
                    S[nt][e] = -1e30f;
                    S[nt][2 + e] = -1e30f;
                }
            }
        }

        float t0 = -1e30f, t1 = -1e30f;
#pragma unroll
        for (int nt = 0; nt < 8; nt++) {
            t0 = fmaxf(t0, fmaxf(S[nt][0], S[nt][1]));
            t1 = fmaxf(t1, fmaxf(S[nt][2], S[nt][3]));
        }
        t0 = fmaxf(t0, __shfl_xor_sync(0xffffffff, t0, 1));
        t0 = fmaxf(t0, __shfl_xor_sync(0xffffffff, t0, 2));
        t1 = fmaxf(t1, __shfl_xor_sync(0xffffffff, t1, 1));
        t1 = fmaxf(t1, __shfl_xor_sync(0xffffffff, t1, 2));
        float mn0 = fmaxf(m0, t0), mn1 = fmaxf(m1, t1);
        float al0 = __expf(m0 - mn0), al1 = __expf(m1 - mn1);
#pragma unroll
        for (int nt = 0; nt < 8; nt++) {
            O[nt][0] *= al0; O[nt][1] *= al0;
            O[nt][2] *= al1; O[nt][3] *= al1;
        }
        float ls0 = 0.f, ls1 = 0.f;
        uint32_t phi[4][4], plo[4][4];
#pragma unroll
        for (int kk = 0; kk < 4; kk++) {
#pragma unroll
            for (int tt = 0; tt < 2; tt++) {
                int t = 2 * kk + tt;
                float p0 = __expf(S[t][0] - mn0), p1 = __expf(S[t][1] - mn0);
                float p2 = __expf(S[t][2] - mn1), p3 = __expf(S[t][3] - mn1);
                ls0 += p0 + p1; ls1 += p2 + p3;
                float h0 = __bfloat162float(__float2bfloat16(p0));
                float h1 = __bfloat162float(__float2bfloat16(p1));
                float h2 = __bfloat162float(__float2bfloat16(p2));
                float h3 = __bfloat162float(__float2bfloat16(p3));
                phi[kk][tt * 2]     = pack_bf16(h0, h1);
                phi[kk][tt * 2 + 1] = pack_bf16(h2, h3);
                plo[kk][tt * 2]     = pack_bf16(p0 - h0, p1 - h1);
                plo[kk][tt * 2 + 1] = pack_bf16(p2 - h2, p3 - h3);
            }
        }
        ls0 += __shfl_xor_sync(0xffffffff, ls0, 1);
        ls0 += __shfl_xor_sync(0xffffffff, ls0, 2);
        ls1 += __shfl_xor_sync(0xffffffff, ls1, 1);
        ls1 += __shfl_xor_sync(0xffffffff, ls1, 2);
        l0 = l0 * al0 + ls0;
        l1 = l1 * al1 + ls1;
        m0 = mn0; m1 = mn1;

        const int vsec[3] = {0, 0, 1};
#pragma unroll
        for (int sp = 0; sp < 3; sp++) {
#pragma unroll
            for (int kk = 0; kk < 4; kk++) {
                uint32_t* A = (sp == 1) ? plo[kk] : phi[kk];
                uint32_t bf[8][2];
#pragma unroll
                for (int p = 0; p < 4; p++) {
                    uint32_t ba = smem_u32(&sV[(p * 16 + ((lane >> 4) << 3) + (lane & 7)) * FA_LD +
                                               vsec[sp] * 64 + kk * 16 + ((lane >> 3) & 1) * 8]);
                    LDSM_X4(bf[2 * p][0], bf[2 * p][1], bf[2 * p + 1][0], bf[2 * p + 1][1], ba);
                }
#pragma unroll
                for (int nt = 0; nt < 8; nt++)
                    MMA16816(O[nt], A[0], A[1], A[2], A[3], bf[nt][0], bf[nt][1]);
            }
        }
    }

    float il0 = 1.0f / l0, il1 = 1.0f / l1;
#pragma unroll
    for (int nt = 0; nt < 8; nt++) {
        int d = h * 64 + nt * 8 + (lane & 3) * 2;
        if (r0g < NT) {
            float v0 = O[nt][0] * il0, v1 = O[nt][1] * il0;
            __nv_bfloat16 h0, lo0, h1, lo1;
            split2(v0, h0, lo0); split2(v1, h1, lo1);
            __nv_bfloat16* o = opk + ((size_t)b * NT + r0g) * 1536;
            *(uint32_t*)&o[d] = pack_bf16(__bfloat162float(h0), __bfloat162float(h1));
            *(uint32_t*)&o[768 + d] = pack_bf16(__bfloat162float(lo0), __bfloat162float(lo1));
        }
        if (r1g < NT) {
            float v0 = O[nt][2] * il1, v1 = O[nt][3] * il1;
            __nv_bfloat16 h0, lo0, h1, lo1;
            split2(v0, h0, lo0); split2(v1, h1, lo1);
            __nv_bfloat16* o = opk + ((size_t)b * NT + r1g) * 1536;
            *(uint32_t*)&o[d] = pack_bf16(__bfloat162float(h0), __bfloat162float(h1));
            *(uint32_t*)&o[768 + d] = pack_bf16(__bfloat162float(lo0), __bfloat162float(lo1));
        }
    }
}

// ------------------------- elementwise helpers ------------------------------
__global__ void patchify_kernel(const float* __restrict__ x, float* __restrict__ A) {
    int idx = blockIdx.x * 256 + threadIdx.x;
    if (idx >= BATCH * 1024 * EMB) return;
    int col = idx % EMB;
    int m = idx / EMB;
    int b = m / 1024, g = m % 1024;
    int gh = g / 32, gw = g % 32;
    int c = col / 256, rem = col % 256;
    int i = rem / 16, j = rem % 16;
    A[idx] = x[(((size_t)(b * 3 + c) * 512) + gh * 16 + i) * 512 + gw * 16 + j];
}

__global__ void assemble_kernel(const float* __restrict__ tok, const float* __restrict__ cls,
                                const float* __restrict__ pos, float* __restrict__ t) {
    int idx = blockIdx.x * 256 + threadIdx.x;
    if (idx >= BATCH * NT * EMB) return;
    int d = idx % EMB;
    int n = (idx / EMB) % NT;
    int b = idx / (EMB * NT);
    float v = (n == 0) ? cls[d] : tok[((size_t)b * 1024 + (n - 1)) * EMB + d];
    t[idx] = v + pos[n * EMB + d];
}

__global__ void biaspack_kernel(const float* __restrict__ qb, const float* __restrict__ vb,
                                float* __restrict__ out) {
    int i = blockIdx.x * 256 + threadIdx.x;
    if (i >= 3 * EMB) return;
    out[i] = (i < EMB) ? qb[i] : ((i < 2 * EMB) ? 0.f : vb[i - 2 * EMB]);
}

__global__ void copy_kernel(const float* __restrict__ src, float* __restrict__ dst, int n) {
    int i = blockIdx.x * 256 + threadIdx.x;
    if (i < n) dst[i] = src[i];
}

__global__ void repack_w_kernel(const float* __restrict__ w, float* __restrict__ wp) {
    int idx = blockIdx.x * 256 + threadIdx.x;
    if (idx >= 3072 * 768) return;
    int c = idx % 768, n = idx / 768;
    int ij = n / 768, d = n % 768;
    wp[idx] = w[(size_t)c * 3072 + d * 4 + ij];
}

__global__ void scatter_bhwc_kernel(const float* __restrict__ tmp, const float* __restrict__ bias,
                                    float* __restrict__ y, int HW) {
    int total = BATCH * HW * HW * 4 * 768;
    int idx = blockIdx.x * 256 + threadIdx.x;
    if (idx >= total) return;
    int d = idx % 768;
    int ij = (idx / 768) % 4;
    int p = (idx / 3072) % (HW * HW);
    int b = idx / (3072 * HW * HW);
    int h = p / HW, w = p % HW, i = ij / 2, j = ij % 2;
    int W2 = 2 * HW;
    y[(((size_t)b * W2 + 2 * h + i) * W2 + (2 * w + j)) * 768 + d] = tmp[idx] + bias[d];
}

__global__ void scatter_bchw_kernel(const float* __restrict__ tmp, const float* __restrict__ bias,
                                    float* __restrict__ out, int HW) {
    int total = BATCH * HW * HW * 4 * 768;
    int idx = blockIdx.x * 256 + threadIdx.x;
    if (idx >= total) return;
    int d = idx % 768;
    int ij = (idx / 768) % 4;
    int p = (idx / 3072) % (HW * HW);
    int b = idx / (3072 * HW * HW);
    int h = p / HW, w = p % HW, i = ij / 2, j = ij % 2;
    int W2 = 2 * HW;
    out[(((size_t)b * 768 + d) * W2 + 2 * h + i) * W2 + (2 * w + j)] = tmp[idx] + bias[d];
}

__global__ void bn_gelu_kernel(float* __restrict__ y, const float* __restrict__ w,
                               const float* __restrict__ b, const float* __restrict__ mean,
                               const float* __restrict__ var) {
    int idx = blockIdx.x * 256 + threadIdx.x;
    if (idx >= BATCH * 64 * 64 * 768) return;
    int c = idx % 768;
    float v = y[idx];
    v = (v - mean[c]) * rsqrtf(var[c] + 1e-5f) * w[c] + b[c];
    y[idx] = gelu_exact(v);
}

__global__ void to_map_kernel(const float* __restrict__ feat, float* __restrict__ out) {
    int idx = blockIdx.x * 256 + threadIdx.x;
    if (idx >= BATCH * 768 * 32 * 32) return;
    int xw = idx % 32;
    int yh = (idx / 32) % 32;
    int c = (idx / 1024) % 768;
    int b = idx / (1024 * 768);
    out[idx] = feat[((size_t)b * NT + 1 + yh * 32 + xw) * EMB + c];
}

__global__ void maxpool_kernel(const float* __restrict__ feat, float* __restrict__ out) {
    int idx = blockIdx.x * 256 + threadIdx.x;
    if (idx >= BATCH * 768 * 16 * 16) return;
    int xw = idx % 16;
    int yh = (idx / 16) % 16;
    int c = (idx / 256) % 768;
    int b = idx / (256 * 768);
    float m = -1e30f;
#pragma unroll
    for (int i = 0; i < 2; i++)
#pragma unroll
        for (int j = 0; j < 2; j++) {
            int Y = 2 * yh + i, X = 2 * xw + j;
            m = fmaxf(m, feat[((size_t)b * NT + 1 + Y * 32 + X) * EMB + c]);
        }
    out[idx] = m;
}

// ------------------------- host helpers -------------------------------------
static void pack(const float* in, __nv_bfloat16* out, int M, int K, int Kp,
                 size_t irs, size_t ics, size_t ibs0, size_t ibs1, int nh,
                 size_t obs, float scale, int nz) {
    dim3 g((M * Kp + 255) / 256, nz);
    pack_kernel<<<g, 256>>>(in, out, M, K, Kp, irs, ics, ibs0, ibs1, nh, obs, scale);
}
#define SMEM_BIG   (2 * 2 * (128 + 128) * 40 * 2)   // 81920, BM128/BN128 2-stage
#define SMEM_SMALL (3 * 2 * (64 + 64) * 40 * 2)     // 61440, BM64/BN64 3-stage
static void gemm_tc(const __nv_bfloat16* A, const __nv_bfloat16* B, float* C,
                    __nv_bfloat16* Cp, const float* bias, const float* resid,
                    int M, int N, int Kp, size_t Abs, size_t Bbs, size_t ldc,
                    size_t cs0, size_t cs1, int nh, int gelu, int nz) {
    int gm128 = (M + 127) / 128;
    if (N % 128 == 0 && (N / 128) * gm128 * nz >= 148) {
        dim3 g(N / 128, gm128, nz);
        hgemm2<128, 128, 2, 2><<<g, 256, SMEM_BIG>>>(A, B, C, Cp, bias, resid, M, N, Kp,
                                                     Abs, Bbs, ldc, cs0, cs1, nh, gelu);
    } else {
        dim3 g(N / 64, (M + 63) / 64, nz);
        hgemm2<64, 64, 3, 3><<<g, 256, SMEM_SMALL>>>(A, B, C, Cp, bias, resid, M, N, Kp,
                                                     Abs, Bbs, ldc, cs0, cs1, nh, gelu);
    }
}

extern "C" void kernel_launch(void* const* d_in, const int* in_sizes, int n_in,
                              void* d_out, int out_size) {
    const float* x         = (const float*)d_in[0];
    const float* patch_w   = (const float*)d_in[1];
    const float* patch_b   = (const float*)d_in[2];
    const float* cls_token = (const float*)d_in[3];
    const float* pos_embed = (const float*)d_in[4];
    const float* ln1_w     = (const float*)d_in[5];
    const float* ln1_b     = (const float*)d_in[6];
    const float* qkv_w     = (const float*)d_in[7];
    const float* q_bias    = (const float*)d_in[8];
    const float* v_bias    = (const float*)d_in[9];
    const float* rel_tab   = (const float*)d_in[10];
    const float* proj_w    = (const float*)d_in[11];
    const float* proj_b    = (const float*)d_in[12];
    const float* ln2_w     = (const float*)d_in[13];
    const float* ln2_b     = (const float*)d_in[14];
    const float* fc1_w     = (const float*)d_in[15];
    const float* fc1_b     = (const float*)d_in[16];
    const float* fc2_w     = (const float*)d_in[17];
    const float* fc2_b     = (const float*)d_in[18];
    const float* d1_w      = (const float*)d_in[19];
    const float* d1_b      = (const float*)d_in[20];
    const float* bn_w      = (const float*)d_in[21];
    const float* bn_b      = (const float*)d_in[22];
    const float* bn_mean   = (const float*)d_in[23];
    const float* bn_var    = (const float*)d_in[24];
    const float* d2_w      = (const float*)d_in[25];
    const float* d2_b      = (const float*)d_in[26];
    const float* f2w       = (const float*)d_in[27];
    const float* f2b       = (const float*)d_in[28];
    const int*   rel_idx   = (const int*)d_in[29];

    float* out = (float*)d_out;
    float* out1 = out;
    float* out2 = out1 + (size_t)BATCH * 768 * 128 * 128;
    float* out3 = out2 + (size_t)BATCH * 768 * 64 * 64;
    float* out4 = out3 + (size_t)BATCH * 768 * 32 * 32;

    static float *pt = nullptr, *pqkv, *ppatch, *ptok;
    static float *pf0, *pf1, *pf2, *pf3, *py, *ptmp, *pwp, *pqb;
    static __nv_bfloat16 *pa, *pb, *pc;
    if (!pt) {
        cudaGetSymbolAddress((void**)&pt, g_t);
        cudaGetSymbolAddress((void**)&pqkv, g_qkv);
        cudaGetSymbolAddress((void**)&ppatch, g_patch);
        cudaGetSymbolAddress((void**)&ptok, g_tok);
        cudaGetSymbolAddress((void**)&pf0, g_feat0);
        cudaGetSymbolAddress((void**)&pf1, g_feat1);
        cudaGetSymbolAddress((void**)&pf2, g_feat2);
        cudaGetSymbolAddress((void**)&pf3, g_feat3);
        cudaGetSymbolAddress((void**)&py, g_y);
        cudaGetSymbolAddress((void**)&ptmp, g_tmp);
        cudaGetSymbolAddress((void**)&pwp, g_wpack);
        cudaGetSymbolAddress((void**)&pqb, g_qkvbias);
        cudaGetSymbolAddress((void**)&pa, g_pa);
        cudaGetSymbolAddress((void**)&pb, g_pb);
        cudaGetSymbolAddress((void**)&pc, g_pc);
        cudaFuncSetAttribute(flash_attn_kernel,
                             cudaFuncAttributeMaxDynamicSharedMemorySize,
                             (128 + 64 + 64) * FA_LD * 2);
        cudaFuncSetAttribute((const void*)hgemm2<128, 128, 2, 2>,
                             cudaFuncAttributeMaxDynamicSharedMemorySize, SMEM_BIG);
        cudaFuncSetAttribute((const void*)hgemm2<64, 64, 3, 3>,
                             cudaFuncAttributeMaxDynamicSharedMemorySize, SMEM_SMALL);
    }

    const int TOKELEMS = BATCH * NT * EMB;
    const int M = BATCH * NT;  // 2050
    const int FA_SMEM = (128 + 64 + 64) * FA_LD * 2;

    // ---- patch embed ----
    patchify_kernel<<<(BATCH * 1024 * EMB + 255) / 256, 256>>>(x, ppatch);
    pack(ppatch, pa, 2048, 768, 768, 768, 1, 0, 0, 1, 0, 1.0f, 1);
    pack(patch_w, pb, 768, 768, 768, 768, 1, 0, 0, 1, 0, 1.0f, 1);
    gemm_tc(pa, pb, ptok, nullptr, patch_b, nullptr, 2048, 768, 768, 0, 0,
            768, 0, 0, 1, 0, 1);
    assemble_kernel<<<(TOKELEMS + 255) / 256, 256>>>(ptok, cls_token, pos_embed, pt);

    // ---- transformer layers ----
    for (int l = 0; l < 12; l++) {
        ln_pack_kernel<<<M, 256>>>(pt, ln1_w + l * EMB, ln1_b + l * EMB, pa);
        biaspack_kernel<<<(3 * EMB + 255) / 256, 256>>>(q_bias + l * EMB, v_bias + l * EMB, pqb);
        pack(qkv_w + (size_t)l * 2304 * 768, pb, 2304, 768, 768, 768, 1, 0, 0, 1, 0, 1.0f, 1);
        gemm_tc(pa, pb, pqkv, nullptr, pqb, nullptr, M, 2304, 768, 0, 0,
                2304, 0, 0, 1, 0, 1);
        {
            dim3 g((NT + 127) / 128, BATCH * HEADS);
            flash_attn_kernel<<<g, 256, FA_SMEM>>>(pqkv, rel_tab + (size_t)l * NREL * HEADS,
                                                   rel_idx, pa);
        }
        pack(proj_w + (size_t)l * 768 * 768, pb, 768, 768, 768, 768, 1, 0, 0, 1, 0, 1.0f, 1);
        gemm_tc(pa, pb, pt, nullptr, proj_b + l * EMB, pt, M, 768, 768, 0, 0,
                768, 0, 0, 1, 0, 1);
        ln_pack_kernel<<<M, 256>>>(pt, ln2_w + l * EMB, ln2_b + l * EMB, pa);
        pack(fc1_w + (size_t)l * 3072 * 768, pb, 3072, 768, 768, 768, 1, 0, 0, 1, 0, 1.0f, 1);
        gemm_tc(pa, pb, nullptr, pc, fc1_b + l * 4 * EMB, nullptr, M, 3072, 768, 0, 0,
                3072, 0, 0, 1, 1, 1);
        pack(fc2_w + (size_t)l * 768 * 3072, pb, 768, 3072, 3072, 3072, 1, 0, 0, 1, 0, 1.0f, 1);
        gemm_tc(pc, pb, pt, nullptr, fc2_b + l * EMB, pt, M, 768, 3072, 0, 0,
                768, 0, 0, 1, 0, 1);
        float* fdst = nullptr;
        if (l == 3) fdst = pf0;
        else if (l == 5) fdst = pf1;
        else if (l == 7) fdst = pf2;
        else if (l == 11) fdst = pf3;
        if (fdst) copy_kernel<<<(TOKELEMS + 255) / 256, 256>>>(pt, fdst, TOKELEMS);
    }

    // ---- o3 / o4 ----
    to_map_kernel<<<(BATCH * 768 * 1024 + 255) / 256, 256>>>(pf2, out3);
    maxpool_kernel<<<(BATCH * 768 * 256 + 255) / 256, 256>>>(pf3, out4);

    // ---- fpn1 stage 1 ----
    repack_w_kernel<<<(3072 * 768 + 255) / 256, 256>>>(d1_w, pwp);
    pack(pwp, pb, 3072, 768, 768, 768, 1, 0, 0, 1, 0, 1.0f, 1);
    pack(pf0 + 768, pa, 1024, 768, 768, 768, 1, (size_t)NT * 768, 0, 1,
         (size_t)1024 * 1536, 1.0f, BATCH);
    gemm_tc(pa, pb, ptmp, nullptr, nullptr, nullptr, 1024, 3072, 768,
            (size_t)1024 * 1536, 0, 3072, (size_t)1024 * 3072, 0, 1, 0, BATCH);
    scatter_bhwc_kernel<<<(BATCH * 1024 * 3072 + 255) / 256, 256>>>(ptmp, d1_b, py, 32);
    bn_gelu_kernel<<<(BATCH * 64 * 64 * 768 + 255) / 256, 256>>>(py, bn_w, bn_b, bn_mean, bn_var);

    // ---- fpn1 stage 2 ----
    repack_w_kernel<<<(3072 * 768 + 255) / 256, 256>>>(d2_w, pwp);
    pack(pwp, pb, 3072, 768, 768, 768, 1, 0, 0, 1, 0, 1.0f, 1);
    pack(py, pa, 4096, 768, 768, 768, 1, (size_t)4096 * 768, 0, 1,
         (size_t)4096 * 1536, 1.0f, BATCH);
    gemm_tc(pa, pb, ptmp, nullptr, nullptr, nullptr, 4096, 3072, 768,
            (size_t)4096 * 1536, 0, 3072, (size_t)4096 * 3072, 0, 1, 0, BATCH);
    scatter_bchw_kernel<<<(BATCH * 4096 * 3072 + 255) / 256, 256>>>(ptmp, d2_b, out1, 64);

    // ---- o2 ----
    repack_w_kernel<<<(3072 * 768 + 255) / 256, 256>>>(f2w, pwp);
    pack(pwp, pb, 3072, 768, 768, 768, 1, 0, 0, 1, 0, 1.0f, 1);
    pack(pf1 + 768, pa, 1024, 768, 768, 768, 1, (size_t)NT * 768, 0, 1,
         (size_t)1024 * 1536, 1.0f, BATCH);
    gemm_tc(pa, pb, ptmp, nullptr, nullptr, nullptr, 1024, 3072, 768,
            (size_t)1024 * 1536, 0, 3072, (size_t)1024 * 3072, 0, 1, 0, BATCH);
    scatter_bchw_kernel<<<(BATCH * 1024 * 3072 + 255) / 256, 256>>>(ptmp, f2b, out2, 32);

    (void)in_sizes; (void)n_in; (void)out_size;
}

// round 12
// speedup vs baseline: 1.2061x; 1.1468x over previous
#include <cuda_runtime.h>
#include <cuda_bf16.h>
#include <math.h>
#include <stdint.h>

#define NT    1025
#define EMB   768
#define BATCH 2
#define HEADS 12
#define NREL  3972

// ------------------------- device scratch (no allocs allowed) ---------------
__device__ float g_t[BATCH * NT * EMB];
__device__ float g_qkv[BATCH * NT * 3 * EMB];
__device__ float g_patch[BATCH * 1024 * EMB];
__device__ float g_tok[BATCH * 1024 * EMB];
__device__ float g_feat0[BATCH * NT * EMB];
__device__ float g_feat1[BATCH * NT * EMB];
__device__ float g_feat2[BATCH * NT * EMB];
__device__ float g_feat3[BATCH * NT * EMB];
__device__ float g_y[BATCH * 64 * 64 * EMB];
__device__ float g_tmp[(size_t)BATCH * 4096 * 3072];
__device__ float g_wpack[3072 * 768];
__device__ float g_qkvbias[12 * 3 * EMB];
__device__ __nv_bfloat16 g_pa[14000000];
__device__ __nv_bfloat16 g_pb[5000000];
__device__ __nv_bfloat16 g_pc[12700000];
// all transformer weights pre-packed [hi|lo]: per layer qkv|proj|fc1|fc2
#define W_QKV  0
#define W_PROJ 3538944
#define W_FC1  4718592
#define W_FC2  9437184
#define W_PER  14155776
__device__ __nv_bfloat16 g_pw[12 * 14155776];

__device__ __forceinline__ float gelu_exact(float x) {
    return 0.5f * x * (1.0f + erff(x * 0.70710678118654752f));
}

__device__ __forceinline__ uint32_t smem_u32(const void* p) {
    uint32_t a;
    asm("{ .reg .u64 t; cvta.to.shared.u64 t, %1; cvt.u32.u64 %0, t; }" : "=r"(a) : "l"(p));
    return a;
}

#define LDSM_X4(r0, r1, r2, r3, addr) \
    asm volatile("ldmatrix.sync.aligned.m8n8.x4.shared.b16 {%0,%1,%2,%3}, [%4];" \
                 : "=r"(r0), "=r"(r1), "=r"(r2), "=r"(r3) : "r"(addr))

#define MMA16816(d, a0, a1, a2, a3, b0, b1) \
    asm volatile("mma.sync.aligned.m16n8k16.row.col.f32.bf16.bf16.f32 " \
                 "{%0,%1,%2,%3}, {%4,%5,%6,%7}, {%8,%9}, {%0,%1,%2,%3};" \
                 : "+f"((d)[0]), "+f"((d)[1]), "+f"((d)[2]), "+f"((d)[3]) \
                 : "r"(a0), "r"(a1), "r"(a2), "r"(a3), "r"(b0), "r"(b1))

#define CP_ASYNC16(dst, src, sz) \
    asm volatile("cp.async.cg.shared.global [%0], [%1], 16, %2;" \
                 :: "r"(dst), "l"(src), "r"(sz))

__device__ __forceinline__ uint32_t pack_bf16(float x, float y) {
    __nv_bfloat162 t = __floats2bfloat162_rn(x, y);
    return *(uint32_t*)&t;
}
__device__ __forceinline__ void split2(float v, __nv_bfloat16& hi, __nv_bfloat16& lo) {
    hi = __float2bfloat16(v);
    lo = __float2bfloat16(v - __bfloat162float(hi));
}

// arithmetic reproduction of make_rel_pos_index
__device__ __forceinline__ int rel_index(int i, int j) {
    if (j == 0) return (i == 0) ? (NREL - 1) : (NREL - 2);
    if (i == 0) return NREL - 3;
    int yi = (i - 1) >> 5, xi = (i - 1) & 31;
    int yj = (j - 1) >> 5, xj = (j - 1) & 31;
    return (yi - yj + 31) * 63 + (xi - xj + 31);
}

// ========================= split-bf16 pack ([hi|lo]) ========================
__global__ void pack_kernel(const float* __restrict__ in, __nv_bfloat16* __restrict__ out,
                            int M, int K, int Kp, size_t irs, size_t ics,
                            size_t ibs0, size_t ibs1, int nh, size_t obs, float scale) {
    int idx = blockIdx.x * 256 + threadIdx.x;
    int z = blockIdx.y;
    if (idx >= M * Kp) return;
    int k = idx % Kp, m = idx / Kp;
    const float* src = in + (size_t)(z / nh) * ibs0 + (size_t)(z % nh) * ibs1;
    float v = (k < K) ? src[(size_t)m * irs + (size_t)k * ics] * scale : 0.f;
    __nv_bfloat16 hi, lo; split2(v, hi, lo);
    __nv_bfloat16* o = out + (size_t)z * obs + (size_t)m * (2 * (size_t)Kp);
    o[k] = hi; o[Kp + k] = lo;
}

// ---------------- fused LayerNorm + split-bf16 pack -------------------------
__global__ void ln_pack_kernel(const float* __restrict__ x, const float* __restrict__ w,
                               const float* __restrict__ b, __nv_bfloat16* __restrict__ out) {
    int r = blockIdx.x;
    const float* xr = x + (size_t)r * EMB;
    __shared__ float red[256];
    int tid = threadIdx.x;
    float s = 0.f;
    for (int i = tid; i < EMB; i += 256) s += xr[i];
    red[tid] = s; __syncthreads();
    for (int st = 128; st > 0; st >>= 1) { if (tid < st) red[tid] += red[tid + st]; __syncthreads(); }
    float mean = red[0] * (1.0f / EMB);
    __syncthreads();
    float s2 = 0.f;
    for (int i = tid; i < EMB; i += 256) { float d = xr[i] - mean; s2 += d * d; }
    red[tid] = s2; __syncthreads();
    for (int st = 128; st > 0; st >>= 1) { if (tid < st) red[tid] += red[tid + st]; __syncthreads(); }
    float inv = rsqrtf(red[0] * (1.0f / EMB) + 1e-6f);
    __nv_bfloat16* o = out + (size_t)r * (2 * EMB);
    for (int i = tid; i < EMB; i += 256) {
        float v = (xr[i] - mean) * inv * w[i] + b[i];
        __nv_bfloat16 hi, lo; split2(v, hi, lo);
        o[i] = hi; o[EMB + i] = lo;
    }
}

// ========================= HMMA GEMM (split-product reuse) ==================
template <int BM, int BN, int NSTAGE, int MINB>
__global__ void __launch_bounds__(256, MINB) hgemm2(
    const __nv_bfloat16* __restrict__ A, const __nv_bfloat16* __restrict__ B,
    float* __restrict__ C, __nv_bfloat16* __restrict__ Cp,
    const float* __restrict__ bias, const float* __restrict__ resid,
    int M, int Nreal, int Kp, size_t Abs, size_t Bbs,
    size_t ldc, size_t cs0, size_t cs1, int nh, int do_gelu) {
    constexpr int MT = BM / 32;
    constexpr int WTN = BN / 4;
    constexpr int NT8 = WTN / 8;
    constexpr int AIT = BM / 64;
    constexpr int NB4 = BN / 64;
    constexpr int AHALF = BM * 40;
    constexpr int BHALF = BN * 40;
    constexpr int STAGE = 2 * (AHALF + BHALF);
    extern __shared__ __nv_bfloat16 dsm[];

    int tid = threadIdx.x;
    int wid = tid >> 5, lane = tid & 31;
    int warp_m = wid >> 2, warp_n = wid & 3;
    int m0 = blockIdx.y * BM, n0 = blockIdx.x * BN;
    int z = blockIdx.z;

    const size_t lda = 2 * (size_t)Kp, ldb = 2 * (size_t)Kp;
    const __nv_bfloat16* Az = A + (size_t)z * Abs;
    const __nv_bfloat16* Bz = B + (size_t)z * Bbs;

    float acc[MT][NT8][4];
#pragma unroll
    for (int i = 0; i < MT; i++)
#pragma unroll
        for (int j = 0; j < NT8; j++)
#pragma unroll
            for (int e = 0; e < 4; e++) acc[i][j][e] = 0.f;

    int nk = Kp >> 5;

    auto load_body = [&](int c, int s) {
        __nv_bfloat16* st = dsm + s * STAGE;
#pragma unroll
        for (int sec = 0; sec < 2; sec++) {
#pragma unroll
            for (int i = 0; i < AIT; i++) {
                int idx = tid + i * 256, row = idx >> 2, cg = idx & 3;
                uint32_t dst = smem_u32(st + sec * AHALF + row * 40 + cg * 8);
                const __nv_bfloat16* src = Az + (size_t)(m0 + row) * lda +
                                           (size_t)sec * Kp + c * 32 + cg * 8;
                CP_ASYNC16(dst, src, (m0 + row < M) ? 16 : 0);
            }
        }
#pragma unroll
        for (int sec = 0; sec < 2; sec++) {
#pragma unroll
            for (int i = 0; i < NB4; i++) {
                int idx = tid + i * 256, row = idx >> 2, cg = idx & 3;
                uint32_t dst = smem_u32(st + 2 * AHALF + sec * BHALF + row * 40 + cg * 8);
                const __nv_bfloat16* src = Bz + (size_t)(n0 + row) * ldb +
                                           (size_t)sec * Kp + c * 32 + cg * 8;
                CP_ASYNC16(dst, src, (n0 + row < Nreal) ? 16 : 0);
            }
        }
    };

#pragma unroll
    for (int s = 0; s < NSTAGE - 1; s++) {
        if (s < nk) load_body(s, s);
        asm volatile("cp.async.commit_group;");
    }

    uint32_t aoff = (warp_m * (BM / 2) + (lane & 15)) * 40 + (lane >> 4) * 8;
    uint32_t boff = (warp_n * WTN + ((lane >> 4) << 3) + (lane & 7)) * 40 + ((lane >> 3) & 1) * 8;
    uint32_t dsm0 = smem_u32(dsm);

    for (int c = 0; c < nk; c++) {
        asm volatile("cp.async.wait_group %0;" :: "n"(NSTAGE - 2));
        __syncthreads();
        {
            int ncd = c + NSTAGE - 1;
            if (ncd < nk) load_body(ncd, ncd % NSTAGE);
            asm volatile("cp.async.commit_group;");
        }
        uint32_t sbase = dsm0 + (c % NSTAGE) * STAGE * 2;
#pragma unroll
        for (int kk = 0; kk < 2; kk++) {
            uint32_t ahi[MT][4], alo[MT][4];
#pragma unroll
            for (int mt = 0; mt < MT; mt++) {
                uint32_t ad = sbase + (aoff + mt * 16 * 40 + kk * 16) * 2;
                LDSM_X4(ahi[mt][0], ahi[mt][1], ahi[mt][2], ahi[mt][3], ad);
                LDSM_X4(alo[mt][0], alo[mt][1], alo[mt][2], alo[mt][3], ad + AHALF * 2);
            }
            uint32_t bhi[NT8][2], blo[NT8][2];
#pragma unroll
            for (int p = 0; p < NT8 / 2; p++) {
                uint32_t bd = sbase + 2 * AHALF * 2 + (boff + p * 16 * 40 + kk * 16) * 2;
                LDSM_X4(bhi[2 * p][0], bhi[2 * p][1], bhi[2 * p + 1][0], bhi[2 * p + 1][1], bd);
                LDSM_X4(blo[2 * p][0], blo[2 * p][1], blo[2 * p + 1][0], blo[2 * p + 1][1],
                        bd + BHALF * 2);
            }
#pragma unroll
            for (int mt = 0; mt < MT; mt++)
#pragma unroll
                for (int nt = 0; nt < NT8; nt++)
                    MMA16816(acc[mt][nt], ahi[mt][0], ahi[mt][1], ahi[mt][2], ahi[mt][3],
                             bhi[nt][0], bhi[nt][1]);
#pragma unroll
            for (int mt = 0; mt < MT; mt++)
#pragma unroll
                for (int nt = 0; nt < NT8; nt++)
                    MMA16816(acc[mt][nt], ahi[mt][0], ahi[mt][1], ahi[mt][2], ahi[mt][3],
                             blo[nt][0], blo[nt][1]);
#pragma unroll
            for (int mt = 0; mt < MT; mt++)
#pragma unroll
                for (int nt = 0; nt < NT8; nt++)
                    MMA16816(acc[mt][nt], alo[mt][0], alo[mt][1], alo[mt][2], alo[mt][3],
                             bhi[nt][0], bhi[nt][1]);
        }
    }

    size_t cbase = (size_t)(z / nh) * cs0 + (size_t)(z % nh) * cs1;
    int mrow = lane >> 2, ncol = (lane & 3) * 2;
#pragma unroll
    for (int mt = 0; mt < MT; mt++) {
#pragma unroll
        for (int half = 0; half < 2; half++) {
            int row = m0 + warp_m * (BM / 2) + mt * 16 + mrow + half * 8;
            if (row >= M) continue;
#pragma unroll
            for (int nt = 0; nt < NT8; nt++) {
                int col = n0 + warp_n * WTN + nt * 8 + ncol;
                float v0 = acc[mt][nt][half * 2];
                float v1 = acc[mt][nt][half * 2 + 1];
                if (bias) { v0 += bias[col]; v1 += bias[col + 1]; }
                if (resid) {
                    size_t off = cbase + (size_t)row * ldc + col;
                    v0 += resid[off]; v1 += resid[off + 1];
                }
                if (do_gelu) { v0 = gelu_exact(v0); v1 = gelu_exact(v1); }
                if (C) {
                    size_t off = cbase + (size_t)row * ldc + col;
                    if (col < Nreal) C[off] = v0;
                    if (col + 1 < Nreal) C[off + 1] = v1;
                }
                if (Cp) {
                    __nv_bfloat16 h0, l0b, h1, l1b;
                    split2(v0, h0, l0b); split2(v1, h1, l1b);
                    __nv_bfloat16* o = Cp + (size_t)row * (2 * (size_t)Nreal);
                    if (col + 1 < Nreal) {
                        *(uint32_t*)&o[col] = pack_bf16(__bfloat162float(h0), __bfloat162float(h1));
                        *(uint32_t*)&o[Nreal + col] = pack_bf16(__bfloat162float(l0b), __bfloat162float(l1b));
                    } else if (col < Nreal) {
                        o[col] = h0; o[Nreal + col] = l0b;
                    }
                }
            }
        }
    }
}

// ========================= fused flash attention ============================
// rel bias: index computed arithmetically; per-head relt column cached in smem.
#define FA_LD 136
__global__ void __launch_bounds__(256, 2) flash_attn_kernel(
    const float* __restrict__ qkv, const float* __restrict__ relt,
    __nv_bfloat16* __restrict__ opk) {
    extern __shared__ __nv_bfloat16 fsm[];
    __nv_bfloat16* sQ = fsm;
    __nv_bfloat16* sK = fsm + 128 * FA_LD;
    __nv_bfloat16* sV = sK + 64 * FA_LD;
    float* sRel = (float*)(sV + 64 * FA_LD);

    int tid = threadIdx.x, wid = tid >> 5, lane = tid & 31;
    int i0 = blockIdx.x * 128;
    int z = blockIdx.y;
    int b = z / HEADS, h = z % HEADS;
    const float* qb = qkv + (size_t)b * NT * 2304 + h * 64;
    const float* kb = qb + 768;
    const float* vb = qb + 1536;

    // cache per-head rel table column in smem
    for (int i = tid; i < NREL; i += 256) sRel[i] = relt[(size_t)i * HEADS + h];

    for (int idx = tid; idx < 128 * 64; idx += 256) {
        int r = idx >> 6, c = idx & 63;
        int gi = i0 + r;
        float v = (gi < NT) ? qb[(size_t)gi * 2304 + c] * 0.125f : 0.f;
        __nv_bfloat16 hi, lo; split2(v, hi, lo);
        sQ[r * FA_LD + c] = hi;
        sQ[r * FA_LD + 64 + c] = lo;
    }

    float m0 = -1e30f, m1 = -1e30f, l0 = 0.f, l1 = 0.f;
    float O[8][4];
#pragma unroll
    for (int t = 0; t < 8; t++)
#pragma unroll
        for (int e = 0; e < 4; e++) O[t][e] = 0.f;

    int r0g = i0 + wid * 16 + (lane >> 2);
    int r1g = r0g + 8;

    for (int j0 = 0; j0 < NT; j0 += 64) {
        __syncthreads();
        for (int idx = tid; idx < 64 * 64; idx += 256) {
            int r = idx >> 6, c = idx & 63;
            int gj = j0 + r;
            float kv = (gj < NT) ? kb[(size_t)gj * 2304 + c] : 0.f;
            __nv_bfloat16 khi, klo; split2(kv, khi, klo);
            sK[r * FA_LD + c] = khi;
            sK[r * FA_LD + 64 + c] = klo;
            float vv = (gj < NT) ? vb[(size_t)gj * 2304 + c] : 0.f;
            __nv_bfloat16 vhi, vlo; split2(vv, vhi, vlo);
            sV[c * FA_LD + r] = vhi;
            sV[c * FA_LD + 64 + r] = vlo;
        }
        __syncthreads();

        float S[8][4];
#pragma unroll
        for (int t = 0; t < 8; t++)
#pragma unroll
            for (int e = 0; e < 4; e++) S[t][e] = 0.f;

        const int qsec[3] = {0, 1, 0}, ksec[3] = {0, 0, 1};
#pragma unroll
        for (int sp = 0; sp < 3; sp++) {
#pragma unroll
            for (int kk = 0; kk < 4; kk++) {
                uint32_t a0, a1, a2, a3;
                uint32_t addr = smem_u32(&sQ[(wid * 16 + (lane & 15)) * FA_LD +
                                             qsec[sp] * 64 + kk * 16 + (lane >> 4) * 8]);
                LDSM_X4(a0, a1, a2, a3, addr);
                uint32_t bf[8][2];
#pragma unroll
                for (int p = 0; p < 4; p++) {
                    uint32_t ba = smem_u32(&sK[(p * 16 + ((lane >> 4) << 3) + (lane & 7)) * FA_LD +
                                               ksec[sp] * 64 + kk * 16 + ((lane >> 3) & 1) * 8]);
                    LDSM_X4(bf[2 * p][0], bf[2 * p][1], bf[2 * p + 1][0], bf[2 * p + 1][1], ba);
                }
#pragma unroll
                for (int nt = 0; nt < 8; nt++)
                    MMA16816(S[nt], a0, a1, a2, a3, bf[nt][0], bf[nt][1]);
            }
        }

        // rel bias (smem gather, arithmetic index) + mask
#pragma unroll
        for (int nt = 0; nt < 8; nt++) {
            int c0 = j0 + nt * 8 + (lane & 3) * 2;
#pragma unroll
            for (int e = 0; e < 2; e++) {
                int jj = c0 + e;
                if (jj < NT) {
                    if (r0g < NT) S[nt][e]     += sRel[rel_index(r0g, jj)];
                    if (r1g < NT) S[nt][2 + e] += sRel[rel_index(r1g, jj)];
                } else {
                    S[nt][e] = -1e30f;
                    S[nt][2 + e] = -1e30f;
                }
            }
        }

        float t0 = -1e30f, t1 = -1e30f;
#pragma unroll
        for (int nt = 0; nt < 8; nt++) {
            t0 = fmaxf(t0, fmaxf(S[nt][0], S[nt][1]));
            t1 = fmaxf(t1, fmaxf(S[nt][2], S[nt][3]));
        }
        t0 = fmaxf(t0, __shfl_xor_sync(0xffffffff, t0, 1));
        t0 = fmaxf(t0, __shfl_xor_sync(0xffffffff, t0, 2));
        t1 = fmaxf(t1, __shfl_xor_sync(0xffffffff, t1, 1));
        t1 = fmaxf(t1, __shfl_xor_sync(0xffffffff, t1, 2));
        float mn0 = fmaxf(m0, t0), mn1 = fmaxf(m1, t1);
        float al0 = __expf(m0 - mn0), al1 = __expf(m1 - mn1);
#pragma unroll
        for (int nt = 0; nt < 8; nt++) {
            O[nt][0] *= al0; O[nt][1] *= al0;
            O[nt][2] *= al1; O[nt][3] *= al1;
        }
        float ls0 = 0.f, ls1 = 0.f;
        uint32_t phi[4][4], plo[4][4];
#pragma unroll
        for (int kk = 0; kk < 4; kk++) {
#pragma unroll
            for (int tt = 0; tt < 2; tt++) {
                int t = 2 * kk + tt;
                float p0 = __expf(S[t][0] - mn0), p1 = __expf(S[t][1] - mn0);
                float p2 = __expf(S[t][2] - mn1), p3 = __expf(S[t][3] - mn1);
                ls0 += p0 + p1; ls1 += p2 + p3;
                float h0 = __bfloat162float(__float2bfloat16(p0));
                float h1 = __bfloat162float(__float2bfloat16(p1));
                float h2 = __bfloat162float(__float2bfloat16(p2));
                float h3 = __bfloat162float(__float2bfloat16(p3));
                phi[kk][tt * 2]     = pack_bf16(h0, h1);
                phi[kk][tt * 2 + 1] = pack_bf16(h2, h3);
                plo[kk][tt * 2]     = pack_bf16(p0 - h0, p1 - h1);
                plo[kk][tt * 2 + 1] = pack_bf16(p2 - h2, p3 - h3);
            }
        }
        ls0 += __shfl_xor_sync(0xffffffff, ls0, 1);
        ls0 += __shfl_xor_sync(0xffffffff, ls0, 2);
        ls1 += __shfl_xor_sync(0xffffffff, ls1, 1);
        ls1 += __shfl_xor_sync(0xffffffff, ls1, 2);
        l0 = l0 * al0 + ls0;
        l1 = l1 * al1 + ls1;
        m0 = mn0; m1 = mn1;

        const int vsec[3] = {0, 0, 1};
#pragma unroll
        for (int sp = 0; sp < 3; sp++) {
#pragma unroll
            for (int kk = 0; kk < 4; kk++) {
                uint32_t* A = (sp == 1) ? plo[kk] : phi[kk];
                uint32_t bf[8][2];
#pragma unroll
                for (int p = 0; p < 4; p++) {
                    uint32_t ba = smem_u32(&sV[(p * 16 + ((lane >> 4) << 3) + (lane & 7)) * FA_LD +
                                               vsec[sp] * 64 + kk * 16 + ((lane >> 3) & 1) * 8]);
                    LDSM_X4(bf[2 * p][0], bf[2 * p][1], bf[2 * p + 1][0], bf[2 * p + 1][1], ba);
                }
#pragma unroll
                for (int nt = 0; nt < 8; nt++)
                    MMA16816(O[nt], A[0], A[1], A[2], A[3], bf[nt][0], bf[nt][1]);
            }
        }
    }

    float il0 = 1.0f / l0, il1 = 1.0f / l1;
#pragma unroll
    for (int nt = 0; nt < 8; nt++) {
        int d = h * 64 + nt * 8 + (lane & 3) * 2;
        if (r0g < NT) {
            float v0 = O[nt][0] * il0, v1 = O[nt][1] * il0;
            __nv_bfloat16 h0, lo0, h1, lo1;
            split2(v0, h0, lo0); split2(v1, h1, lo1);
            __nv_bfloat16* o = opk + ((size_t)b * NT + r0g) * 1536;
            *(uint32_t*)&o[d] = pack_bf16(__bfloat162float(h0), __bfloat162float(h1));
            *(uint32_t*)&o[768 + d] = pack_bf16(__bfloat162float(lo0), __bfloat162float(lo1));
        }
        if (r1g < NT) {
            float v0 = O[nt][2] * il1, v1 = O[nt][3] * il1;
            __nv_bfloat16 h0, lo0, h1, lo1;
            split2(v0, h0, lo0); split2(v1, h1, lo1);
            __nv_bfloat16* o = opk + ((size_t)b * NT + r1g) * 1536;
            *(uint32_t*)&o[d] = pack_bf16(__bfloat162float(h0), __bfloat162float(h1));
            *(uint32_t*)&o[768 + d] = pack_bf16(__bfloat162float(lo0), __bfloat162float(lo1));
        }
    }
}

// ------------------------- elementwise helpers ------------------------------
__global__ void patchify_kernel(const float* __restrict__ x, float* __restrict__ A) {
    int idx = blockIdx.x * 256 + threadIdx.x;
    if (idx >= BATCH * 1024 * EMB) return;
    int col = idx % EMB;
    int m = idx / EMB;
    int b = m / 1024, g = m % 1024;
    int gh = g / 32, gw = g % 32;
    int c = col / 256, rem = col % 256;
    int i = rem / 16, j = rem % 16;
    A[idx] = x[(((size_t)(b * 3 + c) * 512) + gh * 16 + i) * 512 + gw * 16 + j];
}

__global__ void assemble_kernel(const float* __restrict__ tok, const float* __restrict__ cls,
                                const float* __restrict__ pos, float* __restrict__ t) {
    int idx = blockIdx.x * 256 + threadIdx.x;
    if (idx >= BATCH * NT * EMB) return;
    int d = idx % EMB;
    int n = (idx / EMB) % NT;
    int b = idx / (EMB * NT);
    float v = (n == 0) ? cls[d] : tok[((size_t)b * 1024 + (n - 1)) * EMB + d];
    t[idx] = v + pos[n * EMB + d];
}

__global__ void biaspack_all_kernel(const float* __restrict__ qb, const float* __restrict__ vb,
                                    float* __restrict__ out) {
    int i = blockIdx.x * 256 + threadIdx.x;
    if (i >= 12 * 3 * EMB) return;
    int l = i / (3 * EMB), r = i % (3 * EMB);
    out[i] = (r < EMB) ? qb[l * EMB + r]
           : ((r < 2 * EMB) ? 0.f : vb[l * EMB + r - 2 * EMB]);
}

__global__ void copy_kernel(const float* __restrict__ src, float* __restrict__ dst, int n) {
    int i = blockIdx.x * 256 + threadIdx.x;
    if (i < n) dst[i] = src[i];
}

__global__ void repack_w_kernel(const float* __restrict__ w, float* __restrict__ wp) {
    int idx = blockIdx.x * 256 + threadIdx.x;
    if (idx >= 3072 * 768) return;
    int c = idx % 768, n = idx / 768;
    int ij = n / 768, d = n % 768;
    wp[idx] = w[(size_t)c * 3072 + d * 4 + ij];
}

__global__ void scatter_bhwc_kernel(const float* __restrict__ tmp, const float* __restrict__ bias,
                                    float* __restrict__ y, int HW) {
    int total = BATCH * HW * HW * 4 * 768;
    int idx = blockIdx.x * 256 + threadIdx.x;
    if (idx >= total) return;
    int d = idx % 768;
    int ij = (idx / 768) % 4;
    int p = (idx / 3072) % (HW * HW);
    int b = idx / (3072 * HW * HW);
    int h = p / HW, w = p % HW, i = ij / 2, j = ij % 2;
    int W2 = 2 * HW;
    y[(((size_t)b * W2 + 2 * h + i) * W2 + (2 * w + j)) * 768 + d] = tmp[idx] + bias[d];
}

__global__ void scatter_bchw_kernel(const float* __restrict__ tmp, const float* __restrict__ bias,
                                    float* __restrict__ out, int HW) {
    int total = BATCH * HW * HW * 4 * 768;
    int idx = blockIdx.x * 256 + threadIdx.x;
    if (idx >= total) return;
    int d = idx % 768;
    int ij = (idx / 768) % 4;
    int p = (idx / 3072) % (HW * HW);
    int b = idx / (3072 * HW * HW);
    int h = p / HW, w = p % HW, i = ij / 2, j = ij % 2;
    int W2 = 2 * HW;
    out[(((size_t)b * 768 + d) * W2 + 2 * h + i) * W2 + (2 * w + j)] = tmp[idx] + bias[d];
}

__global__ void bn_gelu_kernel(float* __restrict__ y, const float* __restrict__ w,
                               const float* __restrict__ b, const float* __restrict__ mean,
                               const float* __restrict__ var) {
    int idx = blockIdx.x * 256 + threadIdx.x;
    if (idx >= BATCH * 64 * 64 * 768) return;
    int c = idx % 768;
    float v = y[idx];
    v = (v - mean[c]) * rsqrtf(var[c] + 1e-5f) * w[c] + b[c];
    y[idx] = gelu_exact(v);
}

__global__ void to_map_kernel(const float* __restrict__ feat, float* __restrict__ out) {
    int idx = blockIdx.x * 256 + threadIdx.x;
    if (idx >= BATCH * 768 * 32 * 32) return;
    int xw = idx % 32;
    int yh = (idx / 32) % 32;
    int c = (idx / 1024) % 768;
    int b = idx / (1024 * 768);
    out[idx] = feat[((size_t)b * NT + 1 + yh * 32 + xw) * EMB + c];
}

__global__ void maxpool_kernel(const float* __restrict__ feat, float* __restrict__ out) {
    int idx = blockIdx.x * 256 + threadIdx.x;
    if (idx >= BATCH * 768 * 16 * 16) return;
    int xw = idx % 16;
    int yh = (idx / 16) % 16;
    int c = (idx / 256) % 768;
    int b = idx / (256 * 768);
    float m = -1e30f;
#pragma unroll
    for (int i = 0; i < 2; i++)
#pragma unroll
        for (int j = 0; j < 2; j++) {
            int Y = 2 * yh + i, X = 2 * xw + j;
            m = fmaxf(m, feat[((size_t)b * NT + 1 + Y * 32 + X) * EMB + c]);
        }
    out[idx] = m;
}

// ------------------------- host helpers -------------------------------------
static void pack(const float* in, __nv_bfloat16* out, int M, int K, int Kp,
                 size_t irs, size_t ics, size_t ibs0, size_t ibs1, int nh,
                 size_t obs, float scale, int nz) {
    dim3 g((M * Kp + 255) / 256, nz);
    pack_kernel<<<g, 256>>>(in, out, M, K, Kp, irs, ics, ibs0, ibs1, nh, obs, scale);
}
#define SMEM_BIG   (2 * 2 * (128 + 128) * 40 * 2)   // 81920, BM128/BN128 2-stage
#define SMEM_SMALL (3 * 2 * (64 + 64) * 40 * 2)     // 61440, BM64/BN64 3-stage
static void gemm_tc(const __nv_bfloat16* A, const __nv_bfloat16* B, float* C,
                    __nv_bfloat16* Cp, const float* bias, const float* resid,
                    int M, int N, int Kp, size_t Abs, size_t Bbs, size_t ldc,
                    size_t cs0, size_t cs1, int nh, int gelu, int nz) {
    int gm128 = (M + 127) / 128;
    if (N % 128 == 0 && (N / 128) * gm128 * nz >= 148) {
        dim3 g(N / 128, gm128, nz);
        hgemm2<128, 128, 2, 2><<<g, 256, SMEM_BIG>>>(A, B, C, Cp, bias, resid, M, N, Kp,
                                                     Abs, Bbs, ldc, cs0, cs1, nh, gelu);
    } else {
        dim3 g(N / 64, (M + 63) / 64, nz);
        hgemm2<64, 64, 3, 3><<<g, 256, SMEM_SMALL>>>(A, B, C, Cp, bias, resid, M, N, Kp,
                                                     Abs, Bbs, ldc, cs0, cs1, nh, gelu);
    }
}

extern "C" void kernel_launch(void* const* d_in, const int* in_sizes, int n_in,
                              void* d_out, int out_size) {
    const float* x         = (const float*)d_in[0];
    const float* patch_w   = (const float*)d_in[1];
    const float* patch_b   = (const float*)d_in[2];
    const float* cls_token = (const float*)d_in[3];
    const float* pos_embed = (const float*)d_in[4];
    const float* ln1_w     = (const float*)d_in[5];
    const float* ln1_b     = (const float*)d_in[6];
    const float* qkv_w     = (const float*)d_in[7];
    const float* q_bias    = (const float*)d_in[8];
    const float* v_bias    = (const float*)d_in[9];
    const float* rel_tab   = (const float*)d_in[10];
    const float* proj_w    = (const float*)d_in[11];
    const float* proj_b    = (const float*)d_in[12];
    const float* ln2_w     = (const float*)d_in[13];
    const float* ln2_b     = (const float*)d_in[14];
    const float* fc1_w     = (const float*)d_in[15];
    const float* fc1_b     = (const float*)d_in[16];
    const float* fc2_w     = (const float*)d_in[17];
    const float* fc2_b     = (const float*)d_in[18];
    const float* d1_w      = (const float*)d_in[19];
    const float* d1_b      = (const float*)d_in[20];
    const float* bn_w      = (const float*)d_in[21];
    const float* bn_b      = (const float*)d_in[22];
    const float* bn_mean   = (const float*)d_in[23];
    const float* bn_var    = (const float*)d_in[24];
    const float* d2_w      = (const float*)d_in[25];
    const float* d2_b      = (const float*)d_in[26];
    const float* f2w       = (const float*)d_in[27];
    const float* f2b       = (const float*)d_in[28];

    float* out = (float*)d_out;
    float* out1 = out;
    float* out2 = out1 + (size_t)BATCH * 768 * 128 * 128;
    float* out3 = out2 + (size_t)BATCH * 768 * 64 * 64;
    float* out4 = out3 + (size_t)BATCH * 768 * 32 * 32;

    static float *pt = nullptr, *pqkv, *ppatch, *ptok;
    static float *pf0, *pf1, *pf2, *pf3, *py, *ptmp, *pwp, *pqb;
    static __nv_bfloat16 *pa, *pb, *pc, *pw;
    if (!pt) {
        cudaGetSymbolAddress((void**)&pt, g_t);
        cudaGetSymbolAddress((void**)&pqkv, g_qkv);
        cudaGetSymbolAddress((void**)&ppatch, g_patch);
        cudaGetSymbolAddress((void**)&ptok, g_tok);
        cudaGetSymbolAddress((void**)&pf0, g_feat0);
        cudaGetSymbolAddress((void**)&pf1, g_feat1);
        cudaGetSymbolAddress((void**)&pf2, g_feat2);
        cudaGetSymbolAddress((void**)&pf3, g_feat3);
        cudaGetSymbolAddress((void**)&py, g_y);
        cudaGetSymbolAddress((void**)&ptmp, g_tmp);
        cudaGetSymbolAddress((void**)&pwp, g_wpack);
        cudaGetSymbolAddress((void**)&pqb, g_qkvbias);
        cudaGetSymbolAddress((void**)&pa, g_pa);
        cudaGetSymbolAddress((void**)&pb, g_pb);
        cudaGetSymbolAddress((void**)&pc, g_pc);
        cudaGetSymbolAddress((void**)&pw, g_pw);
        cudaFuncSetAttribute(flash_attn_kernel,
                             cudaFuncAttributeMaxDynamicSharedMemorySize,
                             (128 + 64 + 64) * FA_LD * 2 + NREL * 4);
        cudaFuncSetAttribute((const void*)hgemm2<128, 128, 2, 2>,
                             cudaFuncAttributeMaxDynamicSharedMemorySize, SMEM_BIG);
        cudaFuncSetAttribute((const void*)hgemm2<64, 64, 3, 3>,
                             cudaFuncAttributeMaxDynamicSharedMemorySize, SMEM_SMALL);
    }

    const int TOKELEMS = BATCH * NT * EMB;
    const int M = BATCH * NT;  // 2050
    const int FA_SMEM = (128 + 64 + 64) * FA_LD * 2 + NREL * 4;

    // ---- pre-pack ALL transformer weights (4 batched launches) ----
    pack(qkv_w, pw + W_QKV, 2304, 768, 768, 768, 1, (size_t)2304 * 768, 0, 1,
         W_PER, 1.0f, 12);
    pack(proj_w, pw + W_PROJ, 768, 768, 768, 768, 1, (size_t)768 * 768, 0, 1,
         W_PER, 1.0f, 12);
    pack(fc1_w, pw + W_FC1, 3072, 768, 768, 768, 1, (size_t)3072 * 768, 0, 1,
         W_PER, 1.0f, 12);
    pack(fc2_w, pw + W_FC2, 768, 3072, 3072, 3072, 1, (size_t)768 * 3072, 0, 1,
         W_PER, 1.0f, 12);
    biaspack_all_kernel<<<(12 * 3 * EMB + 255) / 256, 256>>>(q_bias, v_bias, pqb);

    // ---- patch embed ----
    patchify_kernel<<<(BATCH * 1024 * EMB + 255) / 256, 256>>>(x, ppatch);
    pack(ppatch, pa, 2048, 768, 768, 768, 1, 0, 0, 1, 0, 1.0f, 1);
    pack(patch_w, pb, 768, 768, 768, 768, 1, 0, 0, 1, 0, 1.0f, 1);
    gemm_tc(pa, pb, ptok, nullptr, patch_b, nullptr, 2048, 768, 768, 0, 0,
            768, 0, 0, 1, 0, 1);
    assemble_kernel<<<(TOKELEMS + 255) / 256, 256>>>(ptok, cls_token, pos_embed, pt);

    // ---- transformer layers ----
    for (int l = 0; l < 12; l++) {
        const __nv_bfloat16* wl = pw + (size_t)l * W_PER;
        ln_pack_kernel<<<M, 256>>>(pt, ln1_w + l * EMB, ln1_b + l * EMB, pa);
        gemm_tc(pa, wl + W_QKV, pqkv, nullptr, pqb + l * 2304, nullptr, M, 2304, 768, 0, 0,
                2304, 0, 0, 1, 0, 1);
        {
            dim3 g((NT + 127) / 128, BATCH * HEADS);
            flash_attn_kernel<<<g, 256, FA_SMEM>>>(pqkv, rel_tab + (size_t)l * NREL * HEADS, pa);
        }
        gemm_tc(pa, wl + W_PROJ, pt, nullptr, proj_b + l * EMB, pt, M, 768, 768, 0, 0,
                768, 0, 0, 1, 0, 1);
        ln_pack_kernel<<<M, 256>>>(pt, ln2_w + l * EMB, ln2_b + l * EMB, pa);
        gemm_tc(pa, wl + W_FC1, nullptr, pc, fc1_b + l * 4 * EMB, nullptr, M, 3072, 768, 0, 0,
                3072, 0, 0, 1, 1, 1);
        gemm_tc(pc, wl + W_FC2, pt, nullptr, fc2_b + l * EMB, pt, M, 768, 3072, 0, 0,
                768, 0, 0, 1, 0, 1);
        float* fdst = nullptr;
        if (l == 3) fdst = pf0;
        else if (l == 5) fdst = pf1;
        else if (l == 7) fdst = pf2;
        else if (l == 11) fdst = pf3;
        if (fdst) copy_kernel<<<(TOKELEMS + 255) / 256, 256>>>(pt, fdst, TOKELEMS);
    }

    // ---- o3 / o4 ----
    to_map_kernel<<<(BATCH * 768 * 1024 + 255) / 256, 256>>>(pf2, out3);
    maxpool_kernel<<<(BATCH * 768 * 256 + 255) / 256, 256>>>(pf3, out4);

    // ---- fpn1 stage 1 ----
    repack_w_kernel<<<(3072 * 768 + 255) / 256, 256>>>(d1_w, pwp);
    pack(pwp, pb, 3072, 768, 768, 768, 1, 0, 0, 1, 0, 1.0f, 1);
    pack(pf0 + 768, pa, 1024, 768, 768, 768, 1, (size_t)NT * 768, 0, 1,
         (size_t)1024 * 1536, 1.0f, BATCH);
    gemm_tc(pa, pb, ptmp, nullptr, nullptr, nullptr, 1024, 3072, 768,
            (size_t)1024 * 1536, 0, 3072, (size_t)1024 * 3072, 0, 1, 0, BATCH);
    scatter_bhwc_kernel<<<(BATCH * 1024 * 3072 + 255) / 256, 256>>>(ptmp, d1_b, py, 32);
    bn_gelu_kernel<<<(BATCH * 64 * 64 * 768 + 255) / 256, 256>>>(py, bn_w, bn_b, bn_mean, bn_var);

    // ---- fpn1 stage 2 ----
    repack_w_kernel<<<(3072 * 768 + 255) / 256, 256>>>(d2_w, pwp);
    pack(pwp, pb, 3072, 768, 768, 768, 1, 0, 0, 1, 0, 1.0f, 1);
    pack(py, pa, 4096, 768, 768, 768, 1, (size_t)4096 * 768, 0, 1,
         (size_t)4096 * 1536, 1.0f, BATCH);
    gemm_tc(pa, pb, ptmp, nullptr, nullptr, nullptr, 4096, 3072, 768,
            (size_t)4096 * 1536, 0, 3072, (size_t)4096 * 3072, 0, 1, 0, BATCH);
    scatter_bchw_kernel<<<(BATCH * 4096 * 3072 + 255) / 256, 256>>>(ptmp, d2_b, out1, 64);

    // ---- o2 ----
    repack_w_kernel<<<(3072 * 768 + 255) / 256, 256>>>(f2w, pwp);
    pack(pwp, pb, 3072, 768, 768, 768, 1, 0, 0, 1, 0, 1.0f, 1);
    pack(pf1 + 768, pa, 1024, 768, 768, 768, 1, (size_t)NT * 768, 0, 1,
         (size_t)1024 * 1536, 1.0f, BATCH);
    gemm_tc(pa, pb, ptmp, nullptr, nullptr, nullptr, 1024, 3072, 768,
            (size_t)1024 * 1536, 0, 3072, (size_t)1024 * 3072, 0, 1, 0, BATCH);
    scatter_bchw_kernel<<<(BATCH * 1024 * 3072 + 255) / 256, 256>>>(ptmp, f2b, out2, 32);

    (void)in_sizes; (void)n_in; (void)out_size;
}

// round 13
// speedup vs baseline: 1.2403x; 1.0283x over previous
#include <cuda_runtime.h>
#include <cuda_bf16.h>
#include <math.h>
#include <stdint.h>

#define NT    1025
#define EMB   768
#define BATCH 2
#define HEADS 12
#define NREL  3972

// ------------------------- device scratch (no allocs allowed) ---------------
__device__ float g_t[BATCH * NT * EMB];
__device__ float g_qkv[BATCH * NT * 3 * EMB];
__device__ float g_patch[BATCH * 1024 * EMB];
__device__ float g_tok[BATCH * 1024 * EMB];
__device__ float g_feat0[BATCH * NT * EMB];
__device__ float g_feat1[BATCH * NT * EMB];
__device__ float g_feat2[BATCH * NT * EMB];
__device__ float g_feat3[BATCH * NT * EMB];
__device__ float g_y[BATCH * 64 * 64 * EMB];
__device__ float g_tmp[(size_t)BATCH * 4096 * 3072];
__device__ float g_wpack[3072 * 768];
__device__ float g_qkvbias[12 * 3 * EMB];
__device__ __nv_bfloat16 g_pa[14000000];
__device__ __nv_bfloat16 g_pb[5000000];
__device__ __nv_bfloat16 g_pc[12700000];
#define W_QKV  0
#define W_PROJ 3538944
#define W_FC1  4718592
#define W_FC2  9437184
#define W_PER  14155776
__device__ __nv_bfloat16 g_pw[12 * 14155776];

__device__ __forceinline__ float gelu_exact(float x) {
    return 0.5f * x * (1.0f + erff(x * 0.70710678118654752f));
}

__device__ __forceinline__ uint32_t smem_u32(const void* p) {
    uint32_t a;
    asm("{ .reg .u64 t; cvta.to.shared.u64 t, %1; cvt.u32.u64 %0, t; }" : "=r"(a) : "l"(p));
    return a;
}

#define LDSM_X4(r0, r1, r2, r3, addr) \
    asm volatile("ldmatrix.sync.aligned.m8n8.x4.shared.b16 {%0,%1,%2,%3}, [%4];" \
                 : "=r"(r0), "=r"(r1), "=r"(r2), "=r"(r3) : "r"(addr))

#define MMA16816(d, a0, a1, a2, a3, b0, b1) \
    asm volatile("mma.sync.aligned.m16n8k16.row.col.f32.bf16.bf16.f32 " \
                 "{%0,%1,%2,%3}, {%4,%5,%6,%7}, {%8,%9}, {%0,%1,%2,%3};" \
                 : "+f"((d)[0]), "+f"((d)[1]), "+f"((d)[2]), "+f"((d)[3]) \
                 : "r"(a0), "r"(a1), "r"(a2), "r"(a3), "r"(b0), "r"(b1))

#define CP_ASYNC16(dst, src, sz) \
    asm volatile("cp.async.cg.shared.global [%0], [%1], 16, %2;" \
                 :: "r"(dst), "l"(src), "r"(sz))

__device__ __forceinline__ uint32_t pack_bf16(float x, float y) {
    __nv_bfloat162 t = __floats2bfloat162_rn(x, y);
    return *(uint32_t*)&t;
}
__device__ __forceinline__ void split2(float v, __nv_bfloat16& hi, __nv_bfloat16& lo) {
    hi = __float2bfloat16(v);
    lo = __float2bfloat16(v - __bfloat162float(hi));
}
__device__ __forceinline__ float b2f(__nv_bfloat16 v) { return __bfloat162float(v); }

// arithmetic reproduction of make_rel_pos_index
__device__ __forceinline__ int rel_index(int i, int j) {
    if (j == 0) return (i == 0) ? (NREL - 1) : (NREL - 2);
    if (i == 0) return NREL - 3;
    int yi = (i - 1) >> 5, xi = (i - 1) & 31;
    int yj = (j - 1) >> 5, xj = (j - 1) & 31;
    return (yi - yj + 31) * 63 + (xi - xj + 31);
}

// ============ vectorized split-bf16 pack ([hi|lo], contiguous rows) =========
// grid: (M, nz).  K % 4 == 0.  in row = in + z*ibs + row*irs (irs in floats).
__global__ void fast_pack_kernel(const float* __restrict__ in, __nv_bfloat16* __restrict__ out,
                                 int K, size_t irs, size_t ibs, size_t obs, float scale) {
    int row = blockIdx.x, z = blockIdx.y;
    const float4* src = (const float4*)(in + (size_t)z * ibs + (size_t)row * irs);
    __nv_bfloat16* o = out + (size_t)z * obs + (size_t)row * (2 * (size_t)K);
    for (int k4 = threadIdx.x; k4 < (K >> 2); k4 += 256) {
        float4 v = src[k4];
        v.x *= scale; v.y *= scale; v.z *= scale; v.w *= scale;
        __nv_bfloat16 h0, l0, h1, l1, h2, l2, h3, l3;
        split2(v.x, h0, l0); split2(v.y, h1, l1);
        split2(v.z, h2, l2); split2(v.w, h3, l3);
        uint2 hv = make_uint2(pack_bf16(b2f(h0), b2f(h1)), pack_bf16(b2f(h2), b2f(h3)));
        uint2 lv = make_uint2(pack_bf16(b2f(l0), b2f(l1)), pack_bf16(b2f(l2), b2f(l3)));
        *(uint2*)&o[k4 * 4] = hv;
        *(uint2*)&o[K + k4 * 4] = lv;
    }
}

// ---------------- fused LayerNorm + split-bf16 pack -------------------------
__global__ void ln_pack_kernel(const float* __restrict__ x, const float* __restrict__ w,
                               const float* __restrict__ b, __nv_bfloat16* __restrict__ out) {
    int r = blockIdx.x;
    const float* xr = x + (size_t)r * EMB;
    __shared__ float red[256];
    int tid = threadIdx.x;
    float s = 0.f;
    for (int i = tid; i < EMB; i += 256) s += xr[i];
    red[tid] = s; __syncthreads();
    for (int st = 128; st > 0; st >>= 1) { if (tid < st) red[tid] += red[tid + st]; __syncthreads(); }
    float mean = red[0] * (1.0f / EMB);
    __syncthreads();
    float s2 = 0.f;
    for (int i = tid; i < EMB; i += 256) { float d = xr[i] - mean; s2 += d * d; }
    red[tid] = s2; __syncthreads();
    for (int st = 128; st > 0; st >>= 1) { if (tid < st) red[tid] += red[tid + st]; __syncthreads(); }
    float inv = rsqrtf(red[0] * (1.0f / EMB) + 1e-6f);
    __nv_bfloat16* o = out + (size_t)r * (2 * EMB);
    for (int i = tid; i < EMB; i += 256) {
        float v = (xr[i] - mean) * inv * w[i] + b[i];
        __nv_bfloat16 hi, lo; split2(v, hi, lo);
        o[i] = hi; o[EMB + i] = lo;
    }
}

// ========================= HMMA GEMM (split-product reuse) ==================
template <int BM, int BN, int NSTAGE, int MINB>
__global__ void __launch_bounds__(256, MINB) hgemm2(
    const __nv_bfloat16* __restrict__ A, const __nv_bfloat16* __restrict__ B,
    float* __restrict__ C, __nv_bfloat16* __restrict__ Cp,
    const float* __restrict__ bias, const float* __restrict__ resid,
    int M, int Nreal, int Kp, size_t Abs, size_t Bbs,
    size_t ldc, size_t cs0, size_t cs1, int nh, int do_gelu) {
    constexpr int MT = BM / 32;
    constexpr int WTN = BN / 4;
    constexpr int NT8 = WTN / 8;
    constexpr int AIT = BM / 64;
    constexpr int NB4 = BN / 64;
    constexpr int AHALF = BM * 40;
    constexpr int BHALF = BN * 40;
    constexpr int STAGE = 2 * (AHALF + BHALF);
    extern __shared__ __nv_bfloat16 dsm[];

    int tid = threadIdx.x;
    int wid = tid >> 5, lane = tid & 31;
    int warp_m = wid >> 2, warp_n = wid & 3;
    int m0 = blockIdx.y * BM, n0 = blockIdx.x * BN;
    int z = blockIdx.z;

    const size_t lda = 2 * (size_t)Kp, ldb = 2 * (size_t)Kp;
    const __nv_bfloat16* Az = A + (size_t)z * Abs;
    const __nv_bfloat16* Bz = B + (size_t)z * Bbs;

    float acc[MT][NT8][4];
#pragma unroll
    for (int i = 0; i < MT; i++)
#pragma unroll
        for (int j = 0; j < NT8; j++)
#pragma unroll
            for (int e = 0; e < 4; e++) acc[i][j][e] = 0.f;

    int nk = Kp >> 5;

    auto load_body = [&](int c, int s) {
        __nv_bfloat16* st = dsm + s * STAGE;
#pragma unroll
        for (int sec = 0; sec < 2; sec++) {
#pragma unroll
            for (int i = 0; i < AIT; i++) {
                int idx = tid + i * 256, row = idx >> 2, cg = idx & 3;
                uint32_t dst = smem_u32(st + sec * AHALF + row * 40 + cg * 8);
                const __nv_bfloat16* src = Az + (size_t)(m0 + row) * lda +
                                           (size_t)sec * Kp + c * 32 + cg * 8;
                CP_ASYNC16(dst, src, (m0 + row < M) ? 16 : 0);
            }
        }
#pragma unroll
        for (int sec = 0; sec < 2; sec++) {
#pragma unroll
            for (int i = 0; i < NB4; i++) {
                int idx = tid + i * 256, row = idx >> 2, cg = idx & 3;
                uint32_t dst = smem_u32(st + 2 * AHALF + sec * BHALF + row * 40 + cg * 8);
                const __nv_bfloat16* src = Bz + (size_t)(n0 + row) * ldb +
                                           (size_t)sec * Kp + c * 32 + cg * 8;
                CP_ASYNC16(dst, src, (n0 + row < Nreal) ? 16 : 0);
            }
        }
    };

#pragma unroll
    for (int s = 0; s < NSTAGE - 1; s++) {
        if (s < nk) load_body(s, s);
        asm volatile("cp.async.commit_group;");
    }

    uint32_t aoff = (warp_m * (BM / 2) + (lane & 15)) * 40 + (lane >> 4) * 8;
    uint32_t boff = (warp_n * WTN + ((lane >> 4) << 3) + (lane & 7)) * 40 + ((lane >> 3) & 1) * 8;
    uint32_t dsm0 = smem_u32(dsm);

    for (int c = 0; c < nk; c++) {
        asm volatile("cp.async.wait_group %0;" :: "n"(NSTAGE - 2));
        __syncthreads();
        {
            int ncd = c + NSTAGE - 1;
            if (ncd < nk) load_body(ncd, ncd % NSTAGE);
            asm volatile("cp.async.commit_group;");
        }
        uint32_t sbase = dsm0 + (c % NSTAGE) * STAGE * 2;
#pragma unroll
        for (int kk = 0; kk < 2; kk++) {
            uint32_t ahi[MT][4], alo[MT][4];
#pragma unroll
            for (int mt = 0; mt < MT; mt++) {
                uint32_t ad = sbase + (aoff + mt * 16 * 40 + kk * 16) * 2;
                LDSM_X4(ahi[mt][0], ahi[mt][1], ahi[mt][2], ahi[mt][3], ad);
                LDSM_X4(alo[mt][0], alo[mt][1], alo[mt][2], alo[mt][3], ad + AHALF * 2);
            }
            uint32_t bhi[NT8][2], blo[NT8][2];
#pragma unroll
            for (int p = 0; p < NT8 / 2; p++) {
                uint32_t bd = sbase + 2 * AHALF * 2 + (boff + p * 16 * 40 + kk * 16) * 2;
                LDSM_X4(bhi[2 * p][0], bhi[2 * p][1], bhi[2 * p + 1][0], bhi[2 * p + 1][1], bd);
                LDSM_X4(blo[2 * p][0], blo[2 * p][1], blo[2 * p + 1][0], blo[2 * p + 1][1],
                        bd + BHALF * 2);
            }
#pragma unroll
            for (int mt = 0; mt < MT; mt++)
#pragma unroll
                for (int nt = 0; nt < NT8; nt++)
                    MMA16816(acc[mt][nt], ahi[mt][0], ahi[mt][1], ahi[mt][2], ahi[mt][3],
                             bhi[nt][0], bhi[nt][1]);
#pragma unroll
            for (int mt = 0; mt < MT; mt++)
#pragma unroll
                for (int nt = 0; nt < NT8; nt++)
                    MMA16816(acc[mt][nt], ahi[mt][0], ahi[mt][1], ahi[mt][2], ahi[mt][3],
                             blo[nt][0], blo[nt][1]);
#pragma unroll
            for (int mt = 0; mt < MT; mt++)
#pragma unroll
                for (int nt = 0; nt < NT8; nt++)
                    MMA16816(acc[mt][nt], alo[mt][0], alo[mt][1], alo[mt][2], alo[mt][3],
                             bhi[nt][0], bhi[nt][1]);
        }
    }

    size_t cbase = (size_t)(z / nh) * cs0 + (size_t)(z % nh) * cs1;
    int mrow = lane >> 2, ncol = (lane & 3) * 2;
#pragma unroll
    for (int mt = 0; mt < MT; mt++) {
#pragma unroll
        for (int half = 0; half < 2; half++) {
            int row = m0 + warp_m * (BM / 2) + mt * 16 + mrow + half * 8;
            if (row >= M) continue;
#pragma unroll
            for (int nt = 0; nt < NT8; nt++) {
                int col = n0 + warp_n * WTN + nt * 8 + ncol;
                float v0 = acc[mt][nt][half * 2];
                float v1 = acc[mt][nt][half * 2 + 1];
                if (bias) { v0 += bias[col]; v1 += bias[col + 1]; }
                if (resid) {
                    size_t off = cbase + (size_t)row * ldc + col;
                    v0 += resid[off]; v1 += resid[off + 1];
                }
                if (do_gelu) { v0 = gelu_exact(v0); v1 = gelu_exact(v1); }
                if (C) {
                    size_t off = cbase + (size_t)row * ldc + col;
                    if (col < Nreal) C[off] = v0;
                    if (col + 1 < Nreal) C[off + 1] = v1;
                }
                if (Cp) {
                    __nv_bfloat16 h0, l0b, h1, l1b;
                    split2(v0, h0, l0b); split2(v1, h1, l1b);
                    __nv_bfloat16* o = Cp + (size_t)row * (2 * (size_t)Nreal);
                    if (col + 1 < Nreal) {
                        *(uint32_t*)&o[col] = pack_bf16(b2f(h0), b2f(h1));
                        *(uint32_t*)&o[Nreal + col] = pack_bf16(b2f(l0b), b2f(l1b));
                    } else if (col < Nreal) {
                        o[col] = h0; o[Nreal + col] = l0b;
                    }
                }
            }
        }
    }
}

// ========================= fused flash attention ============================
#define FA_LD 136
__global__ void __launch_bounds__(256, 2) flash_attn_kernel(
    const float* __restrict__ qkv, const float* __restrict__ relt,
    __nv_bfloat16* __restrict__ opk) {
    extern __shared__ __nv_bfloat16 fsm[];
    __nv_bfloat16* sQ = fsm;
    __nv_bfloat16* sK = fsm + 128 * FA_LD;
    __nv_bfloat16* sV = sK + 64 * FA_LD;
    float* sRel = (float*)(sV + 64 * FA_LD);

    int tid = threadIdx.x, wid = tid >> 5, lane = tid & 31;
    int i0 = blockIdx.x * 128;
    int z = blockIdx.y;
    int b = z / HEADS, h = z % HEADS;
    const float* qb = qkv + (size_t)b * NT * 2304 + h * 64;
    const float* kb = qb + 768;
    const float* vb = qb + 1536;

    for (int i = tid; i < NREL; i += 256) sRel[i] = relt[(size_t)i * HEADS + h];

    for (int idx = tid; idx < 128 * 64; idx += 256) {
        int r = idx >> 6, c = idx & 63;
        int gi = i0 + r;
        float v = (gi < NT) ? qb[(size_t)gi * 2304 + c] * 0.125f : 0.f;
        __nv_bfloat16 hi, lo; split2(v, hi, lo);
        sQ[r * FA_LD + c] = hi;
        sQ[r * FA_LD + 64 + c] = lo;
    }

    float m0 = -1e30f, m1 = -1e30f, l0 = 0.f, l1 = 0.f;
    float O[8][4];
#pragma unroll
    for (int t = 0; t < 8; t++)
#pragma unroll
        for (int e = 0; e < 4; e++) O[t][e] = 0.f;

    int r0g = i0 + wid * 16 + (lane >> 2);
    int r1g = r0g + 8;

    for (int j0 = 0; j0 < NT; j0 += 64) {
        __syncthreads();
        for (int idx = tid; idx < 64 * 64; idx += 256) {
            int r = idx >> 6, c = idx & 63;
            int gj = j0 + r;
            float kv = (gj < NT) ? kb[(size_t)gj * 2304 + c] : 0.f;
            __nv_bfloat16 khi, klo; split2(kv, khi, klo);
            sK[r * FA_LD + c] = khi;
            sK[r * FA_LD + 64 + c] = klo;
            float vv = (gj < NT) ? vb[(size_t)gj * 2304 + c] : 0.f;
            __nv_bfloat16 vhi, vlo; split2(vv, vhi, vlo);
            sV[c * FA_LD + r] = vhi;
            sV[c * FA_LD + 64 + r] = vlo;
        }
        __syncthreads();

        float S[8][4];
#pragma unroll
        for (int t = 0; t < 8; t++)
#pragma unroll
            for (int e = 0; e < 4; e++) S[t][e] = 0.f;

        const int qsec[3] = {0, 1, 0}, ksec[3] = {0, 0, 1};
#pragma unroll
        for (int sp = 0; sp < 3; sp++) {
#pragma unroll
            for (int kk = 0; kk < 4; kk++) {
                uint32_t a0, a1, a2, a3;
                uint32_t addr = smem_u32(&sQ[(wid * 16 + (lane & 15)) * FA_LD +
                                             qsec[sp] * 64 + kk * 16 + (lane >> 4) * 8]);
                LDSM_X4(a0, a1, a2, a3, addr);
                uint32_t bf[8][2];
#pragma unroll
                for (int p = 0; p < 4; p++) {
                    uint32_t ba = smem_u32(&sK[(p * 16 + ((lane >> 4) << 3) + (lane & 7)) * FA_LD +
                                               ksec[sp] * 64 + kk * 16 + ((lane >> 3) & 1) * 8]);
                    LDSM_X4(bf[2 * p][0], bf[2 * p][1], bf[2 * p + 1][0], bf[2 * p + 1][1], ba);
                }
#pragma unroll
                for (int nt = 0; nt < 8; nt++)
                    MMA16816(S[nt], a0, a1, a2, a3, bf[nt][0], bf[nt][1]);
            }
        }

#pragma unroll
        for (int nt = 0; nt < 8; nt++) {
            int c0 = j0 + nt * 8 + (lane & 3) * 2;
#pragma unroll
            for (int e = 0; e < 2; e++) {
                int jj = c0 + e;
                if (jj < NT) {
                    if (r0g < NT) S[nt][e]     += sRel[rel_index(r0g, jj)];
                    if (r1g < NT) S[nt][2 + e] += sRel[rel_index(r1g, jj)];
                } else {
                    S[nt][e] = -1e30f;
                    S[nt][2 + e] = -1e30f;
                }
            }
        }

        float t0 = -1e30f, t1 = -1e30f;
#pragma unroll
        for (int nt = 0; nt < 8; nt++) {
            t0 = fmaxf(t0, fmaxf(S[nt][0], S[nt][1]));
            t1 = fmaxf(t1, fmaxf(S[nt][2], S[nt][3]));
        }
        t0 = fmaxf(t0, __shfl_xor_sync(0xffffffff, t0, 1));
        t0 = fmaxf(t0, __shfl_xor_sync(0xffffffff, t0, 2));
        t1 = fmaxf(t1, __shfl_xor_sync(0xffffffff, t1, 1));
        t1 = fmaxf(t1, __shfl_xor_sync(0xffffffff, t1, 2));
        float mn0 = fmaxf(m0, t0), mn1 = fmaxf(m1, t1);
        float al0 = __expf(m0 - mn0), al1 = __expf(m1 - mn1);
#pragma unroll
        for (int nt = 0; nt < 8; nt++) {
            O[nt][0] *= al0; O[nt][1] *= al0;
            O[nt][2] *= al1; O[nt][3] *= al1;
        }
        float ls0 = 0.f, ls1 = 0.f;
        uint32_t phi[4][4], plo[4][4];
#pragma unroll
        for (int kk = 0; kk < 4; kk++) {
#pragma unroll
            for (int tt = 0; tt < 2; tt++) {
                int t = 2 * kk + tt;
                float p0 = __expf(S[t][0] - mn0), p1 = __expf(S[t][1] - mn0);
                float p2 = __expf(S[t][2] - mn1), p3 = __expf(S[t][3] - mn1);
                ls0 += p0 + p1; ls1 += p2 + p3;
                float h0 = b2f(__float2bfloat16(p0));
                float h1 = b2f(__float2bfloat16(p1));
                float h2 = b2f(__float2bfloat16(p2));
                float h3 = b2f(__float2bfloat16(p3));
                phi[kk][tt * 2]     = pack_bf16(h0, h1);
                phi[kk][tt * 2 + 1] = pack_bf16(h2, h3);
                plo[kk][tt * 2]     = pack_bf16(p0 - h0, p1 - h1);
                plo[kk][tt * 2 + 1] = pack_bf16(p2 - h2, p3 - h3);
            }
        }
        ls0 += __shfl_xor_sync(0xffffffff, ls0, 1);
        ls0 += __shfl_xor_sync(0xffffffff, ls0, 2);
        ls1 += __shfl_xor_sync(0xffffffff, ls1, 1);
        ls1 += __shfl_xor_sync(0xffffffff, ls1, 2);
        l0 = l0 * al0 + ls0;
        l1 = l1 * al1 + ls1;
        m0 = mn0; m1 = mn1;

        const int vsec[3] = {0, 0, 1};
#pragma unroll
        for (int sp = 0; sp < 3; sp++) {
#pragma unroll
            for (int kk = 0; kk < 4; kk++) {
                uint32_t* A = (sp == 1) ? plo[kk] : phi[kk];
                uint32_t bf[8][2];
#pragma unroll
                for (int p = 0; p < 4; p++) {
                    uint32_t ba = smem_u32(&sV[(p * 16 + ((lane >> 4) << 3) + (lane & 7)) * FA_LD +
                                               vsec[sp] * 64 + kk * 16 + ((lane >> 3) & 1) * 8]);
                    LDSM_X4(bf[2 * p][0], bf[2 * p][1], bf[2 * p + 1][0], bf[2 * p + 1][1], ba);
                }
#pragma unroll
                for (int nt = 0; nt < 8; nt++)
                    MMA16816(O[nt], A[0], A[1], A[2], A[3], bf[nt][0], bf[nt][1]);
            }
        }
    }

    float il0 = 1.0f / l0, il1 = 1.0f / l1;
#pragma unroll
    for (int nt = 0; nt < 8; nt++) {
        int d = h * 64 + nt * 8 + (lane & 3) * 2;
        if (r0g < NT) {
            float v0 = O[nt][0] * il0, v1 = O[nt][1] * il0;
            __nv_bfloat16 h0, lo0, h1, lo1;
            split2(v0, h0, lo0); split2(v1, h1, lo1);
            __nv_bfloat16* o = opk + ((size_t)b * NT + r0g) * 1536;
            *(uint32_t*)&o[d] = pack_bf16(b2f(h0), b2f(h1));
            *(uint32_t*)&o[768 + d] = pack_bf16(b2f(lo0), b2f(lo1));
        }
        if (r1g < NT) {
            float v0 = O[nt][2] * il1, v1 = O[nt][3] * il1;
            __nv_bfloat16 h0, lo0, h1, lo1;
            split2(v0, h0, lo0); split2(v1, h1, lo1);
            __nv_bfloat16* o = opk + ((size_t)b * NT + r1g) * 1536;
            *(uint32_t*)&o[d] = pack_bf16(b2f(h0), b2f(h1));
            *(uint32_t*)&o[768 + d] = pack_bf16(b2f(lo0), b2f(lo1));
        }
    }
}

// ------------------------- elementwise helpers ------------------------------
__global__ void patchify_kernel(const float* __restrict__ x, float* __restrict__ A) {
    int idx = blockIdx.x * 256 + threadIdx.x;
    if (idx >= BATCH * 1024 * EMB) return;
    int col = idx % EMB;
    int m = idx / EMB;
    int b = m / 1024, g = m % 1024;
    int gh = g / 32, gw = g % 32;
    int c = col / 256, rem = col % 256;
    int i = rem / 16, j = rem % 16;
    A[idx] = x[(((size_t)(b * 3 + c) * 512) + gh * 16 + i) * 512 + gw * 16 + j];
}

__global__ void assemble_kernel(const float* __restrict__ tok, const float* __restrict__ cls,
                                const float* __restrict__ pos, float* __restrict__ t) {
    int idx = blockIdx.x * 256 + threadIdx.x;
    if (idx >= BATCH * NT * EMB) return;
    int d = idx % EMB;
    int n = (idx / EMB) % NT;
    int b = idx / (EMB * NT);
    float v = (n == 0) ? cls[d] : tok[((size_t)b * 1024 + (n - 1)) * EMB + d];
    t[idx] = v + pos[n * EMB + d];
}

__global__ void biaspack_all_kernel(const float* __restrict__ qb, const float* __restrict__ vb,
                                    float* __restrict__ out) {
    int i = blockIdx.x * 256 + threadIdx.x;
    if (i >= 12 * 3 * EMB) return;
    int l = i / (3 * EMB), r = i % (3 * EMB);
    out[i] = (r < EMB) ? qb[l * EMB + r]
           : ((r < 2 * EMB) ? 0.f : vb[l * EMB + r - 2 * EMB]);
}

__global__ void copy4_kernel(const float4* __restrict__ src, float4* __restrict__ dst, int n4) {
    int i = blockIdx.x * 256 + threadIdx.x;
    if (i < n4) dst[i] = src[i];
}

__global__ void repack_w_kernel(const float* __restrict__ w, float* __restrict__ wp) {
    int idx = blockIdx.x * 256 + threadIdx.x;
    if (idx >= 3072 * 768) return;
    int c = idx % 768, n = idx / 768;
    int ij = n / 768, d = n % 768;
    wp[idx] = w[(size_t)c * 3072 + d * 4 + ij];
}

__global__ void scatter_bhwc_kernel(const float* __restrict__ tmp, const float* __restrict__ bias,
                                    float* __restrict__ y, int HW) {
    int total = BATCH * HW * HW * 4 * 768;
    int idx = blockIdx.x * 256 + threadIdx.x;
    if (idx >= total) return;
    int d = idx % 768;
    int ij = (idx / 768) % 4;
    int p = (idx / 3072) % (HW * HW);
    int b = idx / (3072 * HW * HW);
    int h = p / HW, w = p % HW, i = ij / 2, j = ij % 2;
    int W2 = 2 * HW;
    y[(((size_t)b * W2 + 2 * h + i) * W2 + (2 * w + j)) * 768 + d] = tmp[idx] + bias[d];
}

__global__ void scatter_bchw_kernel(const float* __restrict__ tmp, const float* __restrict__ bias,
                                    float* __restrict__ out, int HW) {
    int total = BATCH * HW * HW * 4 * 768;
    int idx = blockIdx.x * 256 + threadIdx.x;
    if (idx >= total) return;
    int d = idx % 768;
    int ij = (idx / 768) % 4;
    int p = (idx / 3072) % (HW * HW);
    int b = idx / (3072 * HW * HW);
    int h = p / HW, w = p % HW, i = ij / 2, j = ij % 2;
    int W2 = 2 * HW;
    out[(((size_t)b * 768 + d) * W2 + 2 * h + i) * W2 + (2 * w + j)] = tmp[idx] + bias[d];
}

__global__ void bn_gelu_kernel(float* __restrict__ y, const float* __restrict__ w,
                               const float* __restrict__ b, const float* __restrict__ mean,
                               const float* __restrict__ var) {
    int idx = blockIdx.x * 256 + threadIdx.x;
    if (idx >= BATCH * 64 * 64 * 768) return;
    int c = idx % 768;
    float v = y[idx];
    v = (v - mean[c]) * rsqrtf(var[c] + 1e-5f) * w[c] + b[c];
    y[idx] = gelu_exact(v);
}

__global__ void to_map_kernel(const float* __restrict__ feat, float* __restrict__ out) {
    int idx = blockIdx.x * 256 + threadIdx.x;
    if (idx >= BATCH * 768 * 32 * 32) return;
    int xw = idx % 32;
    int yh = (idx / 32) % 32;
    int c = (idx / 1024) % 768;
    int b = idx / (1024 * 768);
    out[idx] = feat[((size_t)b * NT + 1 + yh * 32 + xw) * EMB + c];
}

__global__ void maxpool_kernel(const float* __restrict__ feat, float* __restrict__ out) {
    int idx = blockIdx.x * 256 + threadIdx.x;
    if (idx >= BATCH * 768 * 16 * 16) return;
    int xw = idx % 16;
    int yh = (idx / 16) % 16;
    int c = (idx / 256) % 768;
    int b = idx / (256 * 768);
    float m = -1e30f;
#pragma unroll
    for (int i = 0; i < 2; i++)
#pragma unroll
        for (int j = 0; j < 2; j++) {
            int Y = 2 * yh + i, X = 2 * xw + j;
            m = fmaxf(m, feat[((size_t)b * NT + 1 + Y * 32 + X) * EMB + c]);
        }
    out[idx] = m;
}

// ------------------------- host helpers -------------------------------------
static void fast_pack(const float* in, __nv_bfloat16* out, int M, int K,
                      size_t irs, size_t ibs, size_t obs, float scale, int nz) {
    dim3 g(M, nz);
    fast_pack_kernel<<<g, 256>>>(in, out, K, irs, ibs, obs, scale);
}
#define SMEM_BIG   (2 * 2 * (128 + 128) * 40 * 2)
#define SMEM_SMALL (3 * 2 * (64 + 64) * 40 * 2)
static void gemm_tc(const __nv_bfloat16* A, const __nv_bfloat16* B, float* C,
                    __nv_bfloat16* Cp, const float* bias, const float* resid,
                    int M, int N, int Kp, size_t Abs, size_t Bbs, size_t ldc,
                    size_t cs0, size_t cs1, int nh, int gelu, int nz) {
    int gm128 = (M + 127) / 128;
    if (N % 128 == 0 && (N / 128) * gm128 * nz >= 148) {
        dim3 g(N / 128, gm128, nz);
        hgemm2<128, 128, 2, 2><<<g, 256, SMEM_BIG>>>(A, B, C, Cp, bias, resid, M, N, Kp,
                                                     Abs, Bbs, ldc, cs0, cs1, nh, gelu);
    } else {
        dim3 g(N / 64, (M + 63) / 64, nz);
        hgemm2<64, 64, 3, 3><<<g, 256, SMEM_SMALL>>>(A, B, C, Cp, bias, resid, M, N, Kp,
                                                     Abs, Bbs, ldc, cs0, cs1, nh, gelu);
    }
}

extern "C" void kernel_launch(void* const* d_in, const int* in_sizes, int n_in,
                              void* d_out, int out_size) {
    const float* x         = (const float*)d_in[0];
    const float* patch_w   = (const float*)d_in[1];
    const float* patch_b   = (const float*)d_in[2];
    const float* cls_token = (const float*)d_in[3];
    const float* pos_embed = (const float*)d_in[4];
    const float* ln1_w     = (const float*)d_in[5];
    const float* ln1_b     = (const float*)d_in[6];
    const float* qkv_w     = (const float*)d_in[7];
    const float* q_bias    = (const float*)d_in[8];
    const float* v_bias    = (const float*)d_in[9];
    const float* rel_tab   = (const float*)d_in[10];
    const float* proj_w    = (const float*)d_in[11];
    const float* proj_b    = (const float*)d_in[12];
    const float* ln2_w     = (const float*)d_in[13];
    const float* ln2_b     = (const float*)d_in[14];
    const float* fc1_w     = (const float*)d_in[15];
    const float* fc1_b     = (const float*)d_in[16];
    const float* fc2_w     = (const float*)d_in[17];
    const float* fc2_b     = (const float*)d_in[18];
    const float* d1_w      = (const float*)d_in[19];
    const float* d1_b      = (const float*)d_in[20];
    const float* bn_w      = (const float*)d_in[21];
    const float* bn_b      = (const float*)d_in[22];
    const float* bn_mean   = (const float*)d_in[23];
    const float* bn_var    = (const float*)d_in[24];
    const float* d2_w      = (const float*)d_in[25];
    const float* d2_b      = (const float*)d_in[26];
    const float* f2w       = (const float*)d_in[27];
    const float* f2b       = (const float*)d_in[28];

    float* out = (float*)d_out;
    float* out1 = out;
    float* out2 = out1 + (size_t)BATCH * 768 * 128 * 128;
    float* out3 = out2 + (size_t)BATCH * 768 * 64 * 64;
    float* out4 = out3 + (size_t)BATCH * 768 * 32 * 32;

    static float *pt = nullptr, *pqkv, *ppatch, *ptok;
    static float *pf0, *pf1, *pf2, *pf3, *py, *ptmp, *pwp, *pqb;
    static __nv_bfloat16 *pa, *pb, *pc, *pw;
    if (!pt) {
        cudaGetSymbolAddress((void**)&pt, g_t);
        cudaGetSymbolAddress((void**)&pqkv, g_qkv);
        cudaGetSymbolAddress((void**)&ppatch, g_patch);
        cudaGetSymbolAddress((void**)&ptok, g_tok);
        cudaGetSymbolAddress((void**)&pf0, g_feat0);
        cudaGetSymbolAddress((void**)&pf1, g_feat1);
        cudaGetSymbolAddress((void**)&pf2, g_feat2);
        cudaGetSymbolAddress((void**)&pf3, g_feat3);
        cudaGetSymbolAddress((void**)&py, g_y);
        cudaGetSymbolAddress((void**)&ptmp, g_tmp);
        cudaGetSymbolAddress((void**)&pwp, g_wpack);
        cudaGetSymbolAddress((void**)&pqb, g_qkvbias);
        cudaGetSymbolAddress((void**)&pa, g_pa);
        cudaGetSymbolAddress((void**)&pb, g_pb);
        cudaGetSymbolAddress((void**)&pc, g_pc);
        cudaGetSymbolAddress((void**)&pw, g_pw);
        cudaFuncSetAttribute(flash_attn_kernel,
                             cudaFuncAttributeMaxDynamicSharedMemorySize,
                             (128 + 64 + 64) * FA_LD * 2 + NREL * 4);
        cudaFuncSetAttribute((const void*)hgemm2<128, 128, 2, 2>,
                             cudaFuncAttributeMaxDynamicSharedMemorySize, SMEM_BIG);
        cudaFuncSetAttribute((const void*)hgemm2<64, 64, 3, 3>,
                             cudaFuncAttributeMaxDynamicSharedMemorySize, SMEM_SMALL);
    }

    const int TOKELEMS = BATCH * NT * EMB;
    const int M = BATCH * NT;  // 2050
    const int FA_SMEM = (128 + 64 + 64) * FA_LD * 2 + NREL * 4;

    // ---- pre-pack ALL transformer weights (4 batched vectorized launches) ----
    fast_pack(qkv_w, pw + W_QKV, 2304, 768, 768, (size_t)2304 * 768, W_PER, 1.0f, 12);
    fast_pack(proj_w, pw + W_PROJ, 768, 768, 768, (size_t)768 * 768, W_PER, 1.0f, 12);
    fast_pack(fc1_w, pw + W_FC1, 3072, 768, 768, (size_t)3072 * 768, W_PER, 1.0f, 12);
    fast_pack(fc2_w, pw + W_FC2, 768, 3072, 3072, (size_t)768 * 3072, W_PER, 1.0f, 12);
    biaspack_all_kernel<<<(12 * 3 * EMB + 255) / 256, 256>>>(q_bias, v_bias, pqb);

    // ---- patch embed ----
    patchify_kernel<<<(BATCH * 1024 * EMB + 255) / 256, 256>>>(x, ppatch);
    fast_pack(ppatch, pa, 2048, 768, 768, 0, 0, 1.0f, 1);
    fast_pack(patch_w, pb, 768, 768, 768, 0, 0, 1.0f, 1);
    gemm_tc(pa, pb, ptok, nullptr, patch_b, nullptr, 2048, 768, 768, 0, 0,
            768, 0, 0, 1, 0, 1);
    assemble_kernel<<<(TOKELEMS + 255) / 256, 256>>>(ptok, cls_token, pos_embed, pt);

    // ---- transformer layers ----
    for (int l = 0; l < 12; l++) {
        const __nv_bfloat16* wl = pw + (size_t)l * W_PER;
        ln_pack_kernel<<<M, 256>>>(pt, ln1_w + l * EMB, ln1_b + l * EMB, pa);
        gemm_tc(pa, wl + W_QKV, pqkv, nullptr, pqb + l * 2304, nullptr, M, 2304, 768, 0, 0,
                2304, 0, 0, 1, 0, 1);
        {
            dim3 g((NT + 127) / 128, BATCH * HEADS);
            flash_attn_kernel<<<g, 256, FA_SMEM>>>(pqkv, rel_tab + (size_t)l * NREL * HEADS, pa);
        }
        gemm_tc(pa, wl + W_PROJ, pt, nullptr, proj_b + l * EMB, pt, M, 768, 768, 0, 0,
                768, 0, 0, 1, 0, 1);
        ln_pack_kernel<<<M, 256>>>(pt, ln2_w + l * EMB, ln2_b + l * EMB, pa);
        gemm_tc(pa, wl + W_FC1, nullptr, pc, fc1_b + l * 4 * EMB, nullptr, M, 3072, 768, 0, 0,
                3072, 0, 0, 1, 1, 1);
        gemm_tc(pc, wl + W_FC2, pt, nullptr, fc2_b + l * EMB, pt, M, 768, 3072, 0, 0,
                768, 0, 0, 1, 0, 1);
        float* fdst = nullptr;
        if (l == 3) fdst = pf0;
        else if (l == 5) fdst = pf1;
        else if (l == 7) fdst = pf2;
        else if (l == 11) fdst = pf3;
        if (fdst) copy4_kernel<<<(TOKELEMS / 4 + 255) / 256, 256>>>((const float4*)pt,
                                                                    (float4*)fdst, TOKELEMS / 4);
    }

    // ---- o3 / o4 ----
    to_map_kernel<<<(BATCH * 768 * 1024 + 255) / 256, 256>>>(pf2, out3);
    maxpool_kernel<<<(BATCH * 768 * 256 + 255) / 256, 256>>>(pf3, out4);

    // ---- fpn1 stage 1 ----
    repack_w_kernel<<<(3072 * 768 + 255) / 256, 256>>>(d1_w, pwp);
    fast_pack(pwp, pb, 3072, 768, 768, 0, 0, 1.0f, 1);
    fast_pack(pf0 + 768, pa, 1024, 768, 768, (size_t)NT * 768, (size_t)1024 * 1536, 1.0f, BATCH);
    gemm_tc(pa, pb, ptmp, nullptr, nullptr, nullptr, 1024, 3072, 768,
            (size_t)1024 * 1536, 0, 3072, (size_t)1024 * 3072, 0, 1, 0, BATCH);
    scatter_bhwc_kernel<<<(BATCH * 1024 * 3072 + 255) / 256, 256>>>(ptmp, d1_b, py, 32);
    bn_gelu_kernel<<<(BATCH * 64 * 64 * 768 + 255) / 256, 256>>>(py, bn_w, bn_b, bn_mean, bn_var);

    // ---- fpn1 stage 2 ----
    repack_w_kernel<<<(3072 * 768 + 255) / 256, 256>>>(d2_w, pwp);
    fast_pack(pwp, pb, 3072, 768, 768, 0, 0, 1.0f, 1);
    fast_pack(py, pa, 4096, 768, 768, (size_t)4096 * 768, (size_t)4096 * 1536, 1.0f, BATCH);
    gemm_tc(pa, pb, ptmp, nullptr, nullptr, nullptr, 4096, 3072, 768,
            (size_t)4096 * 1536, 0, 3072, (size_t)4096 * 3072, 0, 1, 0, BATCH);
    scatter_bchw_kernel<<<(BATCH * 4096 * 3072 + 255) / 256, 256>>>(ptmp, d2_b, out1, 64);

    // ---- o2 ----
    repack_w_kernel<<<(3072 * 768 + 255) / 256, 256>>>(f2w, pwp);
    fast_pack(pwp, pb, 3072, 768, 768, 0, 0, 1.0f, 1);
    fast_pack(pf1 + 768, pa, 1024, 768, 768, (size_t)NT * 768, (size_t)1024 * 1536, 1.0f, BATCH);
    gemm_tc(pa, pb, ptmp, nullptr, nullptr, nullptr, 1024, 3072, 768,
            (size_t)1024 * 1536, 0, 3072, (size_t)1024 * 3072, 0, 1, 0, BATCH);
    scatter_bchw_kernel<<<(BATCH * 1024 * 3072 + 255) / 256, 256>>>(ptmp, f2b, out2, 32);

    (void)in_sizes; (void)n_in; (void)out_size;
}

// round 14
// speedup vs baseline: 1.2979x; 1.0465x over previous
#include <cuda_runtime.h>
#include <cuda_bf16.h>
#include <math.h>
#include <stdint.h>

#define NT    1025
#define EMB   768
#define BATCH 2
#define HEADS 12
#define NREL  3972

// ------------------------- device scratch (no allocs allowed) ---------------
__device__ float g_t[BATCH * NT * EMB];
__device__ float g_qkv[BATCH * NT * 3 * EMB];
__device__ float g_patch[BATCH * 1024 * EMB];
__device__ float g_tok[BATCH * 1024 * EMB];
__device__ float g_feat0[BATCH * NT * EMB];
__device__ float g_feat1[BATCH * NT * EMB];
__device__ float g_feat2[BATCH * NT * EMB];
__device__ float g_feat3[BATCH * NT * EMB];
__device__ float g_y[BATCH * 64 * 64 * EMB];
__device__ float g_tmp[(size_t)BATCH * 4096 * 3072];
__device__ float g_wpack[3072 * 768];
__device__ float g_qkvbias[12 * 3 * EMB];
__device__ __nv_bfloat16 g_pa[14000000];
__device__ __nv_bfloat16 g_pb[5000000];
__device__ __nv_bfloat16 g_pc[12700000];
#define W_QKV  0
#define W_PROJ 3538944
#define W_FC1  4718592
#define W_FC2  9437184
#define W_PER  14155776
__device__ __nv_bfloat16 g_pw[12 * 14155776];

__device__ __forceinline__ float gelu_exact(float x) {
    return 0.5f * x * (1.0f + erff(x * 0.70710678118654752f));
}

__device__ __forceinline__ uint32_t smem_u32(const void* p) {
    uint32_t a;
    asm("{ .reg .u64 t; cvta.to.shared.u64 t, %1; cvt.u32.u64 %0, t; }" : "=r"(a) : "l"(p));
    return a;
}

#define LDSM_X4(r0, r1, r2, r3, addr) \
    asm volatile("ldmatrix.sync.aligned.m8n8.x4.shared.b16 {%0,%1,%2,%3}, [%4];" \
                 : "=r"(r0), "=r"(r1), "=r"(r2), "=r"(r3) : "r"(addr))

#define MMA16816(d, a0, a1, a2, a3, b0, b1) \
    asm volatile("mma.sync.aligned.m16n8k16.row.col.f32.bf16.bf16.f32 " \
                 "{%0,%1,%2,%3}, {%4,%5,%6,%7}, {%8,%9}, {%0,%1,%2,%3};" \
                 : "+f"((d)[0]), "+f"((d)[1]), "+f"((d)[2]), "+f"((d)[3]) \
                 : "r"(a0), "r"(a1), "r"(a2), "r"(a3), "r"(b0), "r"(b1))

#define CP_ASYNC16(dst, src, sz) \
    asm volatile("cp.async.cg.shared.global [%0], [%1], 16, %2;" \
                 :: "r"(dst), "l"(src), "r"(sz))

__device__ __forceinline__ uint32_t pack_bf16(float x, float y) {
    __nv_bfloat162 t = __floats2bfloat162_rn(x, y);
    return *(uint32_t*)&t;
}
__device__ __forceinline__ void split2(float v, __nv_bfloat16& hi, __nv_bfloat16& lo) {
    hi = __float2bfloat16(v);
    lo = __float2bfloat16(v - __bfloat162float(hi));
}
__device__ __forceinline__ float b2f(__nv_bfloat16 v) { return __bfloat162float(v); }

// arithmetic reproduction of make_rel_pos_index
__device__ __forceinline__ int rel_index(int i, int j) {
    if (j == 0) return (i == 0) ? (NREL - 1) : (NREL - 2);
    if (i == 0) return NREL - 3;
    int yi = (i - 1) >> 5, xi = (i - 1) & 31;
    int yj = (j - 1) >> 5, xj = (j - 1) & 31;
    return (yi - yj + 31) * 63 + (xi - xj + 31);
}

// ============ vectorized split-bf16 pack ([hi|lo], contiguous rows) =========
__global__ void fast_pack_kernel(const float* __restrict__ in, __nv_bfloat16* __restrict__ out,
                                 int K, size_t irs, size_t ibs, size_t obs, float scale) {
    int row = blockIdx.x, z = blockIdx.y;
    const float4* src = (const float4*)(in + (size_t)z * ibs + (size_t)row * irs);
    __nv_bfloat16* o = out + (size_t)z * obs + (size_t)row * (2 * (size_t)K);
    for (int k4 = threadIdx.x; k4 < (K >> 2); k4 += 256) {
        float4 v = src[k4];
        v.x *= scale; v.y *= scale; v.z *= scale; v.w *= scale;
        __nv_bfloat16 h0, l0, h1, l1, h2, l2, h3, l3;
        split2(v.x, h0, l0); split2(v.y, h1, l1);
        split2(v.z, h2, l2); split2(v.w, h3, l3);
        uint2 hv = make_uint2(pack_bf16(b2f(h0), b2f(h1)), pack_bf16(b2f(h2), b2f(h3)));
        uint2 lv = make_uint2(pack_bf16(b2f(l0), b2f(l1)), pack_bf16(b2f(l2), b2f(l3)));
        *(uint2*)&o[k4 * 4] = hv;
        *(uint2*)&o[K + k4 * 4] = lv;
    }
}

// ---------------- fused LayerNorm + split-bf16 pack -------------------------
__global__ void ln_pack_kernel(const float* __restrict__ x, const float* __restrict__ w,
                               const float* __restrict__ b, __nv_bfloat16* __restrict__ out) {
    int r = blockIdx.x;
    const float* xr = x + (size_t)r * EMB;
    __shared__ float red[256];
    int tid = threadIdx.x;
    float s = 0.f;
    for (int i = tid; i < EMB; i += 256) s += xr[i];
    red[tid] = s; __syncthreads();
    for (int st = 128; st > 0; st >>= 1) { if (tid < st) red[tid] += red[tid + st]; __syncthreads(); }
    float mean = red[0] * (1.0f / EMB);
    __syncthreads();
    float s2 = 0.f;
    for (int i = tid; i < EMB; i += 256) { float d = xr[i] - mean; s2 += d * d; }
    red[tid] = s2; __syncthreads();
    for (int st = 128; st > 0; st >>= 1) { if (tid < st) red[tid] += red[tid + st]; __syncthreads(); }
    float inv = rsqrtf(red[0] * (1.0f / EMB) + 1e-6f);
    __nv_bfloat16* o = out + (size_t)r * (2 * EMB);
    for (int i = tid; i < EMB; i += 256) {
        float v = (xr[i] - mean) * inv * w[i] + b[i];
        __nv_bfloat16 hi, lo; split2(v, hi, lo);
        o[i] = hi; o[EMB + i] = lo;
    }
}

// ========================= HMMA GEMM (split-product reuse) ==================
template <int BM, int BN, int NSTAGE, int MINB>
__global__ void __launch_bounds__(256, MINB) hgemm2(
    const __nv_bfloat16* __restrict__ A, const __nv_bfloat16* __restrict__ B,
    float* __restrict__ C, __nv_bfloat16* __restrict__ Cp,
    const float* __restrict__ bias, const float* __restrict__ resid,
    int M, int Nreal, int Kp, size_t Abs, size_t Bbs,
    size_t ldc, size_t cs0, size_t cs1, int nh, int do_gelu) {
    constexpr int MT = BM / 32;
    constexpr int WTN = BN / 4;
    constexpr int NT8 = WTN / 8;
    constexpr int AIT = BM / 64;
    constexpr int NB4 = BN / 64;
    constexpr int AHALF = BM * 40;
    constexpr int BHALF = BN * 40;
    constexpr int STAGE = 2 * (AHALF + BHALF);
    extern __shared__ __nv_bfloat16 dsm[];

    int tid = threadIdx.x;
    int wid = tid >> 5, lane = tid & 31;
    int warp_m = wid >> 2, warp_n = wid & 3;
    int m0 = blockIdx.y * BM, n0 = blockIdx.x * BN;
    int z = blockIdx.z;

    const size_t lda = 2 * (size_t)Kp, ldb = 2 * (size_t)Kp;
    const __nv_bfloat16* Az = A + (size_t)z * Abs;
    const __nv_bfloat16* Bz = B + (size_t)z * Bbs;

    float acc[MT][NT8][4];
#pragma unroll
    for (int i = 0; i < MT; i++)
#pragma unroll
        for (int j = 0; j < NT8; j++)
#pragma unroll
            for (int e = 0; e < 4; e++) acc[i][j][e] = 0.f;

    int nk = Kp >> 5;

    auto load_body = [&](int c, int s) {
        __nv_bfloat16* st = dsm + s * STAGE;
#pragma unroll
        for (int sec = 0; sec < 2; sec++) {
#pragma unroll
            for (int i = 0; i < AIT; i++) {
                int idx = tid + i * 256, row = idx >> 2, cg = idx & 3;
                uint32_t dst = smem_u32(st + sec * AHALF + row * 40 + cg * 8);
                const __nv_bfloat16* src = Az + (size_t)(m0 + row) * lda +
                                           (size_t)sec * Kp + c * 32 + cg * 8;
                CP_ASYNC16(dst, src, (m0 + row < M) ? 16 : 0);
            }
        }
#pragma unroll
        for (int sec = 0; sec < 2; sec++) {
#pragma unroll
            for (int i = 0; i < NB4; i++) {
                int idx = tid + i * 256, row = idx >> 2, cg = idx & 3;
                uint32_t dst = smem_u32(st + 2 * AHALF + sec * BHALF + row * 40 + cg * 8);
                const __nv_bfloat16* src = Bz + (size_t)(n0 + row) * ldb +
                                           (size_t)sec * Kp + c * 32 + cg * 8;
                CP_ASYNC16(dst, src, (n0 + row < Nreal) ? 16 : 0);
            }
        }
    };

#pragma unroll
    for (int s = 0; s < NSTAGE - 1; s++) {
        if (s < nk) load_body(s, s);
        asm volatile("cp.async.commit_group;");
    }

    uint32_t aoff = (warp_m * (BM / 2) + (lane & 15)) * 40 + (lane >> 4) * 8;
    uint32_t boff = (warp_n * WTN + ((lane >> 4) << 3) + (lane & 7)) * 40 + ((lane >> 3) & 1) * 8;
    uint32_t dsm0 = smem_u32(dsm);

    for (int c = 0; c < nk; c++) {
        asm volatile("cp.async.wait_group %0;" :: "n"(NSTAGE - 2));
        __syncthreads();
        {
            int ncd = c + NSTAGE - 1;
            if (ncd < nk) load_body(ncd, ncd % NSTAGE);
            asm volatile("cp.async.commit_group;");
        }
        uint32_t sbase = dsm0 + (c % NSTAGE) * STAGE * 2;
#pragma unroll
        for (int kk = 0; kk < 2; kk++) {
            uint32_t ahi[MT][4], alo[MT][4];
#pragma unroll
            for (int mt = 0; mt < MT; mt++) {
                uint32_t ad = sbase + (aoff + mt * 16 * 40 + kk * 16) * 2;
                LDSM_X4(ahi[mt][0], ahi[mt][1], ahi[mt][2], ahi[mt][3], ad);
                LDSM_X4(alo[mt][0], alo[mt][1], alo[mt][2], alo[mt][3], ad + AHALF * 2);
            }
            uint32_t bhi[NT8][2], blo[NT8][2];
#pragma unroll
            for (int p = 0; p < NT8 / 2; p++) {
                uint32_t bd = sbase + 2 * AHALF * 2 + (boff + p * 16 * 40 + kk * 16) * 2;
                LDSM_X4(bhi[2 * p][0], bhi[2 * p][1], bhi[2 * p + 1][0], bhi[2 * p + 1][1], bd);
                LDSM_X4(blo[2 * p][0], blo[2 * p][1], blo[2 * p + 1][0], blo[2 * p + 1][1],
                        bd + BHALF * 2);
            }
#pragma unroll
            for (int mt = 0; mt < MT; mt++)
#pragma unroll
                for (int nt = 0; nt < NT8; nt++)
                    MMA16816(acc[mt][nt], ahi[mt][0], ahi[mt][1], ahi[mt][2], ahi[mt][3],
                             bhi[nt][0], bhi[nt][1]);
#pragma unroll
            for (int mt = 0; mt < MT; mt++)
#pragma unroll
                for (int nt = 0; nt < NT8; nt++)
                    MMA16816(acc[mt][nt], ahi[mt][0], ahi[mt][1], ahi[mt][2], ahi[mt][3],
                             blo[nt][0], blo[nt][1]);
#pragma unroll
            for (int mt = 0; mt < MT; mt++)
#pragma unroll
                for (int nt = 0; nt < NT8; nt++)
                    MMA16816(acc[mt][nt], alo[mt][0], alo[mt][1], alo[mt][2], alo[mt][3],
                             bhi[nt][0], bhi[nt][1]);
        }
    }

    size_t cbase = (size_t)(z / nh) * cs0 + (size_t)(z % nh) * cs1;
    int mrow = lane >> 2, ncol = (lane & 3) * 2;
#pragma unroll
    for (int mt = 0; mt < MT; mt++) {
#pragma unroll
        for (int half = 0; half < 2; half++) {
            int row = m0 + warp_m * (BM / 2) + mt * 16 + mrow + half * 8;
            if (row >= M) continue;
#pragma unroll
            for (int nt = 0; nt < NT8; nt++) {
                int col = n0 + warp_n * WTN + nt * 8 + ncol;
                float v0 = acc[mt][nt][half * 2];
                float v1 = acc[mt][nt][half * 2 + 1];
                if (bias) { v0 += bias[col]; v1 += bias[col + 1]; }
                if (resid) {
                    size_t off = cbase + (size_t)row * ldc + col;
                    v0 += resid[off]; v1 += resid[off + 1];
                }
                if (do_gelu) { v0 = gelu_exact(v0); v1 = gelu_exact(v1); }
                if (C) {
                    size_t off = cbase + (size_t)row * ldc + col;
                    if (col < Nreal) C[off] = v0;
                    if (col + 1 < Nreal) C[off + 1] = v1;
                }
                if (Cp) {
                    __nv_bfloat16 h0, l0b, h1, l1b;
                    split2(v0, h0, l0b); split2(v1, h1, l1b);
                    __nv_bfloat16* o = Cp + (size_t)row * (2 * (size_t)Nreal);
                    if (col + 1 < Nreal) {
                        *(uint32_t*)&o[col] = pack_bf16(b2f(h0), b2f(h1));
                        *(uint32_t*)&o[Nreal + col] = pack_bf16(b2f(l0b), b2f(l1b));
                    } else if (col < Nreal) {
                        o[col] = h0; o[Nreal + col] = l0b;
                    }
                }
            }
        }
    }
}

// ========================= fused flash attention ============================
#define FA_LD 136
__global__ void __launch_bounds__(256, 2) flash_attn_kernel(
    const float* __restrict__ qkv, const float* __restrict__ relt,
    __nv_bfloat16* __restrict__ opk) {
    extern __shared__ __nv_bfloat16 fsm[];
    __nv_bfloat16* sQ = fsm;
    __nv_bfloat16* sK = fsm + 128 * FA_LD;
    __nv_bfloat16* sV = sK + 64 * FA_LD;
    float* sRel = (float*)(sV + 64 * FA_LD);

    int tid = threadIdx.x, wid = tid >> 5, lane = tid & 31;
    int i0 = blockIdx.x * 128;
    int z = blockIdx.y;
    int b = z / HEADS, h = z % HEADS;
    const float* qb = qkv + (size_t)b * NT * 2304 + h * 64;
    const float* kb = qb + 768;
    const float* vb = qb + 1536;

    for (int i = tid; i < NREL; i += 256) sRel[i] = relt[(size_t)i * HEADS + h];

    for (int idx = tid; idx < 128 * 64; idx += 256) {
        int r = idx >> 6, c = idx & 63;
        int gi = i0 + r;
        float v = (gi < NT) ? qb[(size_t)gi * 2304 + c] * 0.125f : 0.f;
        __nv_bfloat16 hi, lo; split2(v, hi, lo);
        sQ[r * FA_LD + c] = hi;
        sQ[r * FA_LD + 64 + c] = lo;
    }

    float m0 = -1e30f, m1 = -1e30f, l0 = 0.f, l1 = 0.f;
    float O[8][4];
#pragma unroll
    for (int t = 0; t < 8; t++)
#pragma unroll
        for (int e = 0; e < 4; e++) O[t][e] = 0.f;

    int r0g = i0 + wid * 16 + (lane >> 2);
    int r1g = r0g + 8;

    for (int j0 = 0; j0 < NT; j0 += 64) {
        __syncthreads();
        for (int idx = tid; idx < 64 * 64; idx += 256) {
            int r = idx >> 6, c = idx & 63;
            int gj = j0 + r;
            float kv = (gj < NT) ? kb[(size_t)gj * 2304 + c] : 0.f;
            __nv_bfloat16 khi, klo; split2(kv, khi, klo);
            sK[r * FA_LD + c] = khi;
            sK[r * FA_LD + 64 + c] = klo;
            float vv = (gj < NT) ? vb[(size_t)gj * 2304 + c] : 0.f;
            __nv_bfloat16 vhi, vlo; split2(vv, vhi, vlo);
            sV[c * FA_LD + r] = vhi;
            sV[c * FA_LD + 64 + r] = vlo;
        }
        __syncthreads();

        float S[8][4];
#pragma unroll
        for (int t = 0; t < 8; t++)
#pragma unroll
            for (int e = 0; e < 4; e++) S[t][e] = 0.f;

        const int qsec[3] = {0, 1, 0}, ksec[3] = {0, 0, 1};
#pragma unroll
        for (int sp = 0; sp < 3; sp++) {
#pragma unroll
            for (int kk = 0; kk < 4; kk++) {
                uint32_t a0, a1, a2, a3;
                uint32_t addr = smem_u32(&sQ[(wid * 16 + (lane & 15)) * FA_LD +
                                             qsec[sp] * 64 + kk * 16 + (lane >> 4) * 8]);
                LDSM_X4(a0, a1, a2, a3, addr);
                uint32_t bf[8][2];
#pragma unroll
                for (int p = 0; p < 4; p++) {
                    uint32_t ba = smem_u32(&sK[(p * 16 + ((lane >> 4) << 3) + (lane & 7)) * FA_LD +
                                               ksec[sp] * 64 + kk * 16 + ((lane >> 3) & 1) * 8]);
                    LDSM_X4(bf[2 * p][0], bf[2 * p][1], bf[2 * p + 1][0], bf[2 * p + 1][1], ba);
                }
#pragma unroll
                for (int nt = 0; nt < 8; nt++)
                    MMA16816(S[nt], a0, a1, a2, a3, bf[nt][0], bf[nt][1]);
            }
        }

#pragma unroll
        for (int nt = 0; nt < 8; nt++) {
            int c0 = j0 + nt * 8 + (lane & 3) * 2;
#pragma unroll
            for (int e = 0; e < 2; e++) {
                int jj = c0 + e;
                if (jj < NT) {
                    if (r0g < NT) S[nt][e]     += sRel[rel_index(r0g, jj)];
                    if (r1g < NT) S[nt][2 + e] += sRel[rel_index(r1g, jj)];
                } else {
                    S[nt][e] = -1e30f;
                    S[nt][2 + e] = -1e30f;
                }
            }
        }

        float t0 = -1e30f, t1 = -1e30f;
#pragma unroll
        for (int nt = 0; nt < 8; nt++) {
            t0 = fmaxf(t0, fmaxf(S[nt][0], S[nt][1]));
            t1 = fmaxf(t1, fmaxf(S[nt][2], S[nt][3]));
        }
        t0 = fmaxf(t0, __shfl_xor_sync(0xffffffff, t0, 1));
        t0 = fmaxf(t0, __shfl_xor_sync(0xffffffff, t0, 2));
        t1 = fmaxf(t1, __shfl_xor_sync(0xffffffff, t1, 1));
        t1 = fmaxf(t1, __shfl_xor_sync(0xffffffff, t1, 2));
        float mn0 = fmaxf(m0, t0), mn1 = fmaxf(m1, t1);
        float al0 = __expf(m0 - mn0), al1 = __expf(m1 - mn1);
#pragma unroll
        for (int nt = 0; nt < 8; nt++) {
            O[nt][0] *= al0; O[nt][1] *= al0;
            O[nt][2] *= al1; O[nt][3] *= al1;
        }
        float ls0 = 0.f, ls1 = 0.f;
        uint32_t phi[4][4], plo[4][4];
#pragma unroll
        for (int kk = 0; kk < 4; kk++) {
#pragma unroll
            for (int tt = 0; tt < 2; tt++) {
                int t = 2 * kk + tt;
                float p0 = __expf(S[t][0] - mn0), p1 = __expf(S[t][1] - mn0);
                float p2 = __expf(S[t][2] - mn1), p3 = __expf(S[t][3] - mn1);
                ls0 += p0 + p1; ls1 += p2 + p3;
                float h0 = b2f(__float2bfloat16(p0));
                float h1 = b2f(__float2bfloat16(p1));
                float h2 = b2f(__float2bfloat16(p2));
                float h3 = b2f(__float2bfloat16(p3));
                phi[kk][tt * 2]     = pack_bf16(h0, h1);
                phi[kk][tt * 2 + 1] = pack_bf16(h2, h3);
                plo[kk][tt * 2]     = pack_bf16(p0 - h0, p1 - h1);
                plo[kk][tt * 2 + 1] = pack_bf16(p2 - h2, p3 - h3);
            }
        }
        ls0 += __shfl_xor_sync(0xffffffff, ls0, 1);
        ls0 += __shfl_xor_sync(0xffffffff, ls0, 2);
        ls1 += __shfl_xor_sync(0xffffffff, ls1, 1);
        ls1 += __shfl_xor_sync(0xffffffff, ls1, 2);
        l0 = l0 * al0 + ls0;
        l1 = l1 * al1 + ls1;
        m0 = mn0; m1 = mn1;

        const int vsec[3] = {0, 0, 1};
#pragma unroll
        for (int sp = 0; sp < 3; sp++) {
#pragma unroll
            for (int kk = 0; kk < 4; kk++) {
                uint32_t* A = (sp == 1) ? plo[kk] : phi[kk];
                uint32_t bf[8][2];
#pragma unroll
                for (int p = 0; p < 4; p++) {
                    uint32_t ba = smem_u32(&sV[(p * 16 + ((lane >> 4) << 3) + (lane & 7)) * FA_LD +
                                               vsec[sp] * 64 + kk * 16 + ((lane >> 3) & 1) * 8]);
                    LDSM_X4(bf[2 * p][0], bf[2 * p][1], bf[2 * p + 1][0], bf[2 * p + 1][1], ba);
                }
#pragma unroll
                for (int nt = 0; nt < 8; nt++)
                    MMA16816(O[nt], A[0], A[1], A[2], A[3], bf[nt][0], bf[nt][1]);
            }
        }
    }

    float il0 = 1.0f / l0, il1 = 1.0f / l1;
#pragma unroll
    for (int nt = 0; nt < 8; nt++) {
        int d = h * 64 + nt * 8 + (lane & 3) * 2;
        if (r0g < NT) {
            float v0 = O[nt][0] * il0, v1 = O[nt][1] * il0;
            __nv_bfloat16 h0, lo0, h1, lo1;
            split2(v0, h0, lo0); split2(v1, h1, lo1);
            __nv_bfloat16* o = opk + ((size_t)b * NT + r0g) * 1536;
            *(uint32_t*)&o[d] = pack_bf16(b2f(h0), b2f(h1));
            *(uint32_t*)&o[768 + d] = pack_bf16(b2f(lo0), b2f(lo1));
        }
        if (r1g < NT) {
            float v0 = O[nt][2] * il1, v1 = O[nt][3] * il1;
            __nv_bfloat16 h0, lo0, h1, lo1;
            split2(v0, h0, lo0); split2(v1, h1, lo1);
            __nv_bfloat16* o = opk + ((size_t)b * NT + r1g) * 1536;
            *(uint32_t*)&o[d] = pack_bf16(b2f(h0), b2f(h1));
            *(uint32_t*)&o[768 + d] = pack_bf16(b2f(lo0), b2f(lo1));
        }
    }
}

// ------------------------- elementwise helpers ------------------------------
__global__ void patchify_kernel(const float* __restrict__ x, float* __restrict__ A) {
    int idx = blockIdx.x * 256 + threadIdx.x;
    if (idx >= BATCH * 1024 * EMB) return;
    int col = idx % EMB;
    int m = idx / EMB;
    int b = m / 1024, g = m % 1024;
    int gh = g / 32, gw = g % 32;
    int c = col / 256, rem = col % 256;
    int i = rem / 16, j = rem % 16;
    A[idx] = x[(((size_t)(b * 3 + c) * 512) + gh * 16 + i) * 512 + gw * 16 + j];
}

__global__ void assemble_kernel(const float* __restrict__ tok, const float* __restrict__ cls,
                                const float* __restrict__ pos, float* __restrict__ t) {
    int idx = blockIdx.x * 256 + threadIdx.x;
    if (idx >= BATCH * NT * EMB) return;
    int d = idx % EMB;
    int n = (idx / EMB) % NT;
    int b = idx / (EMB * NT);
    float v = (n == 0) ? cls[d] : tok[((size_t)b * 1024 + (n - 1)) * EMB + d];
    t[idx] = v + pos[n * EMB + d];
}

__global__ void biaspack_all_kernel(const float* __restrict__ qb, const float* __restrict__ vb,
                                    float* __restrict__ out) {
    int i = blockIdx.x * 256 + threadIdx.x;
    if (i >= 12 * 3 * EMB) return;
    int l = i / (3 * EMB), r = i % (3 * EMB);
    out[i] = (r < EMB) ? qb[l * EMB + r]
           : ((r < 2 * EMB) ? 0.f : vb[l * EMB + r - 2 * EMB]);
}

__global__ void copy4_kernel(const float4* __restrict__ src, float4* __restrict__ dst, int n4) {
    int i = blockIdx.x * 256 + threadIdx.x;
    if (i < n4) dst[i] = src[i];
}

__global__ void repack_w_kernel(const float* __restrict__ w, float* __restrict__ wp) {
    int idx = blockIdx.x * 256 + threadIdx.x;
    if (idx >= 3072 * 768) return;
    int c = idx % 768, n = idx / 768;
    int ij = n / 768, d = n % 768;
    wp[idx] = w[(size_t)c * 3072 + d * 4 + ij];
}

__global__ void scatter_bhwc_kernel(const float* __restrict__ tmp, const float* __restrict__ bias,
                                    float* __restrict__ y, int HW) {
    int total = BATCH * HW * HW * 4 * 768;
    int idx = blockIdx.x * 256 + threadIdx.x;
    if (idx >= total) return;
    int d = idx % 768;
    int ij = (idx / 768) % 4;
    int p = (idx / 3072) % (HW * HW);
    int b = idx / (3072 * HW * HW);
    int h = p / HW, w = p % HW, i = ij / 2, j = ij % 2;
    int W2 = 2 * HW;
    y[(((size_t)b * W2 + 2 * h + i) * W2 + (2 * w + j)) * 768 + d] = tmp[idx] + bias[d];
}

__global__ void scatter_bchw_kernel(const float* __restrict__ tmp, const float* __restrict__ bias,
                                    float* __restrict__ out, int HW) {
    int total = BATCH * HW * HW * 4 * 768;
    int idx = blockIdx.x * 256 + threadIdx.x;
    if (idx >= total) return;
    int d = idx % 768;
    int ij = (idx / 768) % 4;
    int p = (idx / 3072) % (HW * HW);
    int b = idx / (3072 * HW * HW);
    int h = p / HW, w = p % HW, i = ij / 2, j = ij % 2;
    int W2 = 2 * HW;
    out[(((size_t)b * 768 + d) * W2 + 2 * h + i) * W2 + (2 * w + j)] = tmp[idx] + bias[d];
}

__global__ void bn_gelu_kernel(float* __restrict__ y, const float* __restrict__ w,
                               const float* __restrict__ b, const float* __restrict__ mean,
                               const float* __restrict__ var) {
    int idx = blockIdx.x * 256 + threadIdx.x;
    if (idx >= BATCH * 64 * 64 * 768) return;
    int c = idx % 768;
    float v = y[idx];
    v = (v - mean[c]) * rsqrtf(var[c] + 1e-5f) * w[c] + b[c];
    y[idx] = gelu_exact(v);
}

__global__ void to_map_kernel(const float* __restrict__ feat, float* __restrict__ out) {
    int idx = blockIdx.x * 256 + threadIdx.x;
    if (idx >= BATCH * 768 * 32 * 32) return;
    int xw = idx % 32;
    int yh = (idx / 32) % 32;
    int c = (idx / 1024) % 768;
    int b = idx / (1024 * 768);
    out[idx] = feat[((size_t)b * NT + 1 + yh * 32 + xw) * EMB + c];
}

__global__ void maxpool_kernel(const float* __restrict__ feat, float* __restrict__ out) {
    int idx = blockIdx.x * 256 + threadIdx.x;
    if (idx >= BATCH * 768 * 16 * 16) return;
    int xw = idx % 16;
    int yh = (idx / 16) % 16;
    int c = (idx / 256) % 768;
    int b = idx / (256 * 768);
    float m = -1e30f;
#pragma unroll
    for (int i = 0; i < 2; i++)
#pragma unroll
        for (int j = 0; j < 2; j++) {
            int Y = 2 * yh + i, X = 2 * xw + j;
            m = fmaxf(m, feat[((size_t)b * NT + 1 + Y * 32 + X) * EMB + c]);
        }
    out[idx] = m;
}

// ------------------------- host helpers -------------------------------------
static void fast_pack(const float* in, __nv_bfloat16* out, int M, int K,
                      size_t irs, size_t ibs, size_t obs, float scale, int nz) {
    dim3 g(M, nz);
    fast_pack_kernel<<<g, 256>>>(in, out, K, irs, ibs, obs, scale);
}
#define SMEM_MED   (3 * 2 * (64 + 128) * 40 * 2)   // 92160, BM64/BN128 3-stage
#define SMEM_SMALL (3 * 2 * (64 + 64) * 40 * 2)    // 61440, BM64/BN64  3-stage
static void gemm_tc(const __nv_bfloat16* A, const __nv_bfloat16* B, float* C,
                    __nv_bfloat16* Cp, const float* bias, const float* resid,
                    int M, int N, int Kp, size_t Abs, size_t Bbs, size_t ldc,
                    size_t cs0, size_t cs1, int nh, int gelu, int nz) {
    int gm64 = (M + 63) / 64;
    if (N % 128 == 0 && (N / 128) * gm64 * nz >= 232) {
        dim3 g(N / 128, gm64, nz);
        hgemm2<64, 128, 3, 2><<<g, 256, SMEM_MED>>>(A, B, C, Cp, bias, resid, M, N, Kp,
                                                    Abs, Bbs, ldc, cs0, cs1, nh, gelu);
    } else {
        dim3 g(N / 64, gm64, nz);
        hgemm2<64, 64, 3, 3><<<g, 256, SMEM_SMALL>>>(A, B, C, Cp, bias, resid, M, N, Kp,
                                                     Abs, Bbs, ldc, cs0, cs1, nh, gelu);
    }
}

extern "C" void kernel_launch(void* const* d_in, const int* in_sizes, int n_in,
                              void* d_out, int out_size) {
    const float* x         = (const float*)d_in[0];
    const float* patch_w   = (const float*)d_in[1];
    const float* patch_b   = (const float*)d_in[2];
    const float* cls_token = (const float*)d_in[3];
    const float* pos_embed = (const float*)d_in[4];
    const float* ln1_w     = (const float*)d_in[5];
    const float* ln1_b     = (const float*)d_in[6];
    const float* qkv_w     = (const float*)d_in[7];
    const float* q_bias    = (const float*)d_in[8];
    const float* v_bias    = (const float*)d_in[9];
    const float* rel_tab   = (const float*)d_in[10];
    const float* proj_w    = (const float*)d_in[11];
    const float* proj_b    = (const float*)d_in[12];
    const float* ln2_w     = (const float*)d_in[13];
    const float* ln2_b     = (const float*)d_in[14];
    const float* fc1_w     = (const float*)d_in[15];
    const float* fc1_b     = (const float*)d_in[16];
    const float* fc2_w     = (const float*)d_in[17];
    const float* fc2_b     = (const float*)d_in[18];
    const float* d1_w      = (const float*)d_in[19];
    const float* d1_b      = (const float*)d_in[20];
    const float* bn_w      = (const float*)d_in[21];
    const float* bn_b      = (const float*)d_in[22];
    const float* bn_mean   = (const float*)d_in[23];
    const float* bn_var    = (const float*)d_in[24];
    const float* d2_w      = (const float*)d_in[25];
    const float* d2_b      = (const float*)d_in[26];
    const float* f2w       = (const float*)d_in[27];
    const float* f2b       = (const float*)d_in[28];

    float* out = (float*)d_out;
    float* out1 = out;
    float* out2 = out1 + (size_t)BATCH * 768 * 128 * 128;
    float* out3 = out2 + (size_t)BATCH * 768 * 64 * 64;
    float* out4 = out3 + (size_t)BATCH * 768 * 32 * 32;

    static float *pt = nullptr, *pqkv, *ppatch, *ptok;
    static float *pf0, *pf1, *pf2, *pf3, *py, *ptmp, *pwp, *pqb;
    static __nv_bfloat16 *pa, *pb, *pc, *pw;
    if (!pt) {
        cudaGetSymbolAddress((void**)&pt, g_t);
        cudaGetSymbolAddress((void**)&pqkv, g_qkv);
        cudaGetSymbolAddress((void**)&ppatch, g_patch);
        cudaGetSymbolAddress((void**)&ptok, g_tok);
        cudaGetSymbolAddress((void**)&pf0, g_feat0);
        cudaGetSymbolAddress((void**)&pf1, g_feat1);
        cudaGetSymbolAddress((void**)&pf2, g_feat2);
        cudaGetSymbolAddress((void**)&pf3, g_feat3);
        cudaGetSymbolAddress((void**)&py, g_y);
        cudaGetSymbolAddress((void**)&ptmp, g_tmp);
        cudaGetSymbolAddress((void**)&pwp, g_wpack);
        cudaGetSymbolAddress((void**)&pqb, g_qkvbias);
        cudaGetSymbolAddress((void**)&pa, g_pa);
        cudaGetSymbolAddress((void**)&pb, g_pb);
        cudaGetSymbolAddress((void**)&pc, g_pc);
        cudaGetSymbolAddress((void**)&pw, g_pw);
        cudaFuncSetAttribute(flash_attn_kernel,
                             cudaFuncAttributeMaxDynamicSharedMemorySize,
                             (128 + 64 + 64) * FA_LD * 2 + NREL * 4);
        cudaFuncSetAttribute((const void*)hgemm2<64, 128, 3, 2>,
                             cudaFuncAttributeMaxDynamicSharedMemorySize, SMEM_MED);
        cudaFuncSetAttribute((const void*)hgemm2<64, 64, 3, 3>,
                             cudaFuncAttributeMaxDynamicSharedMemorySize, SMEM_SMALL);
    }

    const int TOKELEMS = BATCH * NT * EMB;
    const int M = BATCH * NT;  // 2050
    const int FA_SMEM = (128 + 64 + 64) * FA_LD * 2 + NREL * 4;

    // ---- pre-pack ALL transformer weights ----
    fast_pack(qkv_w, pw + W_QKV, 2304, 768, 768, (size_t)2304 * 768, W_PER, 1.0f, 12);
    fast_pack(proj_w, pw + W_PROJ, 768, 768, 768, (size_t)768 * 768, W_PER, 1.0f, 12);
    fast_pack(fc1_w, pw + W_FC1, 3072, 768, 768, (size_t)3072 * 768, W_PER, 1.0f, 12);
    fast_pack(fc2_w, pw + W_FC2, 768, 3072, 3072, (size_t)768 * 3072, W_PER, 1.0f, 12);
    biaspack_all_kernel<<<(12 * 3 * EMB + 255) / 256, 256>>>(q_bias, v_bias, pqb);

    // ---- patch embed ----
    patchify_kernel<<<(BATCH * 1024 * EMB + 255) / 256, 256>>>(x, ppatch);
    fast_pack(ppatch, pa, 2048, 768, 768, 0, 0, 1.0f, 1);
    fast_pack(patch_w, pb, 768, 768, 768, 0, 0, 1.0f, 1);
    gemm_tc(pa, pb, ptok, nullptr, patch_b, nullptr, 2048, 768, 768, 0, 0,
            768, 0, 0, 1, 0, 1);
    assemble_kernel<<<(TOKELEMS + 255) / 256, 256>>>(ptok, cls_token, pos_embed, pt);

    // ---- transformer layers ----
    for (int l = 0; l < 12; l++) {
        const __nv_bfloat16* wl = pw + (size_t)l * W_PER;
        ln_pack_kernel<<<M, 256>>>(pt, ln1_w + l * EMB, ln1_b + l * EMB, pa);
        gemm_tc(pa, wl + W_QKV, pqkv, nullptr, pqb + l * 2304, nullptr, M, 2304, 768, 0, 0,
                2304, 0, 0, 1, 0, 1);
        {
            dim3 g((NT + 127) / 128, BATCH * HEADS);
            flash_attn_kernel<<<g, 256, FA_SMEM>>>(pqkv, rel_tab + (size_t)l * NREL * HEADS, pa);
        }
        gemm_tc(pa, wl + W_PROJ, pt, nullptr, proj_b + l * EMB, pt, M, 768, 768, 0, 0,
                768, 0, 0, 1, 0, 1);
        ln_pack_kernel<<<M, 256>>>(pt, ln2_w + l * EMB, ln2_b + l * EMB, pa);
        gemm_tc(pa, wl + W_FC1, nullptr, pc, fc1_b + l * 4 * EMB, nullptr, M, 3072, 768, 0, 0,
                3072, 0, 0, 1, 1, 1);
        gemm_tc(pc, wl + W_FC2, pt, nullptr, fc2_b + l * EMB, pt, M, 768, 3072, 0, 0,
                768, 0, 0, 1, 0, 1);
        float* fdst = nullptr;
        if (l == 3) fdst = pf0;
        else if (l == 5) fdst = pf1;
        else if (l == 7) fdst = pf2;
        else if (l == 11) fdst = pf3;
        if (fdst) copy4_kernel<<<(TOKELEMS / 4 + 255) / 256, 256>>>((const float4*)pt,
                                                                    (float4*)fdst, TOKELEMS / 4);
    }

    // ---- o3 / o4 ----
    to_map_kernel<<<(BATCH * 768 * 1024 + 255) / 256, 256>>>(pf2, out3);
    maxpool_kernel<<<(BATCH * 768 * 256 + 255) / 256, 256>>>(pf3, out4);

    // ---- fpn1 stage 1 ----
    repack_w_kernel<<<(3072 * 768 + 255) / 256, 256>>>(d1_w, pwp);
    fast_pack(pwp, pb, 3072, 768, 768, 0, 0, 1.0f, 1);
    fast_pack(pf0 + 768, pa, 1024, 768, 768, (size_t)NT * 768, (size_t)1024 * 1536, 1.0f, BATCH);
    gemm_tc(pa, pb, ptmp, nullptr, nullptr, nullptr, 1024, 3072, 768,
            (size_t)1024 * 1536, 0, 3072, (size_t)1024 * 3072, 0, 1, 0, BATCH);
    scatter_bhwc_kernel<<<(BATCH * 1024 * 3072 + 255) / 256, 256>>>(ptmp, d1_b, py, 32);
    bn_gelu_kernel<<<(BATCH * 64 * 64 * 768 + 255) / 256, 256>>>(py, bn_w, bn_b, bn_mean, bn_var);

    // ---- fpn1 stage 2 ----
    repack_w_kernel<<<(3072 * 768 + 255) / 256, 256>>>(d2_w, pwp);
    fast_pack(pwp, pb, 3072, 768, 768, 0, 0, 1.0f, 1);
    fast_pack(py, pa, 4096, 768, 768, (size_t)4096 * 768, (size_t)4096 * 1536, 1.0f, BATCH);
    gemm_tc(pa, pb, ptmp, nullptr, nullptr, nullptr, 4096, 3072, 768,
            (size_t)4096 * 1536, 0, 3072, (size_t)4096 * 3072, 0, 1, 0, BATCH);
    scatter_bchw_kernel<<<(BATCH * 4096 * 3072 + 255) / 256, 256>>>(ptmp, d2_b, out1, 64);

    // ---- o2 ----
    repack_w_kernel<<<(3072 * 768 + 255) / 256, 256>>>(f2w, pwp);
    fast_pack(pwp, pb, 3072, 768, 768, 0, 0, 1.0f, 1);
    fast_pack(pf1 + 768, pa, 1024, 768, 768, (size_t)NT * 768, (size_t)1024 * 1536, 1.0f, BATCH);
    gemm_tc(pa, pb, ptmp, nullptr, nullptr, nullptr, 1024, 3072, 768,
            (size_t)1024 * 1536, 0, 3072, (size_t)1024 * 3072, 0, 1, 0, BATCH);
    scatter_bchw_kernel<<<(BATCH * 1024 * 3072 + 255) / 256, 256>>>(ptmp, f2b, out2, 32);

    (void)in_sizes; (void)n_in; (void)out_size;
}

// round 15
// speedup vs baseline: 1.3397x; 1.0322x over previous
#include <cuda_runtime.h>
#include <cuda_bf16.h>
#include <math.h>
#include <stdint.h>

#define NT    1025
#define EMB   768
#define BATCH 2
#define HEADS 12
#define NREL  3972

// ------------------------- device scratch (no allocs allowed) ---------------
__device__ float g_t[BATCH * NT * EMB];
__device__ float g_qkv[BATCH * NT * 3 * EMB];
__device__ float g_patch[BATCH * 1024 * EMB];
__device__ float g_tok[BATCH * 1024 * EMB];
__device__ float g_feat0[BATCH * NT * EMB];
__device__ float g_feat1[BATCH * NT * EMB];
__device__ float g_feat2[BATCH * NT * EMB];
__device__ float g_feat3[BATCH * NT * EMB];
__device__ float g_y[BATCH * 64 * 64 * EMB];
__device__ float g_tmp[(size_t)BATCH * 4096 * 3072];
__device__ float g_wpack[3072 * 768];
__device__ float g_qkvbias[12 * 3 * EMB];
__device__ __nv_bfloat16 g_pa[14000000];
__device__ __nv_bfloat16 g_pb[5000000];
__device__ __nv_bfloat16 g_pc[12700000];
// dedicated FPN operand buffers (stream-2; never aliased with main loop)
__device__ __nv_bfloat16 g_fpa[12600000];   // max: stage2 A 2*4096*1536 = 12.58M
__device__ __nv_bfloat16 g_fpb[4750000];    // deconv W 3072*1536 = 4.72M
#define W_QKV  0
#define W_PROJ 3538944
#define W_FC1  4718592
#define W_FC2  9437184
#define W_PER  14155776
__device__ __nv_bfloat16 g_pw[12 * 14155776];

__device__ __forceinline__ float gelu_exact(float x) {
    return 0.5f * x * (1.0f + erff(x * 0.70710678118654752f));
}

__device__ __forceinline__ uint32_t smem_u32(const void* p) {
    uint32_t a;
    asm("{ .reg .u64 t; cvta.to.shared.u64 t, %1; cvt.u32.u64 %0, t; }" : "=r"(a) : "l"(p));
    return a;
}

#define LDSM_X4(r0, r1, r2, r3, addr) \
    asm volatile("ldmatrix.sync.aligned.m8n8.x4.shared.b16 {%0,%1,%2,%3}, [%4];" \
                 : "=r"(r0), "=r"(r1), "=r"(r2), "=r"(r3) : "r"(addr))

#define MMA16816(d, a0, a1, a2, a3, b0, b1) \
    asm volatile("mma.sync.aligned.m16n8k16.row.col.f32.bf16.bf16.f32 " \
                 "{%0,%1,%2,%3}, {%4,%5,%6,%7}, {%8,%9}, {%0,%1,%2,%3};" \
                 : "+f"((d)[0]), "+f"((d)[1]), "+f"((d)[2]), "+f"((d)[3]) \
                 : "r"(a0), "r"(a1), "r"(a2), "r"(a3), "r"(b0), "r"(b1))

#define CP_ASYNC16(dst, src, sz) \
    asm volatile("cp.async.cg.shared.global [%0], [%1], 16, %2;" \
                 :: "r"(dst), "l"(src), "r"(sz))

__device__ __forceinline__ uint32_t pack_bf16(float x, float y) {
    __nv_bfloat162 t = __floats2bfloat162_rn(x, y);
    return *(uint32_t*)&t;
}
__device__ __forceinline__ void split2(float v, __nv_bfloat16& hi, __nv_bfloat16& lo) {
    hi = __float2bfloat16(v);
    lo = __float2bfloat16(v - __bfloat162float(hi));
}
__device__ __forceinline__ float b2f(__nv_bfloat16 v) { return __bfloat162float(v); }

// arithmetic reproduction of make_rel_pos_index
__device__ __forceinline__ int rel_index(int i, int j) {
    if (j == 0) return (i == 0) ? (NREL - 1) : (NREL - 2);
    if (i == 0) return NREL - 3;
    int yi = (i - 1) >> 5, xi = (i - 1) & 31;
    int yj = (j - 1) >> 5, xj = (j - 1) & 31;
    return (yi - yj + 31) * 63 + (xi - xj + 31);
}

// ============ vectorized split-bf16 pack ([hi|lo], contiguous rows) =========
__global__ void fast_pack_kernel(const float* __restrict__ in, __nv_bfloat16* __restrict__ out,
                                 int K, size_t irs, size_t ibs, size_t obs, float scale) {
    int row = blockIdx.x, z = blockIdx.y;
    const float4* src = (const float4*)(in + (size_t)z * ibs + (size_t)row * irs);
    __nv_bfloat16* o = out + (size_t)z * obs + (size_t)row * (2 * (size_t)K);
    for (int k4 = threadIdx.x; k4 < (K >> 2); k4 += 256) {
        float4 v = src[k4];
        v.x *= scale; v.y *= scale; v.z *= scale; v.w *= scale;
        __nv_bfloat16 h0, l0, h1, l1, h2, l2, h3, l3;
        split2(v.x, h0, l0); split2(v.y, h1, l1);
        split2(v.z, h2, l2); split2(v.w, h3, l3);
        uint2 hv = make_uint2(pack_bf16(b2f(h0), b2f(h1)), pack_bf16(b2f(h2), b2f(h3)));
        uint2 lv = make_uint2(pack_bf16(b2f(l0), b2f(l1)), pack_bf16(b2f(l2), b2f(l3)));
        *(uint2*)&o[k4 * 4] = hv;
        *(uint2*)&o[K + k4 * 4] = lv;
    }
}

// ---------------- fused LayerNorm + split-bf16 pack -------------------------
__global__ void ln_pack_kernel(const float* __restrict__ x, const float* __restrict__ w,
                               const float* __restrict__ b, __nv_bfloat16* __restrict__ out) {
    int r = blockIdx.x;
    const float* xr = x + (size_t)r * EMB;
    __shared__ float red[256];
    int tid = threadIdx.x;
    float s = 0.f;
    for (int i = tid; i < EMB; i += 256) s += xr[i];
    red[tid] = s; __syncthreads();
    for (int st = 128; st > 0; st >>= 1) { if (tid < st) red[tid] += red[tid + st]; __syncthreads(); }
    float mean = red[0] * (1.0f / EMB);
    __syncthreads();
    float s2 = 0.f;
    for (int i = tid; i < EMB; i += 256) { float d = xr[i] - mean; s2 += d * d; }
    red[tid] = s2; __syncthreads();
    for (int st = 128; st > 0; st >>= 1) { if (tid < st) red[tid] += red[tid + st]; __syncthreads(); }
    float inv = rsqrtf(red[0] * (1.0f / EMB) + 1e-6f);
    __nv_bfloat16* o = out + (size_t)r * (2 * EMB);
    for (int i = tid; i < EMB; i += 256) {
        float v = (xr[i] - mean) * inv * w[i] + b[i];
        __nv_bfloat16 hi, lo; split2(v, hi, lo);
        o[i] = hi; o[EMB + i] = lo;
    }
}

// ========================= HMMA GEMM (split-product reuse) ==================
template <int BM, int BN, int NSTAGE, int MINB>
__global__ void __launch_bounds__(256, MINB) hgemm2(
    const __nv_bfloat16* __restrict__ A, const __nv_bfloat16* __restrict__ B,
    float* __restrict__ C, __nv_bfloat16* __restrict__ Cp,
    const float* __restrict__ bias, const float* __restrict__ resid,
    int M, int Nreal, int Kp, size_t Abs, size_t Bbs,
    size_t ldc, size_t cs0, size_t cs1, int nh, int do_gelu) {
    constexpr int MT = BM / 32;
    constexpr int WTN = BN / 4;
    constexpr int NT8 = WTN / 8;
    constexpr int AIT = BM / 64;
    constexpr int NB4 = BN / 64;
    constexpr int AHALF = BM * 40;
    constexpr int BHALF = BN * 40;
    constexpr int STAGE = 2 * (AHALF + BHALF);
    extern __shared__ __nv_bfloat16 dsm[];

    int tid = threadIdx.x;
    int wid = tid >> 5, lane = tid & 31;
    int warp_m = wid >> 2, warp_n = wid & 3;
    int m0 = blockIdx.y * BM, n0 = blockIdx.x * BN;
    int z = blockIdx.z;

    const size_t lda = 2 * (size_t)Kp, ldb = 2 * (size_t)Kp;
    const __nv_bfloat16* Az = A + (size_t)z * Abs;
    const __nv_bfloat16* Bz = B + (size_t)z * Bbs;

    float acc[MT][NT8][4];
#pragma unroll
    for (int i = 0; i < MT; i++)
#pragma unroll
        for (int j = 0; j < NT8; j++)
#pragma unroll
            for (int e = 0; e < 4; e++) acc[i][j][e] = 0.f;

    int nk = Kp >> 5;

    auto load_body = [&](int c, int s) {
        __nv_bfloat16* st = dsm + s * STAGE;
#pragma unroll
        for (int sec = 0; sec < 2; sec++) {
#pragma unroll
            for (int i = 0; i < AIT; i++) {
                int idx = tid + i * 256, row = idx >> 2, cg = idx & 3;
                uint32_t dst = smem_u32(st + sec * AHALF + row * 40 + cg * 8);
                const __nv_bfloat16* src = Az + (size_t)(m0 + row) * lda +
                                           (size_t)sec * Kp + c * 32 + cg * 8;
                CP_ASYNC16(dst, src, (m0 + row < M) ? 16 : 0);
            }
        }
#pragma unroll
        for (int sec = 0; sec < 2; sec++) {
#pragma unroll
            for (int i = 0; i < NB4; i++) {
                int idx = tid + i * 256, row = idx >> 2, cg = idx & 3;
                uint32_t dst = smem_u32(st + 2 * AHALF + sec * BHALF + row * 40 + cg * 8);
                const __nv_bfloat16* src = Bz + (size_t)(n0 + row) * ldb +
                                           (size_t)sec * Kp + c * 32 + cg * 8;
                CP_ASYNC16(dst, src, (n0 + row < Nreal) ? 16 : 0);
            }
        }
    };

#pragma unroll
    for (int s = 0; s < NSTAGE - 1; s++) {
        if (s < nk) load_body(s, s);
        asm volatile("cp.async.commit_group;");
    }

    uint32_t aoff = (warp_m * (BM / 2) + (lane & 15)) * 40 + (lane >> 4) * 8;
    uint32_t boff = (warp_n * WTN + ((lane >> 4) << 3) + (lane & 7)) * 40 + ((lane >> 3) & 1) * 8;
    uint32_t dsm0 = smem_u32(dsm);

    for (int c = 0; c < nk; c++) {
        asm volatile("cp.async.wait_group %0;" :: "n"(NSTAGE - 2));
        __syncthreads();
        {
            int ncd = c + NSTAGE - 1;
            if (ncd < nk) load_body(ncd, ncd % NSTAGE);
            asm volatile("cp.async.commit_group;");
        }
        uint32_t sbase = dsm0 + (c % NSTAGE) * STAGE * 2;
#pragma unroll
        for (int kk = 0; kk < 2; kk++) {
            uint32_t ahi[MT][4], alo[MT][4];
#pragma unroll
            for (int mt = 0; mt < MT; mt++) {
                uint32_t ad = sbase + (aoff + mt * 16 * 40 + kk * 16) * 2;
                LDSM_X4(ahi[mt][0], ahi[mt][1], ahi[mt][2], ahi[mt][3], ad);
                LDSM_X4(alo[mt][0], alo[mt][1], alo[mt][2], alo[mt][3], ad + AHALF * 2);
            }
            uint32_t bhi[NT8][2], blo[NT8][2];
#pragma unroll
            for (int p = 0; p < NT8 / 2; p++) {
                uint32_t bd = sbase + 2 * AHALF * 2 + (boff + p * 16 * 40 + kk * 16) * 2;
                LDSM_X4(bhi[2 * p][0], bhi[2 * p][1], bhi[2 * p + 1][0], bhi[2 * p + 1][1], bd);
                LDSM_X4(blo[2 * p][0], blo[2 * p][1], blo[2 * p + 1][0], blo[2 * p + 1][1],
                        bd + BHALF * 2);
            }
#pragma unroll
            for (int mt = 0; mt < MT; mt++)
#pragma unroll
                for (int nt = 0; nt < NT8; nt++)
                    MMA16816(acc[mt][nt], ahi[mt][0], ahi[mt][1], ahi[mt][2], ahi[mt][3],
                             bhi[nt][0], bhi[nt][1]);
#pragma unroll
            for (int mt = 0; mt < MT; mt++)
#pragma unroll
                for (int nt = 0; nt < NT8; nt++)
                    MMA16816(acc[mt][nt], ahi[mt][0], ahi[mt][1], ahi[mt][2], ahi[mt][3],
                             blo[nt][0], blo[nt][1]);
#pragma unroll
            for (int mt = 0; mt < MT; mt++)
#pragma unroll
                for (int nt = 0; nt < NT8; nt++)
                    MMA16816(acc[mt][nt], alo[mt][0], alo[mt][1], alo[mt][2], alo[mt][3],
                             bhi[nt][0], bhi[nt][1]);
        }
    }

    size_t cbase = (size_t)(z / nh) * cs0 + (size_t)(z % nh) * cs1;
    int mrow = lane >> 2, ncol = (lane & 3) * 2;
#pragma unroll
    for (int mt = 0; mt < MT; mt++) {
#pragma unroll
        for (int half = 0; half < 2; half++) {
            int row = m0 + warp_m * (BM / 2) + mt * 16 + mrow + half * 8;
            if (row >= M) continue;
#pragma unroll
            for (int nt = 0; nt < NT8; nt++) {
                int col = n0 + warp_n * WTN + nt * 8 + ncol;
                float v0 = acc[mt][nt][half * 2];
                float v1 = acc[mt][nt][half * 2 + 1];
                if (bias) { v0 += bias[col]; v1 += bias[col + 1]; }
                if (resid) {
                    size_t off = cbase + (size_t)row * ldc + col;
                    v0 += resid[off]; v1 += resid[off + 1];
                }
                if (do_gelu) { v0 = gelu_exact(v0); v1 = gelu_exact(v1); }
                if (C) {
                    size_t off = cbase + (size_t)row * ldc + col;
                    if (col < Nreal) C[off] = v0;
                    if (col + 1 < Nreal) C[off + 1] = v1;
                }
                if (Cp) {
                    __nv_bfloat16 h0, l0b, h1, l1b;
                    split2(v0, h0, l0b); split2(v1, h1, l1b);
                    __nv_bfloat16* o = Cp + (size_t)row * (2 * (size_t)Nreal);
                    if (col + 1 < Nreal) {
                        *(uint32_t*)&o[col] = pack_bf16(b2f(h0), b2f(h1));
                        *(uint32_t*)&o[Nreal + col] = pack_bf16(b2f(l0b), b2f(l1b));
                    } else if (col < Nreal) {
                        o[col] = h0; o[Nreal + col] = l0b;
                    }
                }
            }
        }
    }
}

// ========================= fused flash attention ============================
#define FA_LD 136
__global__ void __launch_bounds__(256, 2) flash_attn_kernel(
    const float* __restrict__ qkv, const float* __restrict__ relt,
    __nv_bfloat16* __restrict__ opk) {
    extern __shared__ __nv_bfloat16 fsm[];
    __nv_bfloat16* sQ = fsm;
    __nv_bfloat16* sK = fsm + 128 * FA_LD;
    __nv_bfloat16* sV = sK + 64 * FA_LD;
    float* sRel = (float*)(sV + 64 * FA_LD);

    int tid = threadIdx.x, wid = tid >> 5, lane = tid & 31;
    int i0 = blockIdx.x * 128;
    int z = blockIdx.y;
    int b = z / HEADS, h = z % HEADS;
    const float* qb = qkv + (size_t)b * NT * 2304 + h * 64;
    const float* kb = qb + 768;
    const float* vb = qb + 1536;

    for (int i = tid; i < NREL; i += 256) sRel[i] = relt[(size_t)i * HEADS + h];

    for (int idx = tid; idx < 128 * 64; idx += 256) {
        int r = idx >> 6, c = idx & 63;
        int gi = i0 + r;
        float v = (gi < NT) ? qb[(size_t)gi * 2304 + c] * 0.125f : 0.f;
        __nv_bfloat16 hi, lo; split2(v, hi, lo);
        sQ[r * FA_LD + c] = hi;
        sQ[r * FA_LD + 64 + c] = lo;
    }

    float m0 = -1e30f, m1 = -1e30f, l0 = 0.f, l1 = 0.f;
    float O[8][4];
#pragma unroll
    for (int t = 0; t < 8; t++)
#pragma unroll
        for (int e = 0; e < 4; e++) O[t][e] = 0.f;

    int r0g = i0 + wid * 16 + (lane >> 2);
    int r1g = r0g + 8;

    for (int j0 = 0; j0 < NT; j0 += 64) {
        __syncthreads();
        for (int idx = tid; idx < 64 * 64; idx += 256) {
            int r = idx >> 6, c = idx & 63;
            int gj = j0 + r;
            float kv = (gj < NT) ? kb[(size_t)gj * 2304 + c] : 0.f;
            __nv_bfloat16 khi, klo; split2(kv, khi, klo);
            sK[r * FA_LD + c] = khi;
            sK[r * FA_LD + 64 + c] = klo;
            float vv = (gj < NT) ? vb[(size_t)gj * 2304 + c] : 0.f;
            __nv_bfloat16 vhi, vlo; split2(vv, vhi, vlo);
            sV[c * FA_LD + r] = vhi;
            sV[c * FA_LD + 64 + r] = vlo;
        }
        __syncthreads();

        float S[8][4];
#pragma unroll
        for (int t = 0; t < 8; t++)
#pragma unroll
            for (int e = 0; e < 4; e++) S[t][e] = 0.f;

        const int qsec[3] = {0, 1, 0}, ksec[3] = {0, 0, 1};
#pragma unroll
        for (int sp = 0; sp < 3; sp++) {
#pragma unroll
            for (int kk = 0; kk < 4; kk++) {
                uint32_t a0, a1, a2, a3;
                uint32_t addr = smem_u32(&sQ[(wid * 16 + (lane & 15)) * FA_LD +
                                             qsec[sp] * 64 + kk * 16 + (lane >> 4) * 8]);
                LDSM_X4(a0, a1, a2, a3, addr);
                uint32_t bf[8][2];
#pragma unroll
                for (int p = 0; p < 4; p++) {
                    uint32_t ba = smem_u32(&sK[(p * 16 + ((lane >> 4) << 3) + (lane & 7)) * FA_LD +
                                               ksec[sp] * 64 + kk * 16 + ((lane >> 3) & 1) * 8]);
                    LDSM_X4(bf[2 * p][0], bf[2 * p][1], bf[2 * p + 1][0], bf[2 * p + 1][1], ba);
                }
#pragma unroll
                for (int nt = 0; nt < 8; nt++)
                    MMA16816(S[nt], a0, a1, a2, a3, bf[nt][0], bf[nt][1]);
            }
        }

#pragma unroll
        for (int nt = 0; nt < 8; nt++) {
            int c0 = j0 + nt * 8 + (lane & 3) * 2;
#pragma unroll
            for (int e = 0; e < 2; e++) {
                int jj = c0 + e;
                if (jj < NT) {
                    if (r0g < NT) S[nt][e]     += sRel[rel_index(r0g, jj)];
                    if (r1g < NT) S[nt][2 + e] += sRel[rel_index(r1g, jj)];
                } else {
                    S[nt][e] = -1e30f;
                    S[nt][2 + e] = -1e30f;
                }
            }
        }

        float t0 = -1e30f, t1 = -1e30f;
#pragma unroll
        for (int nt = 0; nt < 8; nt++) {
            t0 = fmaxf(t0, fmaxf(S[nt][0], S[nt][1]));
            t1 = fmaxf(t1, fmaxf(S[nt][2], S[nt][3]));
        }
        t0 = fmaxf(t0, __shfl_xor_sync(0xffffffff, t0, 1));
        t0 = fmaxf(t0, __shfl_xor_sync(0xffffffff, t0, 2));
        t1 = fmaxf(t1, __shfl_xor_sync(0xffffffff, t1, 1));
        t1 = fmaxf(t1, __shfl_xor_sync(0xffffffff, t1, 2));
        float mn0 = fmaxf(m0, t0), mn1 = fmaxf(m1, t1);
        float al0 = __expf(m0 - mn0), al1 = __expf(m1 - mn1);
#pragma unroll
        for (int nt = 0; nt < 8; nt++) {
            O[nt][0] *= al0; O[nt][1] *= al0;
            O[nt][2] *= al1; O[nt][3] *= al1;
        }
        float ls0 = 0.f, ls1 = 0.f;
        uint32_t phi[4][4], plo[4][4];
#pragma unroll
        for (int kk = 0; kk < 4; kk++) {
#pragma unroll
            for (int tt = 0; tt < 2; tt++) {
                int t = 2 * kk + tt;
                float p0 = __expf(S[t][0] - mn0), p1 = __expf(S[t][1] - mn0);
                float p2 = __expf(S[t][2] - mn1), p3 = __expf(S[t][3] - mn1);
                ls0 += p0 + p1; ls1 += p2 + p3;
                float h0 = b2f(__float2bfloat16(p0));
                float h1 = b2f(__float2bfloat16(p1));
                float h2 = b2f(__float2bfloat16(p2));
                float h3 = b2f(__float2bfloat16(p3));
                phi[kk][tt * 2]     = pack_bf16(h0, h1);
                phi[kk][tt * 2 + 1] = pack_bf16(h2, h3);
                plo[kk][tt * 2]     = pack_bf16(p0 - h0, p1 - h1);
                plo[kk][tt * 2 + 1] = pack_bf16(p2 - h2, p3 - h3);
            }
        }
        ls0 += __shfl_xor_sync(0xffffffff, ls0, 1);
        ls0 += __shfl_xor_sync(0xffffffff, ls0, 2);
        ls1 += __shfl_xor_sync(0xffffffff, ls1, 1);
        ls1 += __shfl_xor_sync(0xffffffff, ls1, 2);
        l0 = l0 * al0 + ls0;
        l1 = l1 * al1 + ls1;
        m0 = mn0; m1 = mn1;

        const int vsec[3] = {0, 0, 1};
#pragma unroll
        for (int sp = 0; sp < 3; sp++) {
#pragma unroll
            for (int kk = 0; kk < 4; kk++) {
                uint32_t* A = (sp == 1) ? plo[kk] : phi[kk];
                uint32_t bf[8][2];
#pragma unroll
                for (int p = 0; p < 4; p++) {
                    uint32_t ba = smem_u32(&sV[(p * 16 + ((lane >> 4) << 3) + (lane & 7)) * FA_LD +
                                               vsec[sp] * 64 + kk * 16 + ((lane >> 3) & 1) * 8]);
                    LDSM_X4(bf[2 * p][0], bf[2 * p][1], bf[2 * p + 1][0], bf[2 * p + 1][1], ba);
                }
#pragma unroll
                for (int nt = 0; nt < 8; nt++)
                    MMA16816(O[nt], A[0], A[1], A[2], A[3], bf[nt][0], bf[nt][1]);
            }
        }
    }

    float il0 = 1.0f / l0, il1 = 1.0f / l1;
#pragma unroll
    for (int nt = 0; nt < 8; nt++) {
        int d = h * 64 + nt * 8 + (lane & 3) * 2;
        if (r0g < NT) {
            float v0 = O[nt][0] * il0, v1 = O[nt][1] * il0;
            __nv_bfloat16 h0, lo0, h1, lo1;
            split2(v0, h0, lo0); split2(v1, h1, lo1);
            __nv_bfloat16* o = opk + ((size_t)b * NT + r0g) * 1536;
            *(uint32_t*)&o[d] = pack_bf16(b2f(h0), b2f(h1));
            *(uint32_t*)&o[768 + d] = pack_bf16(b2f(lo0), b2f(lo1));
        }
        if (r1g < NT) {
            float v0 = O[nt][2] * il1, v1 = O[nt][3] * il1;
            __nv_bfloat16 h0, lo0, h1, lo1;
            split2(v0, h0, lo0); split2(v1, h1, lo1);
            __nv_bfloat16* o = opk + ((size_t)b * NT + r1g) * 1536;
            *(uint32_t*)&o[d] = pack_bf16(b2f(h0), b2f(h1));
            *(uint32_t*)&o[768 + d] = pack_bf16(b2f(lo0), b2f(lo1));
        }
    }
}

// ------------------------- elementwise helpers ------------------------------
__global__ void patchify_kernel(const float* __restrict__ x, float* __restrict__ A) {
    int idx = blockIdx.x * 256 + threadIdx.x;
    if (idx >= BATCH * 1024 * EMB) return;
    int col = idx % EMB;
    int m = idx / EMB;
    int b = m / 1024, g = m % 1024;
    int gh = g / 32, gw = g % 32;
    int c = col / 256, rem = col % 256;
    int i = rem / 16, j = rem % 16;
    A[idx] = x[(((size_t)(b * 3 + c) * 512) + gh * 16 + i) * 512 + gw * 16 + j];
}

__global__ void assemble_kernel(const float* __restrict__ tok, const float* __restrict__ cls,
                                const float* __restrict__ pos, float* __restrict__ t) {
    int idx = blockIdx.x * 256 + threadIdx.x;
    if (idx >= BATCH * NT * EMB) return;
    int d = idx % EMB;
    int n = (idx / EMB) % NT;
    int b = idx / (EMB * NT);
    float v = (n == 0) ? cls[d] : tok[((size_t)b * 1024 + (n - 1)) * EMB + d];
    t[idx] = v + pos[n * EMB + d];
}

__global__ void biaspack_all_kernel(const float* __restrict__ qb, const float* __restrict__ vb,
                                    float* __restrict__ out) {
    int i = blockIdx.x * 256 + threadIdx.x;
    if (i >= 12 * 3 * EMB) return;
    int l = i / (3 * EMB), r = i % (3 * EMB);
    out[i] = (r < EMB) ? qb[l * EMB + r]
           : ((r < 2 * EMB) ? 0.f : vb[l * EMB + r - 2 * EMB]);
}

__global__ void copy4_kernel(const float4* __restrict__ src, float4* __restrict__ dst, int n4) {
    int i = blockIdx.x * 256 + threadIdx.x;
    if (i < n4) dst[i] = src[i];
}

__global__ void repack_w_kernel(const float* __restrict__ w, float* __restrict__ wp) {
    int idx = blockIdx.x * 256 + threadIdx.x;
    if (idx >= 3072 * 768) return;
    int c = idx % 768, n = idx / 768;
    int ij = n / 768, d = n % 768;
    wp[idx] = w[(size_t)c * 3072 + d * 4 + ij];
}

__global__ void scatter_bhwc_kernel(const float* __restrict__ tmp, const float* __restrict__ bias,
                                    float* __restrict__ y, int HW) {
    int total = BATCH * HW * HW * 4 * 768;
    int idx = blockIdx.x * 256 + threadIdx.x;
    if (idx >= total) return;
    int d = idx % 768;
    int ij = (idx / 768) % 4;
    int p = (idx / 3072) % (HW * HW);
    int b = idx / (3072 * HW * HW);
    int h = p / HW, w = p % HW, i = ij / 2, j = ij % 2;
    int W2 = 2 * HW;
    y[(((size_t)b * W2 + 2 * h + i) * W2 + (2 * w + j)) * 768 + d] = tmp[idx] + bias[d];
}

__global__ void scatter_bchw_kernel(const float* __restrict__ tmp, const float* __restrict__ bias,
                                    float* __restrict__ out, int HW) {
    int total = BATCH * HW * HW * 4 * 768;
    int idx = blockIdx.x * 256 + threadIdx.x;
    if (idx >= total) return;
    int d = idx % 768;
    int ij = (idx / 768) % 4;
    int p = (idx / 3072) % (HW * HW);
    int b = idx / (3072 * HW * HW);
    int h = p / HW, w = p % HW, i = ij / 2, j = ij % 2;
    int W2 = 2 * HW;
    out[(((size_t)b * 768 + d) * W2 + 2 * h + i) * W2 + (2 * w + j)] = tmp[idx] + bias[d];
}

__global__ void bn_gelu_kernel(float* __restrict__ y, const float* __restrict__ w,
                               const float* __restrict__ b, const float* __restrict__ mean,
                               const float* __restrict__ var) {
    int idx = blockIdx.x * 256 + threadIdx.x;
    if (idx >= BATCH * 64 * 64 * 768) return;
    int c = idx % 768;
    float v = y[idx];
    v = (v - mean[c]) * rsqrtf(var[c] + 1e-5f) * w[c] + b[c];
    y[idx] = gelu_exact(v);
}

__global__ void to_map_kernel(const float* __restrict__ feat, float* __restrict__ out) {
    int idx = blockIdx.x * 256 + threadIdx.x;
    if (idx >= BATCH * 768 * 32 * 32) return;
    int xw = idx % 32;
    int yh = (idx / 32) % 32;
    int c = (idx / 1024) % 768;
    int b = idx / (1024 * 768);
    out[idx] = feat[((size_t)b * NT + 1 + yh * 32 + xw) * EMB + c];
}

__global__ void maxpool_kernel(const float* __restrict__ feat, float* __restrict__ out) {
    int idx = blockIdx.x * 256 + threadIdx.x;
    if (idx >= BATCH * 768 * 16 * 16) return;
    int xw = idx % 16;
    int yh = (idx / 16) % 16;
    int c = (idx / 256) % 768;
    int b = idx / (256 * 768);
    float m = -1e30f;
#pragma unroll
    for (int i = 0; i < 2; i++)
#pragma unroll
        for (int j = 0; j < 2; j++) {
            int Y = 2 * yh + i, X = 2 * xw + j;
            m = fmaxf(m, feat[((size_t)b * NT + 1 + Y * 32 + X) * EMB + c]);
        }
    out[idx] = m;
}

// ------------------------- host helpers -------------------------------------
static void fast_pack(const float* in, __nv_bfloat16* out, int M, int K,
                      size_t irs, size_t ibs, size_t obs, float scale, int nz,
                      cudaStream_t st = 0) {
    dim3 g(M, nz);
    fast_pack_kernel<<<g, 256, 0, st>>>(in, out, K, irs, ibs, obs, scale);
}
#define SMEM_MED   (3 * 2 * (64 + 128) * 40 * 2)   // 92160, BM64/BN128 3-stage
#define SMEM_SMALL (3 * 2 * (64 + 64) * 40 * 2)    // 61440, BM64/BN64  3-stage
static void gemm_tc(const __nv_bfloat16* A, const __nv_bfloat16* B, float* C,
                    __nv_bfloat16* Cp, const float* bias, const float* resid,
                    int M, int N, int Kp, size_t Abs, size_t Bbs, size_t ldc,
                    size_t cs0, size_t cs1, int nh, int gelu, int nz,
                    cudaStream_t st = 0) {
    int gm64 = (M + 63) / 64;
    if (N % 128 == 0 && (N / 128) * gm64 * nz >= 232) {
        dim3 g(N / 128, gm64, nz);
        hgemm2<64, 128, 3, 2><<<g, 256, SMEM_MED, st>>>(A, B, C, Cp, bias, resid, M, N, Kp,
                                                        Abs, Bbs, ldc, cs0, cs1, nh, gelu);
    } else {
        dim3 g(N / 64, gm64, nz);
        hgemm2<64, 64, 3, 3><<<g, 256, SMEM_SMALL, st>>>(A, B, C, Cp, bias, resid, M, N, Kp,
                                                         Abs, Bbs, ldc, cs0, cs1, nh, gelu);
    }
}

extern "C" void kernel_launch(void* const* d_in, const int* in_sizes, int n_in,
                              void* d_out, int out_size) {
    const float* x         = (const float*)d_in[0];
    const float* patch_w   = (const float*)d_in[1];
    const float* patch_b   = (const float*)d_in[2];
    const float* cls_token = (const float*)d_in[3];
    const float* pos_embed = (const float*)d_in[4];
    const float* ln1_w     = (const float*)d_in[5];
    const float* ln1_b     = (const float*)d_in[6];
    const float* qkv_w     = (const float*)d_in[7];
    const float* q_bias    = (const float*)d_in[8];
    const float* v_bias    = (const float*)d_in[9];
    const float* rel_tab   = (const float*)d_in[10];
    const float* proj_w    = (const float*)d_in[11];
    const float* proj_b    = (const float*)d_in[12];
    const float* ln2_w     = (const float*)d_in[13];
    const float* ln2_b     = (const float*)d_in[14];
    const float* fc1_w     = (const float*)d_in[15];
    const float* fc1_b     = (const float*)d_in[16];
    const float* fc2_w     = (const float*)d_in[17];
    const float* fc2_b     = (const float*)d_in[18];
    const float* d1_w      = (const float*)d_in[19];
    const float* d1_b      = (const float*)d_in[20];
    const float* bn_w      = (const float*)d_in[21];
    const float* bn_b      = (const float*)d_in[22];
    const float* bn_mean   = (const float*)d_in[23];
    const float* bn_var    = (const float*)d_in[24];
    const float* d2_w      = (const float*)d_in[25];
    const float* d2_b      = (const float*)d_in[26];
    const float* f2w       = (const float*)d_in[27];
    const float* f2b       = (const float*)d_in[28];

    float* out = (float*)d_out;
    float* out1 = out;
    float* out2 = out1 + (size_t)BATCH * 768 * 128 * 128;
    float* out3 = out2 + (size_t)BATCH * 768 * 64 * 64;
    float* out4 = out3 + (size_t)BATCH * 768 * 32 * 32;

    static float *pt = nullptr, *pqkv, *ppatch, *ptok;
    static float *pf0, *pf1, *pf2, *pf3, *py, *ptmp, *pwp, *pqb;
    static __nv_bfloat16 *pa, *pb, *pc, *pw, *fpa, *fpb;
    static cudaStream_t s2;
    static cudaEvent_t e3, e5, efin;
    if (!pt) {
        cudaGetSymbolAddress((void**)&pt, g_t);
        cudaGetSymbolAddress((void**)&pqkv, g_qkv);
        cudaGetSymbolAddress((void**)&ppatch, g_patch);
        cudaGetSymbolAddress((void**)&ptok, g_tok);
        cudaGetSymbolAddress((void**)&pf0, g_feat0);
        cudaGetSymbolAddress((void**)&pf1, g_feat1);
        cudaGetSymbolAddress((void**)&pf2, g_feat2);
        cudaGetSymbolAddress((void**)&pf3, g_feat3);
        cudaGetSymbolAddress((void**)&py, g_y);
        cudaGetSymbolAddress((void**)&ptmp, g_tmp);
        cudaGetSymbolAddress((void**)&pwp, g_wpack);
        cudaGetSymbolAddress((void**)&pqb, g_qkvbias);
        cudaGetSymbolAddress((void**)&pa, g_pa);
        cudaGetSymbolAddress((void**)&pb, g_pb);
        cudaGetSymbolAddress((void**)&pc, g_pc);
        cudaGetSymbolAddress((void**)&pw, g_pw);
        cudaGetSymbolAddress((void**)&fpa, g_fpa);
        cudaGetSymbolAddress((void**)&fpb, g_fpb);
        cudaStreamCreateWithFlags(&s2, cudaStreamNonBlocking);
        cudaEventCreateWithFlags(&e3, cudaEventDisableTiming);
        cudaEventCreateWithFlags(&e5, cudaEventDisableTiming);
        cudaEventCreateWithFlags(&efin, cudaEventDisableTiming);
        cudaFuncSetAttribute(flash_attn_kernel,
                             cudaFuncAttributeMaxDynamicSharedMemorySize,
                             (128 + 64 + 64) * FA_LD * 2 + NREL * 4);
        cudaFuncSetAttribute((const void*)hgemm2<64, 128, 3, 2>,
                             cudaFuncAttributeMaxDynamicSharedMemorySize, SMEM_MED);
        cudaFuncSetAttribute((const void*)hgemm2<64, 64, 3, 3>,
                             cudaFuncAttributeMaxDynamicSharedMemorySize, SMEM_SMALL);
    }

    const int TOKELEMS = BATCH * NT * EMB;
    const int M = BATCH * NT;  // 2050
    const int FA_SMEM = (128 + 64 + 64) * FA_LD * 2 + NREL * 4;

    // ---- pre-pack ALL transformer weights (main stream) ----
    fast_pack(qkv_w, pw + W_QKV, 2304, 768, 768, (size_t)2304 * 768, W_PER, 1.0f, 12);
    fast_pack(proj_w, pw + W_PROJ, 768, 768, 768, (size_t)768 * 768, W_PER, 1.0f, 12);
    fast_pack(fc1_w, pw + W_FC1, 3072, 768, 768, (size_t)3072 * 768, W_PER, 1.0f, 12);
    fast_pack(fc2_w, pw + W_FC2, 768, 3072, 3072, (size_t)768 * 3072, W_PER, 1.0f, 12);
    biaspack_all_kernel<<<(12 * 3 * EMB + 255) / 256, 256>>>(q_bias, v_bias, pqb);

    // ---- patch embed ----
    patchify_kernel<<<(BATCH * 1024 * EMB + 255) / 256, 256>>>(x, ppatch);
    fast_pack(ppatch, pa, 2048, 768, 768, 0, 0, 1.0f, 1);
    fast_pack(patch_w, pb, 768, 768, 768, 0, 0, 1.0f, 1);
    gemm_tc(pa, pb, ptok, nullptr, patch_b, nullptr, 2048, 768, 768, 0, 0,
            768, 0, 0, 1, 0, 1);
    assemble_kernel<<<(TOKELEMS + 255) / 256, 256>>>(ptok, cls_token, pos_embed, pt);

    // ---- transformer layers (main stream) ----
    for (int l = 0; l < 12; l++) {
        const __nv_bfloat16* wl = pw + (size_t)l * W_PER;
        ln_pack_kernel<<<M, 256>>>(pt, ln1_w + l * EMB, ln1_b + l * EMB, pa);
        gemm_tc(pa, wl + W_QKV, pqkv, nullptr, pqb + l * 2304, nullptr, M, 2304, 768, 0, 0,
                2304, 0, 0, 1, 0, 1);
        {
            dim3 g((NT + 127) / 128, BATCH * HEADS);
            flash_attn_kernel<<<g, 256, FA_SMEM>>>(pqkv, rel_tab + (size_t)l * NREL * HEADS, pa);
        }
        gemm_tc(pa, wl + W_PROJ, pt, nullptr, proj_b + l * EMB, pt, M, 768, 768, 0, 0,
                768, 0, 0, 1, 0, 1);
        ln_pack_kernel<<<M, 256>>>(pt, ln2_w + l * EMB, ln2_b + l * EMB, pa);
        gemm_tc(pa, wl + W_FC1, nullptr, pc, fc1_b + l * 4 * EMB, nullptr, M, 3072, 768, 0, 0,
                3072, 0, 0, 1, 1, 1);
        gemm_tc(pc, wl + W_FC2, pt, nullptr, fc2_b + l * EMB, pt, M, 768, 3072, 0, 0,
                768, 0, 0, 1, 0, 1);
        float* fdst = nullptr;
        if (l == 3) fdst = pf0;
        else if (l == 5) fdst = pf1;
        else if (l == 7) fdst = pf2;
        else if (l == 11) fdst = pf3;
        if (fdst) {
            copy4_kernel<<<(TOKELEMS / 4 + 255) / 256, 256>>>((const float4*)pt,
                                                              (float4*)fdst, TOKELEMS / 4);
            if (l == 3) cudaEventRecord(e3, 0);
            else if (l == 5) cudaEventRecord(e5, 0);
        }
    }

    // ---- FPN on stream 2 (overlaps layers 4..11 on main stream) ----
    cudaStreamWaitEvent(s2, e3, 0);
    // stage 1: deconv d1 on layer-3 map
    repack_w_kernel<<<(3072 * 768 + 255) / 256, 256, 0, s2>>>(d1_w, pwp);
    fast_pack(pwp, fpb, 3072, 768, 768, 0, 0, 1.0f, 1, s2);
    fast_pack(pf0 + 768, fpa, 1024, 768, 768, (size_t)NT * 768,
              (size_t)1024 * 1536, 1.0f, BATCH, s2);
    gemm_tc(fpa, fpb, ptmp, nullptr, nullptr, nullptr, 1024, 3072, 768,
            (size_t)1024 * 1536, 0, 3072, (size_t)1024 * 3072, 0, 1, 0, BATCH, s2);
    scatter_bhwc_kernel<<<(BATCH * 1024 * 3072 + 255) / 256, 256, 0, s2>>>(ptmp, d1_b, py, 32);
    bn_gelu_kernel<<<(BATCH * 64 * 64 * 768 + 255) / 256, 256, 0, s2>>>(py, bn_w, bn_b,
                                                                        bn_mean, bn_var);
    // stage 2: deconv d2 -> out1
    repack_w_kernel<<<(3072 * 768 + 255) / 256, 256, 0, s2>>>(d2_w, pwp);
    fast_pack(pwp, fpb, 3072, 768, 768, 0, 0, 1.0f, 1, s2);
    fast_pack(py, fpa, 4096, 768, 768, (size_t)4096 * 768,
              (size_t)4096 * 1536, 1.0f, BATCH, s2);
    gemm_tc(fpa, fpb, ptmp, nullptr, nullptr, nullptr, 4096, 3072, 768,
            (size_t)4096 * 1536, 0, 3072, (size_t)4096 * 3072, 0, 1, 0, BATCH, s2);
    scatter_bchw_kernel<<<(BATCH * 4096 * 3072 + 255) / 256, 256, 0, s2>>>(ptmp, d2_b, out1, 64);
    // o2: deconv f2 on layer-5 map -> out2
    cudaStreamWaitEvent(s2, e5, 0);
    repack_w_kernel<<<(3072 * 768 + 255) / 256, 256, 0, s2>>>(f2w, pwp);
    fast_pack(pwp, fpb, 3072, 768, 768, 0, 0, 1.0f, 1, s2);
    fast_pack(pf1 + 768, fpa, 1024, 768, 768, (size_t)NT * 768,
              (size_t)1024 * 1536, 1.0f, BATCH, s2);
    gemm_tc(fpa, fpb, ptmp, nullptr, nullptr, nullptr, 1024, 3072, 768,
            (size_t)1024 * 1536, 0, 3072, (size_t)1024 * 3072, 0, 1, 0, BATCH, s2);
    scatter_bchw_kernel<<<(BATCH * 1024 * 3072 + 255) / 256, 256, 0, s2>>>(ptmp, f2b, out2, 32);
    cudaEventRecord(efin, s2);

    // ---- o3 / o4 (main stream; depend on pf2 / pf3 only) ----
    to_map_kernel<<<(BATCH * 768 * 1024 + 255) / 256, 256>>>(pf2, out3);
    maxpool_kernel<<<(BATCH * 768 * 256 + 255) / 256, 256>>>(pf3, out4);

    // join stream 2 back into main stream
    cudaStreamWaitEvent(0, efin, 0);

    (void)in_sizes; (void)n_in; (void)out_size;
}